// round 1
// baseline (speedup 1.0000x reference)
#include <cuda_runtime.h>

// Problem constants (fixed shapes)
//   x: (4, 256, 8, 64, 64)  -> images N=32 (Bs*T), C=256, H=W=64
//   conv_off1: 256 -> 512 ; conv1: 256 -> 64 ; conv_off2: 64 -> 128 ; conv2: 64 -> 64
//   out: (4, 64, 8, 64, 64)

#define HW   4096
#define NIMG 32

// ---------------- device scratch (no allocations allowed) ----------------
__device__ float g_nd  [32u * 256u * 4096u];   // x transposed to (N,C,H,W)
__device__ float g_off1[32u * 512u * 4096u];   // offsets stage 1
__device__ float g_def1[32u * 256u * 4096u];   // deformed stage 1
__device__ float g_c1  [32u *  64u * 4096u];   // conv1 + bn + lrelu
__device__ float g_off2[32u * 128u * 4096u];   // offsets stage 2
__device__ float g_def2[32u *  64u * 4096u];   // deformed stage 2

// ---------------- (Bs,C,T,H,W) -> (Bs*T,C,H,W) ----------------
__global__ void k_transpose_in(const float* __restrict__ x, float* __restrict__ nd)
{
    long long idx = (long long)blockIdx.x * 256 + threadIdx.x;   // over 32*256*4096
    int pix = (int)(idx & 4095);
    long long r = idx >> 12;
    int c = (int)(r & 255);
    int n = (int)(r >> 8);
    int b = n >> 3, t = n & 7;
    nd[idx] = x[((((long long)b * 256 + c) * 8 + t) << 12) + pix];
}

// ---------------- direct 3x3 conv, stride 1, pad 1, H=W=64 ----------------
// Block: 64 output channels x 16x16 spatial tile. 256 threads.
// Thread: 8 oc x 8 px register tile. Cin chunked by 8 through smem.
__global__ __launch_bounds__(256, 2)
void k_conv3x3(const float* __restrict__ in, const float* __restrict__ wt,
               const float* __restrict__ bng, const float* __restrict__ bnb,
               const float* __restrict__ bnm, const float* __restrict__ bnv,
               float* __restrict__ out, int Cin, int Cout, int outTrans)
{
    __shared__ float s_in[8 * 324];        // 8 ic x 18x18 halo tile
    __shared__ float s_w[64 * 72];         // [oc][ic(8)][tap(9)]

    const int n   = blockIdx.z;
    const int oc0 = blockIdx.y << 6;
    const int ty0 = (blockIdx.x >> 2) << 4;
    const int tx0 = (blockIdx.x & 3) << 4;

    const int t   = threadIdx.x;
    const int ocg = t >> 5;        // 0..7, constant within a warp (weight broadcast)
    const int pxg = t & 31;        // 0..31

    int poff[8];
#pragma unroll
    for (int j = 0; j < 8; j++) {
        int p = pxg + (j << 5);                 // pixel 0..255 inside 16x16 tile
        poff[j] = (p >> 4) * 18 + (p & 15);     // smem offset (row-major, width 18)
    }

    float acc[8][8];
#pragma unroll
    for (int i = 0; i < 8; i++)
#pragma unroll
        for (int j = 0; j < 8; j++) acc[i][j] = 0.f;

    const float* in_n = in + (long long)n * Cin * HW;

    for (int ic0 = 0; ic0 < Cin; ic0 += 8) {
        // stage input halo (8 x 18 x 18)
        for (int idx = t; idx < 8 * 324; idx += 256) {
            int ic = idx / 324;
            int r  = idx - ic * 324;
            int iy = r / 18 + ty0 - 1;
            int ix = r % 18 + tx0 - 1;
            float v = 0.f;
            if ((unsigned)iy < 64u && (unsigned)ix < 64u)
                v = in_n[(long long)(ic0 + ic) * HW + iy * 64 + ix];
            s_in[idx] = v;
        }
        // stage weights (64 oc x 8 ic x 9 taps) — contiguous slab per oc
        for (int idx = t; idx < 64 * 72; idx += 256) {
            int oc = idx / 72;
            int r  = idx - oc * 72;
            s_w[idx] = wt[((long long)(oc0 + oc) * Cin + ic0) * 9 + r];
        }
        __syncthreads();

#pragma unroll
        for (int ic = 0; ic < 8; ic++) {
            const float* si  = s_in + ic * 324;
            const float* swp = s_w + ic * 9;
#pragma unroll
            for (int dy = 0; dy < 3; dy++)
#pragma unroll
            for (int dx = 0; dx < 3; dx++) {
                const int tap = dy * 3 + dx;
                const int dd  = dy * 18 + dx;
                float wv[8], xv[8];
#pragma unroll
                for (int i = 0; i < 8; i++)
                    wv[i] = swp[(ocg * 8 + i) * 72 + tap];
#pragma unroll
                for (int j = 0; j < 8; j++)
                    xv[j] = si[poff[j] + dd];
#pragma unroll
                for (int i = 0; i < 8; i++)
#pragma unroll
                    for (int j = 0; j < 8; j++)
                        acc[i][j] = fmaf(wv[i], xv[j], acc[i][j]);
            }
        }
        __syncthreads();
    }

    // epilogue: optional BN (eval) + LeakyReLU(0.01), optional (N,OC)->(B,OC,T) transpose
    const bool dobn = (bng != nullptr);
#pragma unroll
    for (int i = 0; i < 8; i++) {
        int oc = oc0 + ocg * 8 + i;
        float sc = 1.f, bi = 0.f;
        if (dobn) {
            sc = bng[oc] * rsqrtf(bnv[oc] + 1e-5f);
            bi = bnb[oc] - bnm[oc] * sc;
        }
#pragma unroll
        for (int j = 0; j < 8; j++) {
            int p  = pxg + (j << 5);
            int y  = ty0 + (p >> 4);
            int xc = tx0 + (p & 15);
            float v = acc[i][j];
            if (dobn) {
                v = v * sc + bi;
                v = (v > 0.f) ? v : 0.01f * v;
            }
            long long oidx;
            if (outTrans) {
                int b = n >> 3, tt = n & 7;
                oidx = ((((long long)b * Cout + oc) * 8 + tt) << 12) + y * 64 + xc;
            } else {
                oidx = (((long long)n * Cout + oc) << 12) + y * 64 + xc;
            }
            out[oidx] = v;
        }
    }
}

// ---------------- per-channel bilinear sampling (ConvOffset2D semantics) ----
// off viewed as (N*C, H, W, 2): within image n, for channel c the (y,x) offsets
// for pixel p live at flat index c*2*HW + 2*p + {0,1}.
__global__ void k_deform(const float* __restrict__ x, const float* __restrict__ off,
                         float* __restrict__ out, int C)
{
    long long idx = (long long)blockIdx.x * 256 + threadIdx.x;  // over N*C*HW
    int pix = (int)(idx & 4095);
    long long r = idx >> 12;
    int c = (int)(r % C);
    int n = (int)(r / C);
    int h = pix >> 6, w = pix & 63;

    const float* offb = off + (((long long)n * C + c) << 13);   // c*2*HW within image
    float oy = offb[2 * pix];
    float ox = offb[2 * pix + 1];

    float cy = fminf(fmaxf((float)h + oy, 0.f), 63.f);
    float cx = fminf(fmaxf((float)w + ox, 0.f), 63.f);
    float y0f = floorf(cy), x0f = floorf(cx);
    float ty = cy - y0f, tx = cx - x0f;
    int y0 = (int)y0f, x0 = (int)x0f;
    int y1 = min(y0 + 1, 63), x1 = min(x0 + 1, 63);

    const float* xc = x + (((long long)n * C + c) << 12);
    float v00 = xc[(y0 << 6) + x0];
    float v01 = xc[(y0 << 6) + x1];
    float v10 = xc[(y1 << 6) + x0];
    float v11 = xc[(y1 << 6) + x1];

    out[idx] = v00 * (1.f - ty) * (1.f - tx) + v01 * (1.f - ty) * tx +
               v10 * ty * (1.f - tx)         + v11 * ty * tx;
}

// ---------------- launch ----------------
extern "C" void kernel_launch(void* const* d_in, const int* in_sizes, int n_in,
                              void* d_out, int out_size)
{
    const float* x      = (const float*)d_in[0];
    const float* w_off1 = (const float*)d_in[3];
    const float* w1     = (const float*)d_in[4];
    const float* g1     = (const float*)d_in[5];
    const float* b1     = (const float*)d_in[6];
    const float* m1     = (const float*)d_in[7];
    const float* v1     = (const float*)d_in[8];
    const float* w_off2 = (const float*)d_in[9];
    const float* w2     = (const float*)d_in[10];
    const float* g2     = (const float*)d_in[11];
    const float* b2     = (const float*)d_in[12];
    const float* m2     = (const float*)d_in[13];
    const float* v2     = (const float*)d_in[14];
    float* out = (float*)d_out;

    float *nd, *off1, *def1, *c1, *off2, *def2;
    cudaGetSymbolAddress((void**)&nd,   g_nd);
    cudaGetSymbolAddress((void**)&off1, g_off1);
    cudaGetSymbolAddress((void**)&def1, g_def1);
    cudaGetSymbolAddress((void**)&c1,   g_c1);
    cudaGetSymbolAddress((void**)&off2, g_off2);
    cudaGetSymbolAddress((void**)&def2, g_def2);

    // 1) (Bs,C,T,H,W) -> (N,C,H,W)
    k_transpose_in<<<131072, 256>>>(x, nd);

    // 2) offset conv 1: 256 -> 512
    k_conv3x3<<<dim3(16, 8, NIMG), 256>>>(nd, w_off1,
        nullptr, nullptr, nullptr, nullptr, off1, 256, 512, 0);

    // 3) bilinear deform 1
    k_deform<<<131072, 256>>>(nd, off1, def1, 256);

    // 4) conv1 + bn1 + lrelu: 256 -> 64
    k_conv3x3<<<dim3(16, 1, NIMG), 256>>>(def1, w1, g1, b1, m1, v1, c1, 256, 64, 0);

    // 5) offset conv 2: 64 -> 128
    k_conv3x3<<<dim3(16, 2, NIMG), 256>>>(c1, w_off2,
        nullptr, nullptr, nullptr, nullptr, off2, 64, 128, 0);

    // 6) bilinear deform 2
    k_deform<<<32768, 256>>>(c1, off2, def2, 64);

    // 7) conv2 + bn2 + lrelu + output transpose: 64 -> 64, (N,64,H,W)->(Bs,64,T,H,W)
    k_conv3x3<<<dim3(16, 1, NIMG), 256>>>(def2, w2, g2, b2, m2, v2, out, 64, 64, 1);
}

// round 2
// speedup vs baseline: 1.3646x; 1.3646x over previous
#include <cuda_runtime.h>

// Problem constants (fixed shapes)
//   x: (4, 256, 8, 64, 64)  -> images N=32 (Bs*T), C=256, H=W=64
//   conv_off1: 256 -> 512 ; conv1: 256 -> 64 ; conv_off2: 64 -> 128 ; conv2: 64 -> 64
//   out: (4, 64, 8, 64, 64)

#define HW   4096
#define NIMG 32

// ---------------- device scratch (no allocations allowed) ----------------
__device__ float g_nd  [32u * 256u * 4096u];   // x transposed to (N,C,H,W)
__device__ float g_off1[32u * 512u * 4096u];   // offsets stage 1
__device__ float g_def1[32u * 256u * 4096u];   // deformed stage 1
__device__ float g_c1  [32u *  64u * 4096u];   // conv1 + bn + lrelu
__device__ float g_off2[32u * 128u * 4096u];   // offsets stage 2
__device__ float g_def2[32u *  64u * 4096u];   // deformed stage 2

// ---------------- packed f32x2 helpers ----------------
__device__ __forceinline__ unsigned long long pk2(float a, float b) {
    unsigned long long r;
    asm("mov.b64 %0, {%1, %2};" : "=l"(r) : "f"(a), "f"(b));
    return r;
}
__device__ __forceinline__ void unpk2(unsigned long long v, float& a, float& b) {
    asm("mov.b64 {%0, %1}, %2;" : "=f"(a), "=f"(b) : "l"(v));
}
__device__ __forceinline__ void ffma2(unsigned long long& d,
                                      unsigned long long a, unsigned long long b) {
    asm("fma.rn.f32x2 %0, %1, %2, %3;" : "=l"(d) : "l"(a), "l"(b), "l"(d));
}

// ---------------- (Bs,C,T,H,W) -> (Bs*T,C,H,W) ----------------
__global__ void k_transpose_in(const float* __restrict__ x, float* __restrict__ nd)
{
    long long idx = (long long)blockIdx.x * 256 + threadIdx.x;   // over 32*256*4096
    int pix = (int)(idx & 4095);
    long long r = idx >> 12;
    int c = (int)(r & 255);
    int n = (int)(r >> 8);
    int b = n >> 3, t = n & 7;
    nd[idx] = x[((((long long)b * 256 + c) * 8 + t) << 12) + pix];
}

// ---------------- direct 3x3 conv, stride 1, pad 1, H=W=64 ----------------
// Block: 64 output channels x 16x16 spatial tile. 256 threads.
// Thread: 4 oc-pairs (packed f32x2) x 8 px register tile = 8 oc x 8 px MACs.
// Cin chunked by 8 through smem. Inner loop uses fma.rn.f32x2 (FFMA2).
#define WSTRIDE 66   // padded oc-stride: conflict-free staging + 8B-aligned pairs
__global__ __launch_bounds__(256, 2)
void k_conv3x3(const float* __restrict__ in, const float* __restrict__ wt,
               const float* __restrict__ bng, const float* __restrict__ bnb,
               const float* __restrict__ bnm, const float* __restrict__ bnv,
               float* __restrict__ out, int Cin, int Cout, int outTrans)
{
    __shared__ float s_in[8 * 324];                     // 8 ic x 18x18 halo tile
    __shared__ __align__(8) float s_w[72 * WSTRIDE];    // [ic(8)*tap(9)][oc(64) pad 66]

    const int n   = blockIdx.z;
    const int oc0 = blockIdx.y << 6;
    const int ty0 = (blockIdx.x >> 2) << 4;
    const int tx0 = (blockIdx.x & 3) << 4;

    const int t   = threadIdx.x;
    const int ocg = t >> 5;        // 0..7, constant within a warp (weight broadcast)
    const int pxg = t & 31;        // 0..31

    int poff[8];
#pragma unroll
    for (int j = 0; j < 8; j++) {
        int p = pxg + (j << 5);                 // pixel 0..255 inside 16x16 tile
        poff[j] = (p >> 4) * 18 + (p & 15);     // smem offset (row-major, width 18)
    }

    unsigned long long acc2[4][8];
#pragma unroll
    for (int i = 0; i < 4; i++)
#pragma unroll
        for (int j = 0; j < 8; j++) acc2[i][j] = 0ull;

    const float* in_n = in + (long long)n * Cin * HW;

    for (int ic0 = 0; ic0 < Cin; ic0 += 8) {
        // stage input halo (8 x 18 x 18)
        for (int idx = t; idx < 8 * 324; idx += 256) {
            int ic = idx / 324;
            int r  = idx - ic * 324;
            int iy = r / 18 + ty0 - 1;
            int ix = r % 18 + tx0 - 1;
            float v = 0.f;
            if ((unsigned)iy < 64u && (unsigned)ix < 64u)
                v = in_n[(long long)(ic0 + ic) * HW + iy * 64 + ix];
            s_in[idx] = v;
        }
        // stage weights: gmem coalesced [oc][ic(8)][tap(9)] -> smem [ic][tap][oc]
        for (int idx = t; idx < 64 * 72; idx += 256) {
            int oc = idx / 72;
            int r  = idx - oc * 72;              // r = ic*9 + tap
            float w = wt[((long long)(oc0 + oc) * Cin + ic0) * 9 + r];
            s_w[r * WSTRIDE + oc] = w;
        }
        __syncthreads();

#pragma unroll
        for (int ic = 0; ic < 8; ic++) {
            const float* si = s_in + ic * 324;
#pragma unroll
            for (int dy = 0; dy < 3; dy++)
#pragma unroll
            for (int dx = 0; dx < 3; dx++) {
                const int tap = dy * 3 + dx;
                const int dd  = dy * 18 + dx;
                // 4 packed oc-pair weights (aligned 64-bit broadcast loads)
                const unsigned long long* wp = (const unsigned long long*)
                    (s_w + (ic * 9 + tap) * WSTRIDE + ocg * 8);
                unsigned long long w0 = wp[0], w1 = wp[1], w2 = wp[2], w3 = wp[3];
#pragma unroll
                for (int j = 0; j < 8; j++) {
                    float xv = si[poff[j] + dd];
                    unsigned long long xx = pk2(xv, xv);
                    ffma2(acc2[0][j], w0, xx);
                    ffma2(acc2[1][j], w1, xx);
                    ffma2(acc2[2][j], w2, xx);
                    ffma2(acc2[3][j], w3, xx);
                }
            }
        }
        __syncthreads();
    }

    // epilogue: optional BN (eval) + LeakyReLU(0.01), optional output transpose
    const bool dobn = (bng != nullptr);
    const int b = n >> 3, tt = n & 7;
#pragma unroll
    for (int ip = 0; ip < 4; ip++) {
        int ocA = oc0 + ocg * 8 + 2 * ip;
        int ocB = ocA + 1;
        float scA = 1.f, biA = 0.f, scB = 1.f, biB = 0.f;
        if (dobn) {
            scA = bng[ocA] * rsqrtf(bnv[ocA] + 1e-5f);
            biA = bnb[ocA] - bnm[ocA] * scA;
            scB = bng[ocB] * rsqrtf(bnv[ocB] + 1e-5f);
            biB = bnb[ocB] - bnm[ocB] * scB;
        }
#pragma unroll
        for (int j = 0; j < 8; j++) {
            int p  = pxg + (j << 5);
            int y  = ty0 + (p >> 4);
            int xc = tx0 + (p & 15);
            float vA, vB;
            unpk2(acc2[ip][j], vA, vB);
            if (dobn) {
                vA = vA * scA + biA;  vA = (vA > 0.f) ? vA : 0.01f * vA;
                vB = vB * scB + biB;  vB = (vB > 0.f) ? vB : 0.01f * vB;
            }
            long long oA, oB;
            if (outTrans) {
                oA = ((((long long)b * Cout + ocA) * 8 + tt) << 12) + y * 64 + xc;
                oB = ((((long long)b * Cout + ocB) * 8 + tt) << 12) + y * 64 + xc;
            } else {
                oA = (((long long)n * Cout + ocA) << 12) + y * 64 + xc;
                oB = (((long long)n * Cout + ocB) << 12) + y * 64 + xc;
            }
            out[oA] = vA;
            out[oB] = vB;
        }
    }
}

// ---------------- per-channel bilinear sampling (ConvOffset2D semantics) ----
__global__ void k_deform(const float* __restrict__ x, const float* __restrict__ off,
                         float* __restrict__ out, int C)
{
    long long idx = (long long)blockIdx.x * 256 + threadIdx.x;  // over N*C*HW
    int pix = (int)(idx & 4095);
    long long r = idx >> 12;
    int c = (int)(r % C);
    int n = (int)(r / C);
    int h = pix >> 6, w = pix & 63;

    const float* offb = off + (((long long)n * C + c) << 13);   // c*2*HW within image
    float oy = offb[2 * pix];
    float ox = offb[2 * pix + 1];

    float cy = fminf(fmaxf((float)h + oy, 0.f), 63.f);
    float cx = fminf(fmaxf((float)w + ox, 0.f), 63.f);
    float y0f = floorf(cy), x0f = floorf(cx);
    float ty = cy - y0f, tx = cx - x0f;
    int y0 = (int)y0f, x0 = (int)x0f;
    int y1 = min(y0 + 1, 63), x1 = min(x0 + 1, 63);

    const float* xc = x + (((long long)n * C + c) << 12);
    float v00 = xc[(y0 << 6) + x0];
    float v01 = xc[(y0 << 6) + x1];
    float v10 = xc[(y1 << 6) + x0];
    float v11 = xc[(y1 << 6) + x1];

    out[idx] = v00 * (1.f - ty) * (1.f - tx) + v01 * (1.f - ty) * tx +
               v10 * ty * (1.f - tx)         + v11 * ty * tx;
}

// ---------------- launch ----------------
extern "C" void kernel_launch(void* const* d_in, const int* in_sizes, int n_in,
                              void* d_out, int out_size)
{
    const float* x      = (const float*)d_in[0];
    const float* w_off1 = (const float*)d_in[3];
    const float* w1     = (const float*)d_in[4];
    const float* g1     = (const float*)d_in[5];
    const float* b1     = (const float*)d_in[6];
    const float* m1     = (const float*)d_in[7];
    const float* v1     = (const float*)d_in[8];
    const float* w_off2 = (const float*)d_in[9];
    const float* w2     = (const float*)d_in[10];
    const float* g2     = (const float*)d_in[11];
    const float* b2     = (const float*)d_in[12];
    const float* m2     = (const float*)d_in[13];
    const float* v2     = (const float*)d_in[14];
    float* out = (float*)d_out;

    float *nd, *off1, *def1, *c1, *off2, *def2;
    cudaGetSymbolAddress((void**)&nd,   g_nd);
    cudaGetSymbolAddress((void**)&off1, g_off1);
    cudaGetSymbolAddress((void**)&def1, g_def1);
    cudaGetSymbolAddress((void**)&c1,   g_c1);
    cudaGetSymbolAddress((void**)&off2, g_off2);
    cudaGetSymbolAddress((void**)&def2, g_def2);

    // 1) (Bs,C,T,H,W) -> (N,C,H,W)
    k_transpose_in<<<131072, 256>>>(x, nd);

    // 2) offset conv 1: 256 -> 512
    k_conv3x3<<<dim3(16, 8, NIMG), 256>>>(nd, w_off1,
        nullptr, nullptr, nullptr, nullptr, off1, 256, 512, 0);

    // 3) bilinear deform 1
    k_deform<<<131072, 256>>>(nd, off1, def1, 256);

    // 4) conv1 + bn1 + lrelu: 256 -> 64
    k_conv3x3<<<dim3(16, 1, NIMG), 256>>>(def1, w1, g1, b1, m1, v1, c1, 256, 64, 0);

    // 5) offset conv 2: 64 -> 128
    k_conv3x3<<<dim3(16, 2, NIMG), 256>>>(c1, w_off2,
        nullptr, nullptr, nullptr, nullptr, off2, 64, 128, 0);

    // 6) bilinear deform 2
    k_deform<<<32768, 256>>>(c1, off2, def2, 64);

    // 7) conv2 + bn2 + lrelu + output transpose: 64 -> 64
    k_conv3x3<<<dim3(16, 1, NIMG), 256>>>(def2, w2, g2, b2, m2, v2, out, 64, 64, 1);
}

// round 3
// speedup vs baseline: 1.4987x; 1.0983x over previous
#include <cuda_runtime.h>

// Problem constants (fixed shapes)
//   x: (4, 256, 8, 64, 64)  -> images N=32 (Bs*T), C=256, H=W=64
//   conv_off1: 256 -> 512 ; conv1: 256 -> 64 ; conv_off2: 64 -> 128 ; conv2: 64 -> 64

#define HW   4096
#define NIMG 32

// ---------------- device scratch (no allocations allowed) ----------------
__device__ float g_nd  [32u * 256u * 4096u];
__device__ float g_off1[32u * 512u * 4096u];
__device__ float g_def1[32u * 256u * 4096u];
__device__ float g_c1  [32u *  64u * 4096u];
__device__ float g_off2[32u * 128u * 4096u];
__device__ float g_def2[32u *  64u * 4096u];

// ---------------- packed f32x2 helpers ----------------
__device__ __forceinline__ unsigned long long pk2(float a, float b) {
    unsigned long long r;
    asm("mov.b64 %0, {%1, %2};" : "=l"(r) : "f"(a), "f"(b));
    return r;
}
__device__ __forceinline__ void unpk2(unsigned long long v, float& a, float& b) {
    asm("mov.b64 {%0, %1}, %2;" : "=f"(a), "=f"(b) : "l"(v));
}
__device__ __forceinline__ void ffma2(unsigned long long& d,
                                      unsigned long long a, unsigned long long b) {
    asm("fma.rn.f32x2 %0, %1, %2, %3;" : "=l"(d) : "l"(a), "l"(b), "l"(d));
}

// ---------------- (Bs,C,T,H,W) -> (Bs*T,C,H,W) ----------------
__global__ void k_transpose_in(const float* __restrict__ x, float* __restrict__ nd)
{
    long long idx = (long long)blockIdx.x * 256 + threadIdx.x;
    int pix = (int)(idx & 4095);
    long long r = idx >> 12;
    int c = (int)(r & 255);
    int n = (int)(r >> 8);
    int b = n >> 3, t = n & 7;
    nd[idx] = x[((((long long)b * 256 + c) * 8 + t) << 12) + pix];
}

// ---------------- direct 3x3 conv, stride 1, pad 1, H=W=64 ----------------
// Block: 64 oc x 16x16 spatial tile, 256 threads.
// Thread: 4 oc-pairs (f32x2) x 8 CONTIGUOUS pixels in one row.
// Per (ic,dy): one 12-float row span via 3x LDS.128, reused across 3 dx taps.
#define WSTRIDE 66   // weight smem oc-stride
#define RSTRIDE 20   // input halo row stride (floats): 16B-aligned rows
__global__ __launch_bounds__(256, 2)
void k_conv3x3(const float* __restrict__ in, const float* __restrict__ wt,
               const float* __restrict__ bng, const float* __restrict__ bnb,
               const float* __restrict__ bnm, const float* __restrict__ bnv,
               float* __restrict__ out, int Cin, int Cout, int outTrans)
{
    __shared__ __align__(16) float s_in[8 * 18 * RSTRIDE];   // 8 ic x 18 x 20
    __shared__ __align__(8)  float s_w[72 * WSTRIDE];        // [ic*9+tap][oc pad 66]

    const int n   = blockIdx.z;
    const int oc0 = blockIdx.y << 6;
    const int ty0 = (blockIdx.x >> 2) << 4;
    const int tx0 = (blockIdx.x & 3) << 4;

    const int t    = threadIdx.x;
    const int ocg  = t >> 5;            // warp-constant -> weight broadcast
    const int pxg  = t & 31;
    const int prow = pxg & 15;          // 0..15 row in tile
    const int pxb  = (pxg >> 4) << 3;   // 0 or 8: start col of 8-px strip

    unsigned long long acc2[4][8];
#pragma unroll
    for (int i = 0; i < 4; i++)
#pragma unroll
        for (int j = 0; j < 8; j++) acc2[i][j] = 0ull;

    const float* in_n = in + (long long)n * Cin * HW;

    for (int ic0 = 0; ic0 < Cin; ic0 += 8) {
        // stage input halo (8 x 18 x 20, cols 18-19 padding)
        for (int idx = t; idx < 8 * 18 * RSTRIDE; idx += 256) {
            int ic  = idx / (18 * RSTRIDE);
            int r   = idx - ic * (18 * RSTRIDE);
            int row = r / RSTRIDE;
            int col = r - row * RSTRIDE;
            int iy = row + ty0 - 1;
            int ix = col + tx0 - 1;
            float v = 0.f;
            if ((unsigned)iy < 64u && (unsigned)ix < 64u)
                v = in_n[(long long)(ic0 + ic) * HW + iy * 64 + ix];
            s_in[idx] = v;
        }
        // stage weights: gmem [oc][ic(8)][tap(9)] -> smem [ic*9+tap][oc]
        for (int idx = t; idx < 64 * 72; idx += 256) {
            int oc = idx / 72;
            int r  = idx - oc * 72;
            s_w[r * WSTRIDE + oc] = wt[((long long)(oc0 + oc) * Cin + ic0) * 9 + r];
        }
        __syncthreads();

#pragma unroll
        for (int ic = 0; ic < 8; ic++) {
            const float* sbase = s_in + ic * (18 * RSTRIDE) + prow * RSTRIDE + pxb;
#pragma unroll
            for (int dy = 0; dy < 3; dy++) {
                // 12-float row span, 3 aligned conflict-free LDS.128
                const float4* rp = (const float4*)(sbase + dy * RSTRIDE);
                float4 A = rp[0], B = rp[1], C = rp[2];
                float xr[12] = {A.x, A.y, A.z, A.w,
                                B.x, B.y, B.z, B.w,
                                C.x, C.y, C.z, C.w};
#pragma unroll
                for (int dx = 0; dx < 3; dx++) {
                    const int tap = dy * 3 + dx;
                    const unsigned long long* wp = (const unsigned long long*)
                        (s_w + (ic * 9 + tap) * WSTRIDE + ocg * 8);
                    unsigned long long w0 = wp[0], w1 = wp[1],
                                       w2 = wp[2], w3 = wp[3];
#pragma unroll
                    for (int j = 0; j < 8; j++) {
                        unsigned long long xx = pk2(xr[dx + j], xr[dx + j]);
                        ffma2(acc2[0][j], w0, xx);
                        ffma2(acc2[1][j], w1, xx);
                        ffma2(acc2[2][j], w2, xx);
                        ffma2(acc2[3][j], w3, xx);
                    }
                }
            }
        }
        __syncthreads();
    }

    // epilogue: BN(eval)+LeakyReLU, optional transpose, STG.128 stores
    const bool dobn = (bng != nullptr);
    const int b = n >> 3, tt = n & 7;
    const int y = ty0 + prow;
    const int xbase = tx0 + pxb;
#pragma unroll
    for (int ip = 0; ip < 4; ip++) {
        int ocA = oc0 + ocg * 8 + 2 * ip;
        int ocB = ocA + 1;
        float scA = 1.f, biA = 0.f, scB = 1.f, biB = 0.f;
        if (dobn) {
            scA = bng[ocA] * rsqrtf(bnv[ocA] + 1e-5f);
            biA = bnb[ocA] - bnm[ocA] * scA;
            scB = bng[ocB] * rsqrtf(bnv[ocB] + 1e-5f);
            biB = bnb[ocB] - bnm[ocB] * scB;
        }
        float rA[8], rB[8];
#pragma unroll
        for (int j = 0; j < 8; j++) {
            float vA, vB;
            unpk2(acc2[ip][j], vA, vB);
            if (dobn) {
                vA = vA * scA + biA;  vA = (vA > 0.f) ? vA : 0.01f * vA;
                vB = vB * scB + biB;  vB = (vB > 0.f) ? vB : 0.01f * vB;
            }
            rA[j] = vA;  rB[j] = vB;
        }
        long long oA, oB;
        if (outTrans) {
            oA = ((((long long)b * Cout + ocA) * 8 + tt) << 12) + y * 64 + xbase;
            oB = ((((long long)b * Cout + ocB) * 8 + tt) << 12) + y * 64 + xbase;
        } else {
            oA = (((long long)n * Cout + ocA) << 12) + y * 64 + xbase;
            oB = (((long long)n * Cout + ocB) << 12) + y * 64 + xbase;
        }
        *(float4*)(out + oA)     = make_float4(rA[0], rA[1], rA[2], rA[3]);
        *(float4*)(out + oA + 4) = make_float4(rA[4], rA[5], rA[6], rA[7]);
        *(float4*)(out + oB)     = make_float4(rB[0], rB[1], rB[2], rB[3]);
        *(float4*)(out + oB + 4) = make_float4(rB[4], rB[5], rB[6], rB[7]);
    }
}

// ---------------- per-channel bilinear sampling (ConvOffset2D semantics) ----
__global__ void k_deform(const float* __restrict__ x, const float* __restrict__ off,
                         float* __restrict__ out, int C)
{
    long long idx = (long long)blockIdx.x * 256 + threadIdx.x;
    int pix = (int)(idx & 4095);
    long long r = idx >> 12;
    int c = (int)(r % C);
    int n = (int)(r / C);
    int h = pix >> 6, w = pix & 63;

    const float* offb = off + (((long long)n * C + c) << 13);
    float oy = offb[2 * pix];
    float ox = offb[2 * pix + 1];

    float cy = fminf(fmaxf((float)h + oy, 0.f), 63.f);
    float cx = fminf(fmaxf((float)w + ox, 0.f), 63.f);
    float y0f = floorf(cy), x0f = floorf(cx);
    float ty = cy - y0f, tx = cx - x0f;
    int y0 = (int)y0f, x0 = (int)x0f;
    int y1 = min(y0 + 1, 63), x1 = min(x0 + 1, 63);

    const float* xc = x + (((long long)n * C + c) << 12);
    float v00 = xc[(y0 << 6) + x0];
    float v01 = xc[(y0 << 6) + x1];
    float v10 = xc[(y1 << 6) + x0];
    float v11 = xc[(y1 << 6) + x1];

    out[idx] = v00 * (1.f - ty) * (1.f - tx) + v01 * (1.f - ty) * tx +
               v10 * ty * (1.f - tx)         + v11 * ty * tx;
}

// ---------------- launch ----------------
extern "C" void kernel_launch(void* const* d_in, const int* in_sizes, int n_in,
                              void* d_out, int out_size)
{
    const float* x      = (const float*)d_in[0];
    const float* w_off1 = (const float*)d_in[3];
    const float* w1     = (const float*)d_in[4];
    const float* g1     = (const float*)d_in[5];
    const float* b1     = (const float*)d_in[6];
    const float* m1     = (const float*)d_in[7];
    const float* v1     = (const float*)d_in[8];
    const float* w_off2 = (const float*)d_in[9];
    const float* w2     = (const float*)d_in[10];
    const float* g2     = (const float*)d_in[11];
    const float* b2     = (const float*)d_in[12];
    const float* m2     = (const float*)d_in[13];
    const float* v2     = (const float*)d_in[14];
    float* out = (float*)d_out;

    float *nd, *off1, *def1, *c1, *off2, *def2;
    cudaGetSymbolAddress((void**)&nd,   g_nd);
    cudaGetSymbolAddress((void**)&off1, g_off1);
    cudaGetSymbolAddress((void**)&def1, g_def1);
    cudaGetSymbolAddress((void**)&c1,   g_c1);
    cudaGetSymbolAddress((void**)&off2, g_off2);
    cudaGetSymbolAddress((void**)&def2, g_def2);

    k_transpose_in<<<131072, 256>>>(x, nd);

    k_conv3x3<<<dim3(16, 8, NIMG), 256>>>(nd, w_off1,
        nullptr, nullptr, nullptr, nullptr, off1, 256, 512, 0);

    k_deform<<<131072, 256>>>(nd, off1, def1, 256);

    k_conv3x3<<<dim3(16, 1, NIMG), 256>>>(def1, w1, g1, b1, m1, v1, c1, 256, 64, 0);

    k_conv3x3<<<dim3(16, 2, NIMG), 256>>>(c1, w_off2,
        nullptr, nullptr, nullptr, nullptr, off2, 64, 128, 0);

    k_deform<<<32768, 256>>>(c1, off2, def2, 64);

    k_conv3x3<<<dim3(16, 1, NIMG), 256>>>(def2, w2, g2, b2, m2, v2, out, 64, 64, 1);
}

// round 4
// speedup vs baseline: 1.5304x; 1.0212x over previous
#include <cuda_runtime.h>

// Problem constants (fixed shapes)
//   x: (4, 256, 8, 64, 64)  -> images N=32 (Bs*T), C=256, H=W=64
//   conv_off1: 256 -> 512 ; conv1: 256 -> 64 ; conv_off2: 64 -> 128 ; conv2: 64 -> 64

#define HW   4096
#define NIMG 32

// ---------------- device scratch (no allocations allowed) ----------------
__device__ float g_nd  [32u * 256u * 4096u];
__device__ float g_off1[32u * 512u * 4096u];
__device__ float g_def1[32u * 256u * 4096u];
__device__ float g_c1  [32u *  64u * 4096u];
__device__ float g_off2[32u * 128u * 4096u];
__device__ float g_def2[32u *  64u * 4096u];

// ---------------- packed f32x2 helpers ----------------
__device__ __forceinline__ unsigned long long pk2(float a, float b) {
    unsigned long long r;
    asm("mov.b64 %0, {%1, %2};" : "=l"(r) : "f"(a), "f"(b));
    return r;
}
__device__ __forceinline__ void unpk2(unsigned long long v, float& a, float& b) {
    asm("mov.b64 {%0, %1}, %2;" : "=f"(a), "=f"(b) : "l"(v));
}
__device__ __forceinline__ void ffma2(unsigned long long& d,
                                      unsigned long long a, unsigned long long b) {
    asm("fma.rn.f32x2 %0, %1, %2, %3;" : "=l"(d) : "l"(a), "l"(b), "l"(d));
}

// ---------------- (Bs,C,T,H,W) -> (Bs*T,C,H,W) ----------------
__global__ void k_transpose_in(const float* __restrict__ x, float* __restrict__ nd)
{
    long long idx = (long long)blockIdx.x * 256 + threadIdx.x;
    int pix = (int)(idx & 4095);
    long long r = idx >> 12;
    int c = (int)(r & 255);
    int n = (int)(r >> 8);
    int b = n >> 3, t = n & 7;
    nd[idx] = x[((((long long)b * 256 + c) * 8 + t) << 12) + pix];
}

// ---------------- direct 3x3 conv, stride 1, pad 1, H=W=64 ----------------
// Block: 64 oc x 16x16 spatial tile, 256 threads.
// Thread: 4 oc-pairs (f32x2) x 8 contiguous pixels in one row.
// Per (ic,dy): 3x LDS.128 row span; 10 packed {x,x} built ONCE; per tap the
// 4 oc-pair weights load as 2x LDS.128 (WSTRIDE=68 keeps 16B alignment).
#define WSTRIDE 68   // weight smem oc-stride (272B rows: 16B-aligned)
#define RSTRIDE 20   // input halo row stride (floats): 16B-aligned rows
__global__ __launch_bounds__(256, 2)
void k_conv3x3(const float* __restrict__ in, const float* __restrict__ wt,
               const float* __restrict__ bng, const float* __restrict__ bnb,
               const float* __restrict__ bnm, const float* __restrict__ bnv,
               float* __restrict__ out, int Cin, int Cout, int outTrans)
{
    __shared__ __align__(16) float s_in[8 * 18 * RSTRIDE];   // 8 ic x 18 x 20
    __shared__ __align__(16) float s_w[72 * WSTRIDE];        // [ic*9+tap][oc pad 68]

    const int n   = blockIdx.z;
    const int oc0 = blockIdx.y << 6;
    const int ty0 = (blockIdx.x >> 2) << 4;
    const int tx0 = (blockIdx.x & 3) << 4;

    const int t    = threadIdx.x;
    const int ocg  = t >> 5;            // warp-constant -> weight broadcast
    const int pxg  = t & 31;
    const int prow = pxg & 15;          // 0..15 row in tile
    const int pxb  = (pxg >> 4) << 3;   // 0 or 8: start col of 8-px strip

    unsigned long long acc2[4][8];
#pragma unroll
    for (int i = 0; i < 4; i++)
#pragma unroll
        for (int j = 0; j < 8; j++) acc2[i][j] = 0ull;

    const float* in_n = in + (long long)n * Cin * HW;

    for (int ic0 = 0; ic0 < Cin; ic0 += 8) {
        // stage input halo (8 x 18 x 20, cols 18-19 padding)
        for (int idx = t; idx < 8 * 18 * RSTRIDE; idx += 256) {
            int ic  = idx / (18 * RSTRIDE);
            int r   = idx - ic * (18 * RSTRIDE);
            int row = r / RSTRIDE;
            int col = r - row * RSTRIDE;
            int iy = row + ty0 - 1;
            int ix = col + tx0 - 1;
            float v = 0.f;
            if ((unsigned)iy < 64u && (unsigned)ix < 64u)
                v = in_n[(long long)(ic0 + ic) * HW + iy * 64 + ix];
            s_in[idx] = v;
        }
        // stage weights: gmem [oc][ic(8)][tap(9)] -> smem [ic*9+tap][oc]
        for (int idx = t; idx < 64 * 72; idx += 256) {
            int oc = idx / 72;
            int r  = idx - oc * 72;
            s_w[r * WSTRIDE + oc] = wt[((long long)(oc0 + oc) * Cin + ic0) * 9 + r];
        }
        __syncthreads();

#pragma unroll
        for (int ic = 0; ic < 8; ic++) {
            const float* sbase = s_in + ic * (18 * RSTRIDE) + prow * RSTRIDE + pxb;
#pragma unroll
            for (int dy = 0; dy < 3; dy++) {
                // 12-float row span, 3 aligned conflict-free LDS.128
                const float4* rp = (const float4*)(sbase + dy * RSTRIDE);
                float4 A = rp[0], B = rp[1], C = rp[2];
                float xr[12] = {A.x, A.y, A.z, A.w,
                                B.x, B.y, B.z, B.w,
                                C.x, C.y, C.z, C.w};
                // hoisted packs: only xr[0..9] are consumed
                unsigned long long xx[10];
#pragma unroll
                for (int q = 0; q < 10; q++) xx[q] = pk2(xr[q], xr[q]);
#pragma unroll
                for (int dx = 0; dx < 3; dx++) {
                    const int tap = dy * 3 + dx;
                    const float* wbase = s_w + (ic * 9 + tap) * WSTRIDE + ocg * 8;
                    ulonglong2 wA = *(const ulonglong2*)(wbase);      // w0,w1
                    ulonglong2 wB = *(const ulonglong2*)(wbase + 4);  // w2,w3
#pragma unroll
                    for (int j = 0; j < 8; j++) {
                        ffma2(acc2[0][j], wA.x, xx[dx + j]);
                        ffma2(acc2[1][j], wA.y, xx[dx + j]);
                        ffma2(acc2[2][j], wB.x, xx[dx + j]);
                        ffma2(acc2[3][j], wB.y, xx[dx + j]);
                    }
                }
            }
        }
        __syncthreads();
    }

    // epilogue: BN(eval)+LeakyReLU, optional transpose, STG.128 stores
    const bool dobn = (bng != nullptr);
    const int b = n >> 3, tt = n & 7;
    const int y = ty0 + prow;
    const int xbase = tx0 + pxb;
#pragma unroll
    for (int ip = 0; ip < 4; ip++) {
        int ocA = oc0 + ocg * 8 + 2 * ip;
        int ocB = ocA + 1;
        float scA = 1.f, biA = 0.f, scB = 1.f, biB = 0.f;
        if (dobn) {
            scA = bng[ocA] * rsqrtf(bnv[ocA] + 1e-5f);
            biA = bnb[ocA] - bnm[ocA] * scA;
            scB = bng[ocB] * rsqrtf(bnv[ocB] + 1e-5f);
            biB = bnb[ocB] - bnm[ocB] * scB;
        }
        float rA[8], rB[8];
#pragma unroll
        for (int j = 0; j < 8; j++) {
            float vA, vB;
            unpk2(acc2[ip][j], vA, vB);
            if (dobn) {
                vA = vA * scA + biA;  vA = (vA > 0.f) ? vA : 0.01f * vA;
                vB = vB * scB + biB;  vB = (vB > 0.f) ? vB : 0.01f * vB;
            }
            rA[j] = vA;  rB[j] = vB;
        }
        long long oA, oB;
        if (outTrans) {
            oA = ((((long long)b * Cout + ocA) * 8 + tt) << 12) + y * 64 + xbase;
            oB = ((((long long)b * Cout + ocB) * 8 + tt) << 12) + y * 64 + xbase;
        } else {
            oA = (((long long)n * Cout + ocA) << 12) + y * 64 + xbase;
            oB = (((long long)n * Cout + ocB) << 12) + y * 64 + xbase;
        }
        *(float4*)(out + oA)     = make_float4(rA[0], rA[1], rA[2], rA[3]);
        *(float4*)(out + oA + 4) = make_float4(rA[4], rA[5], rA[6], rA[7]);
        *(float4*)(out + oB)     = make_float4(rB[0], rB[1], rB[2], rB[3]);
        *(float4*)(out + oB + 4) = make_float4(rB[4], rB[5], rB[6], rB[7]);
    }
}

// ---------------- per-channel bilinear sampling (ConvOffset2D semantics) ----
__global__ void k_deform(const float* __restrict__ x, const float* __restrict__ off,
                         float* __restrict__ out, int C)
{
    long long idx = (long long)blockIdx.x * 256 + threadIdx.x;
    int pix = (int)(idx & 4095);
    long long r = idx >> 12;
    int c = (int)(r % C);
    int n = (int)(r / C);
    int h = pix >> 6, w = pix & 63;

    const float* offb = off + (((long long)n * C + c) << 13);
    float oy = offb[2 * pix];
    float ox = offb[2 * pix + 1];

    float cy = fminf(fmaxf((float)h + oy, 0.f), 63.f);
    float cx = fminf(fmaxf((float)w + ox, 0.f), 63.f);
    float y0f = floorf(cy), x0f = floorf(cx);
    float ty = cy - y0f, tx = cx - x0f;
    int y0 = (int)y0f, x0 = (int)x0f;
    int y1 = min(y0 + 1, 63), x1 = min(x0 + 1, 63);

    const float* xc = x + (((long long)n * C + c) << 12);
    float v00 = xc[(y0 << 6) + x0];
    float v01 = xc[(y0 << 6) + x1];
    float v10 = xc[(y1 << 6) + x0];
    float v11 = xc[(y1 << 6) + x1];

    out[idx] = v00 * (1.f - ty) * (1.f - tx) + v01 * (1.f - ty) * tx +
               v10 * ty * (1.f - tx)         + v11 * ty * tx;
}

// ---------------- launch ----------------
extern "C" void kernel_launch(void* const* d_in, const int* in_sizes, int n_in,
                              void* d_out, int out_size)
{
    const float* x      = (const float*)d_in[0];
    const float* w_off1 = (const float*)d_in[3];
    const float* w1     = (const float*)d_in[4];
    const float* g1     = (const float*)d_in[5];
    const float* b1     = (const float*)d_in[6];
    const float* m1     = (const float*)d_in[7];
    const float* v1     = (const float*)d_in[8];
    const float* w_off2 = (const float*)d_in[9];
    const float* w2     = (const float*)d_in[10];
    const float* g2     = (const float*)d_in[11];
    const float* b2     = (const float*)d_in[12];
    const float* m2     = (const float*)d_in[13];
    const float* v2     = (const float*)d_in[14];
    float* out = (float*)d_out;

    float *nd, *off1, *def1, *c1, *off2, *def2;
    cudaGetSymbolAddress((void**)&nd,   g_nd);
    cudaGetSymbolAddress((void**)&off1, g_off1);
    cudaGetSymbolAddress((void**)&def1, g_def1);
    cudaGetSymbolAddress((void**)&c1,   g_c1);
    cudaGetSymbolAddress((void**)&off2, g_off2);
    cudaGetSymbolAddress((void**)&def2, g_def2);

    k_transpose_in<<<131072, 256>>>(x, nd);

    k_conv3x3<<<dim3(16, 8, NIMG), 256>>>(nd, w_off1,
        nullptr, nullptr, nullptr, nullptr, off1, 256, 512, 0);

    k_deform<<<131072, 256>>>(nd, off1, def1, 256);

    k_conv3x3<<<dim3(16, 1, NIMG), 256>>>(def1, w1, g1, b1, m1, v1, c1, 256, 64, 0);

    k_conv3x3<<<dim3(16, 2, NIMG), 256>>>(c1, w_off2,
        nullptr, nullptr, nullptr, nullptr, off2, 64, 128, 0);

    k_deform<<<32768, 256>>>(c1, off2, def2, 64);

    k_conv3x3<<<dim3(16, 1, NIMG), 256>>>(def2, w2, g2, b2, m2, v2, out, 64, 64, 1);
}

// round 6
// speedup vs baseline: 2.1275x; 1.3901x over previous
#include <cuda_runtime.h>
#include <cuda_bf16.h>
#include <cstdint>

#define HW   4096
#define NIMG 32

// ---------------- device scratch (no allocations allowed) ----------------
__device__ float g_nd  [32u * 256u * 4096u];
__device__ float g_off1[32u * 512u * 4096u];
__device__ float g_def1[32u * 256u * 4096u];
__device__ float g_c1  [32u *  64u * 4096u];
__device__ float g_off2[32u * 128u * 4096u];
__device__ float g_def2[32u *  64u * 4096u];
// bf16-split inputs for tensor conv (NHWC: [n][pix][c])
__device__ __nv_bfloat16 g_xh[32u * 4096u * 256u];
__device__ __nv_bfloat16 g_xl[32u * 4096u * 256u];
// bf16-split weights ([oc][tap][ic])
__device__ __nv_bfloat16 g_wh[512u * 9u * 256u];
__device__ __nv_bfloat16 g_wl[512u * 9u * 256u];

// ---------------- packed f32x2 helpers (scalar convs) ----------------
__device__ __forceinline__ unsigned long long pk2(float a, float b) {
    unsigned long long r;
    asm("mov.b64 %0, {%1, %2};" : "=l"(r) : "f"(a), "f"(b));
    return r;
}
__device__ __forceinline__ void unpk2(unsigned long long v, float& a, float& b) {
    asm("mov.b64 {%0, %1}, %2;" : "=f"(a), "=f"(b) : "l"(v));
}
__device__ __forceinline__ void ffma2(unsigned long long& d,
                                      unsigned long long a, unsigned long long b) {
    asm("fma.rn.f32x2 %0, %1, %2, %3;" : "=l"(d) : "l"(a), "l"(b), "l"(d));
}

// ---------------- mma.sync helpers (base-target, no 'a' features) -----------
__device__ __forceinline__ uint32_t smem_u32(const void* p) {
    uint32_t a;
    asm("{ .reg .u64 t; cvta.to.shared.u64 t, %1; cvt.u32.u64 %0, t; }"
        : "=r"(a) : "l"(p));
    return a;
}
__device__ __forceinline__ void ldsm_x4(uint32_t& r0, uint32_t& r1,
                                        uint32_t& r2, uint32_t& r3, uint32_t addr) {
    asm volatile("ldmatrix.sync.aligned.m8n8.x4.shared.b16 {%0,%1,%2,%3}, [%4];"
                 : "=r"(r0), "=r"(r1), "=r"(r2), "=r"(r3) : "r"(addr));
}
__device__ __forceinline__ void mma_bf16(float* c, const uint32_t* a,
                                         const uint32_t* b) {
    asm volatile(
        "mma.sync.aligned.m16n8k16.row.col.f32.bf16.bf16.f32 "
        "{%0,%1,%2,%3}, {%4,%5,%6,%7}, {%8,%9}, {%0,%1,%2,%3};"
        : "+f"(c[0]), "+f"(c[1]), "+f"(c[2]), "+f"(c[3])
        : "r"(a[0]), "r"(a[1]), "r"(a[2]), "r"(a[3]), "r"(b[0]), "r"(b[1]));
}

// ---------------- (Bs,C,T,H,W) -> (Bs*T,C,H,W) ----------------
__global__ void k_transpose_in(const float* __restrict__ x, float* __restrict__ nd)
{
    long long idx = (long long)blockIdx.x * 256 + threadIdx.x;
    int pix = (int)(idx & 4095);
    long long r = idx >> 12;
    int c = (int)(r & 255);
    int n = (int)(r >> 8);
    int b = n >> 3, t = n & 7;
    nd[idx] = x[((((long long)b * 256 + c) * 8 + t) << 12) + pix];
}

// ---------------- prep: x -> NHWC bf16 hi/lo (smem transpose) ----------------
__global__ void k_prep_x(const float* __restrict__ x,
                         __nv_bfloat16* __restrict__ xh, __nv_bfloat16* __restrict__ xl)
{
    __shared__ float sm[32][33];
    int n    = blockIdx.z;
    int c0   = blockIdx.y << 5;
    int pix0 = blockIdx.x << 5;
    int tx = threadIdx.x, ty = threadIdx.y;
    int b = n >> 3, t = n & 7;
#pragma unroll
    for (int q = 0; q < 4; q++) {
        int c = c0 + ty + q * 8;
        sm[ty + q * 8][tx] = x[((((long long)b * 256 + c) * 8 + t) << 12) + pix0 + tx];
    }
    __syncthreads();
#pragma unroll
    for (int q = 0; q < 4; q++) {
        int pix = pix0 + ty + q * 8;
        float v = sm[tx][ty + q * 8];
        __nv_bfloat16 hi = __float2bfloat16(v);
        __nv_bfloat16 lo = __float2bfloat16(v - __bfloat162float(hi));
        long long o = ((long long)n * 4096 + pix) * 256 + c0 + tx;
        xh[o] = hi;
        xl[o] = lo;
    }
}

// ---------------- prep: w (oc,ic,3,3) -> [oc][tap][ic] bf16 hi/lo -------------
__global__ void k_prep_w(const float* __restrict__ w,
                         __nv_bfloat16* __restrict__ wh, __nv_bfloat16* __restrict__ wl,
                         int Cin, int total)
{
    int i = blockIdx.x * 256 + threadIdx.x;
    if (i >= total) return;
    int oc  = i / (Cin * 9);
    int r   = i - oc * (Cin * 9);
    int tap = r / Cin;
    int ic  = r - tap * Cin;
    float v = w[(long long)(oc * Cin + ic) * 9 + tap];
    __nv_bfloat16 hi = __float2bfloat16(v);
    __nv_bfloat16 lo = __float2bfloat16(v - __bfloat162float(hi));
    wh[i] = hi;
    wl[i] = lo;
}

// ---------------- mma.sync conv (off1): D[128 px][128 oc] -------------------
// grid.x = image*32 + Mtile (128 px = 2 image rows), grid.y = oc-tile.
// 256 threads = 8 warps (4 M x 2 N). Warp tile: 32 px x 64 oc.
// K looped as 9 taps x (Cin/64) ic-chunks; bf16 split: passes hh, lh, hl.
#define ASTRIDE 72   // bf16 row stride (144B): ldmatrix conflict-free
__global__ __launch_bounds__(256)
void k_conv_mma(const __nv_bfloat16* __restrict__ xh, const __nv_bfloat16* __restrict__ xl,
                const __nv_bfloat16* __restrict__ wh, const __nv_bfloat16* __restrict__ wl,
                float* __restrict__ out, int Cin, int Cout)
{
    extern __shared__ __align__(16) __nv_bfloat16 sm[];
    __nv_bfloat16* sAh = sm;                    // [128][72]
    __nv_bfloat16* sAl = sm + 128 * ASTRIDE;
    __nv_bfloat16* sBh = sm + 2 * 128 * ASTRIDE;
    __nv_bfloat16* sBl = sm + 3 * 128 * ASTRIDE;

    const int tid  = threadIdx.x;
    const int lane = tid & 31;
    const int wid  = tid >> 5;
    const int wm   = wid >> 1;          // 0..3  (px)
    const int wn   = wid & 1;           // 0..1  (oc)

    const int n   = blockIdx.x >> 5;
    const int mt  = blockIdx.x & 31;
    const int oc0 = blockIdx.y << 7;
    const int nic = Cin >> 6;
    const int nchunks = 9 * nic;

    float acc[2][8][4];
#pragma unroll
    for (int i = 0; i < 2; i++)
#pragma unroll
        for (int j = 0; j < 8; j++)
#pragma unroll
            for (int q = 0; q < 4; q++) acc[i][j][q] = 0.f;

    // ldmatrix lane->address components
    const uint32_t uAh = smem_u32(sAh), uAl = smem_u32(sAl);
    const uint32_t uBh = smem_u32(sBh), uBl = smem_u32(sBl);
    const int aRow = wm * 32 + (lane & 15);          // + i*16
    const int aOff = (lane >> 4) << 4;               // 16B half
    const int bRow = wn * 64 + (lane & 7) + ((lane >> 4) << 3);  // + j2*16
    const int bOff = ((lane >> 3) & 1) << 4;

    for (int chunk = 0; chunk < nchunks; chunk++) {
        const int tap = chunk / nic;
        const int ic0 = (chunk - tap * nic) << 6;
        const int dy = tap / 3 - 1, dx = tap % 3 - 1;

        __syncthreads();
        // stage A: 2 pre x 128 px-rows x 8 16B-units (tap-shifted, zero-pad)
        for (int i = tid; i < 2048; i += 256) {
            int pre = i >> 10;
            int f   = i & 1023;
            int m   = f >> 3;
            int u   = f & 7;
            int y = (mt << 1) + (m >> 6), xq = m & 63;
            int ys = y + dy, xs = xq + dx;
            uint4 v = make_uint4(0, 0, 0, 0);
            if ((unsigned)ys < 64u && (unsigned)xs < 64u) {
                const __nv_bfloat16* src = (pre ? xl : xh) +
                    (((long long)n * 4096 + ys * 64 + xs) * 256 + ic0 + (u << 3));
                v = *(const uint4*)src;
            }
            *(uint4*)((pre ? sAl : sAh) + m * ASTRIDE + (u << 3)) = v;
        }
        // stage B: 2 pre x 128 oc-rows x 8 units
        for (int i = tid; i < 2048; i += 256) {
            int pre = i >> 10;
            int f   = i & 1023;
            int r   = f >> 3;
            int u   = f & 7;
            const __nv_bfloat16* src = (pre ? wl : wh) +
                ((long long)(oc0 + r) * 9 + tap) * Cin + ic0 + (u << 3);
            uint4 v = *(const uint4*)src;
            *(uint4*)((pre ? sBl : sBh) + r * ASTRIDE + (u << 3)) = v;
        }
        __syncthreads();

#pragma unroll
        for (int ks = 0; ks < 4; ks++) {
            const int kbyte = ks * 32;
            uint32_t ah[2][4], al[2][4], bh[4][4], bl[4][4];
            // A hi fragments (2 m16 tiles)
#pragma unroll
            for (int i = 0; i < 2; i++)
                ldsm_x4(ah[i][0], ah[i][1], ah[i][2], ah[i][3],
                        uAh + (aRow + i * 16) * (ASTRIDE * 2) + kbyte + aOff);
            // B hi fragments (4 n16 groups)
#pragma unroll
            for (int j2 = 0; j2 < 4; j2++)
                ldsm_x4(bh[j2][0], bh[j2][1], bh[j2][2], bh[j2][3],
                        uBh + (bRow + j2 * 16) * (ASTRIDE * 2) + kbyte + bOff);
            // pass hh
#pragma unroll
            for (int i = 0; i < 2; i++)
#pragma unroll
                for (int j2 = 0; j2 < 4; j2++) {
                    mma_bf16(acc[i][j2 * 2 + 0], ah[i], &bh[j2][0]);
                    mma_bf16(acc[i][j2 * 2 + 1], ah[i], &bh[j2][2]);
                }
            // A lo, pass lh (Al x Bh)
#pragma unroll
            for (int i = 0; i < 2; i++)
                ldsm_x4(al[i][0], al[i][1], al[i][2], al[i][3],
                        uAl + (aRow + i * 16) * (ASTRIDE * 2) + kbyte + aOff);
#pragma unroll
            for (int i = 0; i < 2; i++)
#pragma unroll
                for (int j2 = 0; j2 < 4; j2++) {
                    mma_bf16(acc[i][j2 * 2 + 0], al[i], &bh[j2][0]);
                    mma_bf16(acc[i][j2 * 2 + 1], al[i], &bh[j2][2]);
                }
            // B lo, pass hl (Ah x Bl)
#pragma unroll
            for (int j2 = 0; j2 < 4; j2++)
                ldsm_x4(bl[j2][0], bl[j2][1], bl[j2][2], bl[j2][3],
                        uBl + (bRow + j2 * 16) * (ASTRIDE * 2) + kbyte + bOff);
#pragma unroll
            for (int i = 0; i < 2; i++)
#pragma unroll
                for (int j2 = 0; j2 < 4; j2++) {
                    mma_bf16(acc[i][j2 * 2 + 0], ah[i], &bl[j2][0]);
                    mma_bf16(acc[i][j2 * 2 + 1], ah[i], &bl[j2][2]);
                }
        }
    }

    // epilogue: acc -> out NCHW fp32
    const int qrow = lane >> 2;          // 0..7
    const int qcol = (lane & 3) << 1;    // 0,2,4,6
    const long long pixbase = (long long)mt * 128 + wm * 32;
#pragma unroll
    for (int i = 0; i < 2; i++) {
#pragma unroll
        for (int j = 0; j < 8; j++) {
            int oc = oc0 + wn * 64 + j * 8 + qcol;
            long long p0 = pixbase + i * 16 + qrow;
            float* o0 = out + ((long long)n * Cout + oc) * 4096;
            float* o1 = out + ((long long)n * Cout + oc + 1) * 4096;
            o0[p0]     = acc[i][j][0];
            o1[p0]     = acc[i][j][1];
            o0[p0 + 8] = acc[i][j][2];
            o1[p0 + 8] = acc[i][j][3];
        }
    }
}

// ---------------- scalar direct 3x3 conv (R4, known-good) ----------------
#define WSTRIDE 68
#define RSTRIDE 20
__global__ __launch_bounds__(256, 2)
void k_conv3x3(const float* __restrict__ in, const float* __restrict__ wt,
               const float* __restrict__ bng, const float* __restrict__ bnb,
               const float* __restrict__ bnm, const float* __restrict__ bnv,
               float* __restrict__ out, int Cin, int Cout, int outTrans)
{
    __shared__ __align__(16) float s_in[8 * 18 * RSTRIDE];
    __shared__ __align__(16) float s_w[72 * WSTRIDE];

    const int n   = blockIdx.z;
    const int oc0 = blockIdx.y << 6;
    const int ty0 = (blockIdx.x >> 2) << 4;
    const int tx0 = (blockIdx.x & 3) << 4;

    const int t    = threadIdx.x;
    const int ocg  = t >> 5;
    const int pxg  = t & 31;
    const int prow = pxg & 15;
    const int pxb  = (pxg >> 4) << 3;

    unsigned long long acc2[4][8];
#pragma unroll
    for (int i = 0; i < 4; i++)
#pragma unroll
        for (int j = 0; j < 8; j++) acc2[i][j] = 0ull;

    const float* in_n = in + (long long)n * Cin * HW;

    for (int ic0 = 0; ic0 < Cin; ic0 += 8) {
        for (int idx = t; idx < 8 * 18 * RSTRIDE; idx += 256) {
            int ic  = idx / (18 * RSTRIDE);
            int r   = idx - ic * (18 * RSTRIDE);
            int row = r / RSTRIDE;
            int col = r - row * RSTRIDE;
            int iy = row + ty0 - 1;
            int ix = col + tx0 - 1;
            float v = 0.f;
            if ((unsigned)iy < 64u && (unsigned)ix < 64u)
                v = in_n[(long long)(ic0 + ic) * HW + iy * 64 + ix];
            s_in[idx] = v;
        }
        for (int idx = t; idx < 64 * 72; idx += 256) {
            int oc = idx / 72;
            int r  = idx - oc * 72;
            s_w[r * WSTRIDE + oc] = wt[((long long)(oc0 + oc) * Cin + ic0) * 9 + r];
        }
        __syncthreads();

#pragma unroll
        for (int ic = 0; ic < 8; ic++) {
            const float* sbase = s_in + ic * (18 * RSTRIDE) + prow * RSTRIDE + pxb;
#pragma unroll
            for (int dy = 0; dy < 3; dy++) {
                const float4* rp = (const float4*)(sbase + dy * RSTRIDE);
                float4 A = rp[0], B = rp[1], C = rp[2];
                float xr[12] = {A.x, A.y, A.z, A.w,
                                B.x, B.y, B.z, B.w,
                                C.x, C.y, C.z, C.w};
                unsigned long long xx[10];
#pragma unroll
                for (int q = 0; q < 10; q++) xx[q] = pk2(xr[q], xr[q]);
#pragma unroll
                for (int dx = 0; dx < 3; dx++) {
                    const int tap = dy * 3 + dx;
                    const float* wbase = s_w + (ic * 9 + tap) * WSTRIDE + ocg * 8;
                    ulonglong2 wA = *(const ulonglong2*)(wbase);
                    ulonglong2 wB = *(const ulonglong2*)(wbase + 4);
#pragma unroll
                    for (int j = 0; j < 8; j++) {
                        ffma2(acc2[0][j], wA.x, xx[dx + j]);
                        ffma2(acc2[1][j], wA.y, xx[dx + j]);
                        ffma2(acc2[2][j], wB.x, xx[dx + j]);
                        ffma2(acc2[3][j], wB.y, xx[dx + j]);
                    }
                }
            }
        }
        __syncthreads();
    }

    const bool dobn = (bng != nullptr);
    const int b = n >> 3, tt = n & 7;
    const int y = ty0 + prow;
    const int xbase = tx0 + pxb;
#pragma unroll
    for (int ip = 0; ip < 4; ip++) {
        int ocA = oc0 + ocg * 8 + 2 * ip;
        int ocB = ocA + 1;
        float scA = 1.f, biA = 0.f, scB = 1.f, biB = 0.f;
        if (dobn) {
            scA = bng[ocA] * rsqrtf(bnv[ocA] + 1e-5f);
            biA = bnb[ocA] - bnm[ocA] * scA;
            scB = bng[ocB] * rsqrtf(bnv[ocB] + 1e-5f);
            biB = bnb[ocB] - bnm[ocB] * scB;
        }
        float rA[8], rB[8];
#pragma unroll
        for (int j = 0; j < 8; j++) {
            float vA, vB;
            unpk2(acc2[ip][j], vA, vB);
            if (dobn) {
                vA = vA * scA + biA;  vA = (vA > 0.f) ? vA : 0.01f * vA;
                vB = vB * scB + biB;  vB = (vB > 0.f) ? vB : 0.01f * vB;
            }
            rA[j] = vA;  rB[j] = vB;
        }
        long long oA, oB;
        if (outTrans) {
            oA = ((((long long)b * Cout + ocA) * 8 + tt) << 12) + y * 64 + xbase;
            oB = ((((long long)b * Cout + ocB) * 8 + tt) << 12) + y * 64 + xbase;
        } else {
            oA = (((long long)n * Cout + ocA) << 12) + y * 64 + xbase;
            oB = (((long long)n * Cout + ocB) << 12) + y * 64 + xbase;
        }
        *(float4*)(out + oA)     = make_float4(rA[0], rA[1], rA[2], rA[3]);
        *(float4*)(out + oA + 4) = make_float4(rA[4], rA[5], rA[6], rA[7]);
        *(float4*)(out + oB)     = make_float4(rB[0], rB[1], rB[2], rB[3]);
        *(float4*)(out + oB + 4) = make_float4(rB[4], rB[5], rB[6], rB[7]);
    }
}

// ---------------- per-channel bilinear sampling ----------------
__global__ void k_deform(const float* __restrict__ x, const float* __restrict__ off,
                         float* __restrict__ out, int C)
{
    long long idx = (long long)blockIdx.x * 256 + threadIdx.x;
    int pix = (int)(idx & 4095);
    long long r = idx >> 12;
    int c = (int)(r % C);
    int n = (int)(r / C);
    int h = pix >> 6, w = pix & 63;

    const float* offb = off + (((long long)n * C + c) << 13);
    float oy = offb[2 * pix];
    float ox = offb[2 * pix + 1];

    float cy = fminf(fmaxf((float)h + oy, 0.f), 63.f);
    float cx = fminf(fmaxf((float)w + ox, 0.f), 63.f);
    float y0f = floorf(cy), x0f = floorf(cx);
    float ty = cy - y0f, tx = cx - x0f;
    int y0 = (int)y0f, x0 = (int)x0f;
    int y1 = min(y0 + 1, 63), x1 = min(x0 + 1, 63);

    const float* xc = x + (((long long)n * C + c) << 12);
    float v00 = xc[(y0 << 6) + x0];
    float v01 = xc[(y0 << 6) + x1];
    float v10 = xc[(y1 << 6) + x0];
    float v11 = xc[(y1 << 6) + x1];

    out[idx] = v00 * (1.f - ty) * (1.f - tx) + v01 * (1.f - ty) * tx +
               v10 * ty * (1.f - tx)         + v11 * ty * tx;
}

// ---------------- launch ----------------
extern "C" void kernel_launch(void* const* d_in, const int* in_sizes, int n_in,
                              void* d_out, int out_size)
{
    const float* x      = (const float*)d_in[0];
    const float* w_off1 = (const float*)d_in[3];
    const float* w1     = (const float*)d_in[4];
    const float* g1     = (const float*)d_in[5];
    const float* b1     = (const float*)d_in[6];
    const float* m1     = (const float*)d_in[7];
    const float* v1     = (const float*)d_in[8];
    const float* w_off2 = (const float*)d_in[9];
    const float* w2     = (const float*)d_in[10];
    const float* g2     = (const float*)d_in[11];
    const float* b2     = (const float*)d_in[12];
    const float* m2     = (const float*)d_in[13];
    const float* v2     = (const float*)d_in[14];
    float* out = (float*)d_out;

    float *nd, *off1, *def1, *c1, *off2, *def2;
    __nv_bfloat16 *xh, *xl, *wh, *wl;
    cudaGetSymbolAddress((void**)&nd,   g_nd);
    cudaGetSymbolAddress((void**)&off1, g_off1);
    cudaGetSymbolAddress((void**)&def1, g_def1);
    cudaGetSymbolAddress((void**)&c1,   g_c1);
    cudaGetSymbolAddress((void**)&off2, g_off2);
    cudaGetSymbolAddress((void**)&def2, g_def2);
    cudaGetSymbolAddress((void**)&xh,   g_xh);
    cudaGetSymbolAddress((void**)&xl,   g_xl);
    cudaGetSymbolAddress((void**)&wh,   g_wh);
    cudaGetSymbolAddress((void**)&wl,   g_wl);

    const int MMA_SMEM = 4 * 128 * 72 * 2;   // 73728 B
    cudaFuncSetAttribute(k_conv_mma, cudaFuncAttributeMaxDynamicSharedMemorySize,
                         MMA_SMEM);

    // preps
    k_transpose_in<<<131072, 256>>>(x, nd);
    k_prep_x<<<dim3(128, 8, NIMG), dim3(32, 8)>>>(x, xh, xl);
    {
        int total = 512 * 9 * 256;
        k_prep_w<<<(total + 255) / 256, 256>>>(w_off1, wh, wl, 256, total);
    }

    // offset conv 1 (mma.sync bf16-split): 256 -> 512
    k_conv_mma<<<dim3(NIMG * 32, 4), 256, MMA_SMEM>>>(xh, xl, wh, wl, off1, 256, 512);

    k_deform<<<131072, 256>>>(nd, off1, def1, 256);

    k_conv3x3<<<dim3(16, 1, NIMG), 256>>>(def1, w1, g1, b1, m1, v1, c1, 256, 64, 0);

    k_conv3x3<<<dim3(16, 2, NIMG), 256>>>(c1, w_off2,
        nullptr, nullptr, nullptr, nullptr, off2, 64, 128, 0);

    k_deform<<<32768, 256>>>(c1, off2, def2, 64);

    k_conv3x3<<<dim3(16, 1, NIMG), 256>>>(def2, w2, g2, b2, m2, v2, out, 64, 64, 1);
}

// round 7
// speedup vs baseline: 3.0073x; 1.4135x over previous
#include <cuda_runtime.h>
#include <cuda_bf16.h>
#include <cstdint>

#define HW   4096
#define NIMG 32

// ---------------- device scratch (no allocations allowed) ----------------
__device__ float g_nd  [32u * 256u * 4096u];   // x transposed (N,C,H,W) f32
__device__ float g_off1[32u * 512u * 4096u];   // offsets 1 (NCHW f32)
__device__ float g_c1  [32u *  64u * 4096u];   // conv1 out (NCHW f32, deform2 src)
__device__ float g_off2[32u * 128u * 4096u];   // offsets 2 (NCHW f32)
// NHWC bf16 hi/lo operands
__device__ __nv_bfloat16 g_xh [32u * 4096u * 256u];
__device__ __nv_bfloat16 g_xl [32u * 4096u * 256u];
__device__ __nv_bfloat16 g_dh1[32u * 4096u * 256u];
__device__ __nv_bfloat16 g_dl1[32u * 4096u * 256u];
__device__ __nv_bfloat16 g_ch1[32u * 4096u * 64u];
__device__ __nv_bfloat16 g_cl1[32u * 4096u * 64u];
__device__ __nv_bfloat16 g_dh2[32u * 4096u * 64u];
__device__ __nv_bfloat16 g_dl2[32u * 4096u * 64u];
// weights, all 4 convs, [oc][tap][ic] hi/lo
#define WO_OFF1 0
#define WO_C1   1179648
#define WO_OFF2 1327104
#define WO_C2   1400832
__device__ __nv_bfloat16 g_wh[1437696];
__device__ __nv_bfloat16 g_wl[1437696];

// ---------------- helpers ----------------
__device__ __forceinline__ uint32_t smem_u32(const void* p) {
    uint32_t a;
    asm("{ .reg .u64 t; cvta.to.shared.u64 t, %1; cvt.u32.u64 %0, t; }"
        : "=r"(a) : "l"(p));
    return a;
}
__device__ __forceinline__ void ldsm_x4(uint32_t& r0, uint32_t& r1,
                                        uint32_t& r2, uint32_t& r3, uint32_t addr) {
    asm volatile("ldmatrix.sync.aligned.m8n8.x4.shared.b16 {%0,%1,%2,%3}, [%4];"
                 : "=r"(r0), "=r"(r1), "=r"(r2), "=r"(r3) : "r"(addr));
}
__device__ __forceinline__ void mma_bf16(float* c, const uint32_t* a,
                                         const uint32_t* b) {
    asm volatile(
        "mma.sync.aligned.m16n8k16.row.col.f32.bf16.bf16.f32 "
        "{%0,%1,%2,%3}, {%4,%5,%6,%7}, {%8,%9}, {%0,%1,%2,%3};"
        : "+f"(c[0]), "+f"(c[1]), "+f"(c[2]), "+f"(c[3])
        : "r"(a[0]), "r"(a[1]), "r"(a[2]), "r"(a[3]), "r"(b[0]), "r"(b[1]));
}
__device__ __forceinline__ void cpa16(uint32_t dst, const void* src, uint32_t sz) {
    asm volatile("cp.async.cg.shared.global [%0], [%1], 16, %2;"
                 :: "r"(dst), "l"(src), "r"(sz));
}
#define CPA_COMMIT() asm volatile("cp.async.commit_group;" ::: "memory")
#define CPA_WAIT1()  asm volatile("cp.async.wait_group 1;" ::: "memory")

// smem buffer geometry (bytes): per buffer Ah|Al|Bh|Bl, 128 rows x 144B
#define ROWB  144
#define MATB  (128 * ROWB)        // 18432
#define BUFB  (4 * MATB)          // 73728
#define SMEMB (2 * BUFB)          // 147456

// ---------------- (Bs,C,T,H,W) -> (Bs*T,C,H,W) ----------------
__global__ void k_transpose_in(const float* __restrict__ x, float* __restrict__ nd)
{
    long long idx = (long long)blockIdx.x * 256 + threadIdx.x;
    int pix = (int)(idx & 4095);
    long long r = idx >> 12;
    int c = (int)(r & 255);
    int n = (int)(r >> 8);
    int b = n >> 3, t = n & 7;
    nd[idx] = x[((((long long)b * 256 + c) * 8 + t) << 12) + pix];
}

// ---------------- prep: x -> NHWC bf16 hi/lo ----------------
__global__ void k_prep_x(const float* __restrict__ x,
                         __nv_bfloat16* __restrict__ xh, __nv_bfloat16* __restrict__ xl)
{
    __shared__ float sm[32][33];
    int n    = blockIdx.z;
    int c0   = blockIdx.y << 5;
    int pix0 = blockIdx.x << 5;
    int tx = threadIdx.x, ty = threadIdx.y;
    int b = n >> 3, t = n & 7;
#pragma unroll
    for (int q = 0; q < 4; q++) {
        int c = c0 + ty + q * 8;
        sm[ty + q * 8][tx] = x[((((long long)b * 256 + c) * 8 + t) << 12) + pix0 + tx];
    }
    __syncthreads();
#pragma unroll
    for (int q = 0; q < 4; q++) {
        int pix = pix0 + ty + q * 8;
        float v = sm[tx][ty + q * 8];
        __nv_bfloat16 hi = __float2bfloat16(v);
        __nv_bfloat16 lo = __float2bfloat16(v - __bfloat162float(hi));
        long long o = ((long long)n * 4096 + pix) * 256 + c0 + tx;
        xh[o] = hi;
        xl[o] = lo;
    }
}

// ---------------- prep: w (oc,ic,3,3) -> [oc][tap][ic] bf16 hi/lo ------------
__global__ void k_prep_w(const float* __restrict__ w,
                         __nv_bfloat16* __restrict__ wh, __nv_bfloat16* __restrict__ wl,
                         int Cin, int total)
{
    int i = blockIdx.x * 256 + threadIdx.x;
    if (i >= total) return;
    int oc  = i / (Cin * 9);
    int r   = i - oc * (Cin * 9);
    int tap = r / Cin;
    int ic  = r - tap * Cin;
    float v = w[(long long)(oc * Cin + ic) * 9 + tap];
    __nv_bfloat16 hi = __float2bfloat16(v);
    __nv_bfloat16 lo = __float2bfloat16(v - __bfloat162float(hi));
    wh[i] = hi;
    wl[i] = lo;
}

// ---------------- staging (cp.async) into one buffer ----------------
__device__ __forceinline__ void stage_chunk(
    uint32_t bufbase, int tid, int chunk, int nic, int n, int mt, int oc0,
    int Cin, int NOC,
    const __nv_bfloat16* xh, const __nv_bfloat16* xl,
    const __nv_bfloat16* wh, const __nv_bfloat16* wl)
{
    const int tap = chunk / nic;
    const int ic0 = (chunk - tap * nic) << 6;
    const int dy = tap / 3 - 1, dx = tap % 3 - 1;
    // A: 2 pre x 128 rows x 8 units
    for (int i = tid; i < 2048; i += 256) {
        int pre = i >> 10;
        int f   = i & 1023;
        int m   = f >> 3;
        int u   = f & 7;
        int y = (mt << 1) + (m >> 6), xq = m & 63;
        int ys = y + dy, xs = xq + dx;
        bool ok = ((unsigned)ys < 64u) && ((unsigned)xs < 64u);
        const __nv_bfloat16* base = pre ? xl : xh;
        const __nv_bfloat16* src = ok ?
            base + (((long long)n * 4096 + ys * 64 + xs) * Cin + ic0 + (u << 3)) : base;
        cpa16(bufbase + pre * MATB + m * ROWB + (u << 4), src, ok ? 16u : 0u);
    }
    // B: 2 pre x NOC rows x 8 units
    const int btot = NOC << 4;
    for (int i = tid; i < btot; i += 256) {
        int pre = i / (NOC << 3);
        int f   = i - pre * (NOC << 3);
        int r   = f >> 3;
        int u   = f & 7;
        const __nv_bfloat16* src = (pre ? wl : wh) +
            ((long long)(oc0 + r) * 9 + tap) * Cin + ic0 + (u << 3);
        cpa16(bufbase + 2 * MATB + pre * MATB + r * ROWB + (u << 4), src, 16u);
    }
}

// ---------------- mma implicit-GEMM conv: D[128 px][NOC oc] ------------------
// grid.x = n*32 + mt, grid.y = oc tile. 8 warps: 4 (px) x 2 (oc).
// bf16-split passes hh, lh, hl. cp.async double-buffered chunks (tap x ic64).
template<int NOC>
__global__ __launch_bounds__(256)
void k_conv_mma(const __nv_bfloat16* __restrict__ xh, const __nv_bfloat16* __restrict__ xl,
                const __nv_bfloat16* __restrict__ wh, const __nv_bfloat16* __restrict__ wl,
                float* __restrict__ out_f32,
                __nv_bfloat16* __restrict__ out_h, __nv_bfloat16* __restrict__ out_l,
                const float* __restrict__ bng, const float* __restrict__ bnb,
                const float* __restrict__ bnm, const float* __restrict__ bnv,
                int Cin, int Cout, int outTrans)
{
    extern __shared__ __align__(16) char sm[];
    const uint32_t uS = smem_u32(sm);

    const int tid  = threadIdx.x;
    const int lane = tid & 31;
    const int wid  = tid >> 5;
    const int wm   = wid >> 1;
    const int wn   = wid & 1;

    const int n   = blockIdx.x >> 5;
    const int mt  = blockIdx.x & 31;
    const int oc0 = blockIdx.y * NOC;
    const int nic = Cin >> 6;
    const int nchunks = 9 * nic;

    constexpr int J2 = NOC / 32;       // 16-oc groups per warp
    float acc[2][J2 * 2][4];
#pragma unroll
    for (int i = 0; i < 2; i++)
#pragma unroll
        for (int j = 0; j < J2 * 2; j++)
#pragma unroll
            for (int q = 0; q < 4; q++) acc[i][j][q] = 0.f;

    const int aRow = wm * 32 + (lane & 15);
    const int aOff = (lane >> 4) << 4;
    const int bRow = wn * (NOC >> 1) + (lane & 7) + ((lane >> 4) << 3);
    const int bOff = ((lane >> 3) & 1) << 4;

    // prologue
    stage_chunk(uS, tid, 0, nic, n, mt, oc0, Cin, NOC, xh, xl, wh, wl);
    CPA_COMMIT();

    for (int c = 0; c < nchunks; c++) {
        if (c + 1 < nchunks)
            stage_chunk(uS + ((c + 1) & 1) * BUFB, tid, c + 1, nic, n, mt, oc0,
                        Cin, NOC, xh, xl, wh, wl);
        CPA_COMMIT();
        CPA_WAIT1();
        __syncthreads();

        const uint32_t base = uS + (c & 1) * BUFB;
        const uint32_t uAh = base, uAl = base + MATB;
        const uint32_t uBh = base + 2 * MATB, uBl = base + 3 * MATB;

#pragma unroll
        for (int ks = 0; ks < 4; ks++) {
            const int kbyte = ks * 32;
            uint32_t ah[2][4], al[2][4], bh[J2][4], bl[J2][4];
#pragma unroll
            for (int i = 0; i < 2; i++)
                ldsm_x4(ah[i][0], ah[i][1], ah[i][2], ah[i][3],
                        uAh + (aRow + i * 16) * ROWB + kbyte + aOff);
#pragma unroll
            for (int j2 = 0; j2 < J2; j2++)
                ldsm_x4(bh[j2][0], bh[j2][1], bh[j2][2], bh[j2][3],
                        uBh + (bRow + j2 * 16) * ROWB + kbyte + bOff);
#pragma unroll
            for (int i = 0; i < 2; i++)
#pragma unroll
                for (int j2 = 0; j2 < J2; j2++) {
                    mma_bf16(acc[i][j2 * 2 + 0], ah[i], &bh[j2][0]);
                    mma_bf16(acc[i][j2 * 2 + 1], ah[i], &bh[j2][2]);
                }
#pragma unroll
            for (int i = 0; i < 2; i++)
                ldsm_x4(al[i][0], al[i][1], al[i][2], al[i][3],
                        uAl + (aRow + i * 16) * ROWB + kbyte + aOff);
#pragma unroll
            for (int i = 0; i < 2; i++)
#pragma unroll
                for (int j2 = 0; j2 < J2; j2++) {
                    mma_bf16(acc[i][j2 * 2 + 0], al[i], &bh[j2][0]);
                    mma_bf16(acc[i][j2 * 2 + 1], al[i], &bh[j2][2]);
                }
#pragma unroll
            for (int j2 = 0; j2 < J2; j2++)
                ldsm_x4(bl[j2][0], bl[j2][1], bl[j2][2], bl[j2][3],
                        uBl + (bRow + j2 * 16) * ROWB + kbyte + bOff);
#pragma unroll
            for (int i = 0; i < 2; i++)
#pragma unroll
                for (int j2 = 0; j2 < J2; j2++) {
                    mma_bf16(acc[i][j2 * 2 + 0], ah[i], &bl[j2][0]);
                    mma_bf16(acc[i][j2 * 2 + 1], ah[i], &bl[j2][2]);
                }
        }
        __syncthreads();
    }

    // epilogue
    const bool dobn = (bng != nullptr);
    const int qrow = lane >> 2;
    const int qcol = (lane & 3) << 1;
    const long long pixbase = (long long)mt * 128 + wm * 32;
    const int b = n >> 3, tt = n & 7;
#pragma unroll
    for (int i = 0; i < 2; i++) {
#pragma unroll
        for (int j = 0; j < J2 * 2; j++) {
            int oc = oc0 + wn * (NOC >> 1) + j * 8 + qcol;
            long long p0 = pixbase + i * 16 + qrow;
            float v0 = acc[i][j][0], v1 = acc[i][j][1];
            float v2 = acc[i][j][2], v3 = acc[i][j][3];
            if (dobn) {
                float sc0 = bng[oc] * rsqrtf(bnv[oc] + 1e-5f);
                float bi0 = bnb[oc] - bnm[oc] * sc0;
                float sc1 = bng[oc + 1] * rsqrtf(bnv[oc + 1] + 1e-5f);
                float bi1 = bnb[oc + 1] - bnm[oc + 1] * sc1;
                v0 = v0 * sc0 + bi0; v0 = (v0 > 0.f) ? v0 : 0.01f * v0;
                v1 = v1 * sc1 + bi1; v1 = (v1 > 0.f) ? v1 : 0.01f * v1;
                v2 = v2 * sc0 + bi0; v2 = (v2 > 0.f) ? v2 : 0.01f * v2;
                v3 = v3 * sc1 + bi1; v3 = (v3 > 0.f) ? v3 : 0.01f * v3;
            }
            if (out_f32) {
                long long o0, o1;
                if (outTrans) {
                    o0 = ((((long long)b * Cout + oc) * 8 + tt) << 12) + p0;
                    o1 = ((((long long)b * Cout + oc + 1) * 8 + tt) << 12) + p0;
                } else {
                    o0 = (((long long)n * Cout + oc) << 12) + p0;
                    o1 = (((long long)n * Cout + oc + 1) << 12) + p0;
                }
                out_f32[o0]     = v0;
                out_f32[o1]     = v1;
                out_f32[o0 + 8] = v2;
                out_f32[o1 + 8] = v3;
            }
            if (out_h) {
                __nv_bfloat16 h0 = __float2bfloat16(v0);
                __nv_bfloat16 h1 = __float2bfloat16(v1);
                __nv_bfloat16 h2 = __float2bfloat16(v2);
                __nv_bfloat16 h3 = __float2bfloat16(v3);
                __nv_bfloat162 hp0; hp0.x = h0; hp0.y = h1;
                __nv_bfloat162 hp1; hp1.x = h2; hp1.y = h3;
                __nv_bfloat162 lp0;
                lp0.x = __float2bfloat16(v0 - __bfloat162float(h0));
                lp0.y = __float2bfloat16(v1 - __bfloat162float(h1));
                __nv_bfloat162 lp1;
                lp1.x = __float2bfloat16(v2 - __bfloat162float(h2));
                lp1.y = __float2bfloat16(v3 - __bfloat162float(h3));
                long long q0 = ((long long)n * 4096 + p0) * Cout + oc;
                long long q1 = ((long long)n * 4096 + p0 + 8) * Cout + oc;
                *(__nv_bfloat162*)(out_h + q0) = hp0;
                *(__nv_bfloat162*)(out_h + q1) = hp1;
                *(__nv_bfloat162*)(out_l + q0) = lp0;
                *(__nv_bfloat162*)(out_l + q1) = lp1;
            }
        }
    }
}

// ---------------- deform -> NHWC bf16 hi/lo ----------------
// block (32,8): 64 channels x 32 pixels; smem transpose for coalesced writes.
__global__ void k_deform_nhwc(const float* __restrict__ x, const float* __restrict__ off,
                              __nv_bfloat16* __restrict__ oh, __nv_bfloat16* __restrict__ ol,
                              int C)
{
    __shared__ float sv[64][33];
    const int n    = blockIdx.z;
    const int c0   = blockIdx.y << 6;
    const int pix0 = blockIdx.x << 5;
    const int tx = threadIdx.x, ty = threadIdx.y;

    const int pix = pix0 + tx;
    const int h = pix >> 6, w = pix & 63;
#pragma unroll
    for (int q = 0; q < 8; q++) {
        int c = c0 + q * 8 + ty;
        const float* offb = off + (((long long)n * C + c) << 13);
        float oy = offb[2 * pix];
        float ox = offb[2 * pix + 1];
        float cy = fminf(fmaxf((float)h + oy, 0.f), 63.f);
        float cx = fminf(fmaxf((float)w + ox, 0.f), 63.f);
        float y0f = floorf(cy), x0f = floorf(cx);
        float tyf = cy - y0f, txf = cx - x0f;
        int y0 = (int)y0f, x0 = (int)x0f;
        int y1 = min(y0 + 1, 63), x1 = min(x0 + 1, 63);
        const float* xc = x + (((long long)n * C + c) << 12);
        float v00 = xc[(y0 << 6) + x0];
        float v01 = xc[(y0 << 6) + x1];
        float v10 = xc[(y1 << 6) + x0];
        float v11 = xc[(y1 << 6) + x1];
        sv[q * 8 + ty][tx] =
            v00 * (1.f - tyf) * (1.f - txf) + v01 * (1.f - tyf) * txf +
            v10 * tyf * (1.f - txf)         + v11 * tyf * txf;
    }
    __syncthreads();

    const int tid = ty * 32 + tx;
    const int pl  = tid >> 3;          // 0..31 pixel
    const int cb  = (tid & 7) << 3;    // 0,8,..56 channel start
    __nv_bfloat16 hv[8], lv[8];
#pragma unroll
    for (int k = 0; k < 8; k++) {
        float v = sv[cb + k][pl];
        hv[k] = __float2bfloat16(v);
        lv[k] = __float2bfloat16(v - __bfloat162float(hv[k]));
    }
    long long o = ((long long)n * 4096 + pix0 + pl) * C + c0 + cb;
    *(uint4*)(oh + o) = *(uint4*)hv;
    *(uint4*)(ol + o) = *(uint4*)lv;
}

// ---------------- launch ----------------
extern "C" void kernel_launch(void* const* d_in, const int* in_sizes, int n_in,
                              void* d_out, int out_size)
{
    const float* x      = (const float*)d_in[0];
    const float* w_off1 = (const float*)d_in[3];
    const float* w1     = (const float*)d_in[4];
    const float* g1     = (const float*)d_in[5];
    const float* b1     = (const float*)d_in[6];
    const float* m1     = (const float*)d_in[7];
    const float* v1     = (const float*)d_in[8];
    const float* w_off2 = (const float*)d_in[9];
    const float* w2     = (const float*)d_in[10];
    const float* g2     = (const float*)d_in[11];
    const float* b2     = (const float*)d_in[12];
    const float* m2     = (const float*)d_in[13];
    const float* v2     = (const float*)d_in[14];
    float* out = (float*)d_out;

    float *nd, *off1, *c1, *off2;
    __nv_bfloat16 *xh, *xl, *dh1, *dl1, *ch1, *cl1, *dh2, *dl2, *wh, *wl;
    cudaGetSymbolAddress((void**)&nd,   g_nd);
    cudaGetSymbolAddress((void**)&off1, g_off1);
    cudaGetSymbolAddress((void**)&c1,   g_c1);
    cudaGetSymbolAddress((void**)&off2, g_off2);
    cudaGetSymbolAddress((void**)&xh,   g_xh);
    cudaGetSymbolAddress((void**)&xl,   g_xl);
    cudaGetSymbolAddress((void**)&dh1,  g_dh1);
    cudaGetSymbolAddress((void**)&dl1,  g_dl1);
    cudaGetSymbolAddress((void**)&ch1,  g_ch1);
    cudaGetSymbolAddress((void**)&cl1,  g_cl1);
    cudaGetSymbolAddress((void**)&dh2,  g_dh2);
    cudaGetSymbolAddress((void**)&dl2,  g_dl2);
    cudaGetSymbolAddress((void**)&wh,   g_wh);
    cudaGetSymbolAddress((void**)&wl,   g_wl);

    cudaFuncSetAttribute(k_conv_mma<128>, cudaFuncAttributeMaxDynamicSharedMemorySize, SMEMB);
    cudaFuncSetAttribute(k_conv_mma<64>,  cudaFuncAttributeMaxDynamicSharedMemorySize, SMEMB);

    // preps
    k_transpose_in<<<131072, 256>>>(x, nd);
    k_prep_x<<<dim3(128, 8, NIMG), dim3(32, 8)>>>(x, xh, xl);
    k_prep_w<<<(1179648 + 255) / 256, 256>>>(w_off1, wh + WO_OFF1, wl + WO_OFF1, 256, 1179648);
    k_prep_w<<<(147456 + 255) / 256, 256>>>(w1,     wh + WO_C1,   wl + WO_C1,   256, 147456);
    k_prep_w<<<(73728 + 255) / 256, 256>>>(w_off2,  wh + WO_OFF2, wl + WO_OFF2, 64,  73728);
    k_prep_w<<<(36864 + 255) / 256, 256>>>(w2,      wh + WO_C2,   wl + WO_C2,   64,  36864);

    // off1: 256 -> 512
    k_conv_mma<128><<<dim3(NIMG * 32, 4), 256, SMEMB>>>(
        xh, xl, wh + WO_OFF1, wl + WO_OFF1, off1, nullptr, nullptr,
        nullptr, nullptr, nullptr, nullptr, 256, 512, 0);

    // deform1 -> NHWC bf16 (C=256)
    k_deform_nhwc<<<dim3(128, 4, NIMG), dim3(32, 8)>>>(nd, off1, dh1, dl1, 256);

    // conv1 + bn1 + lrelu: 256 -> 64 (f32 NCHW + NHWC bf16 split)
    k_conv_mma<64><<<dim3(NIMG * 32, 1), 256, SMEMB>>>(
        dh1, dl1, wh + WO_C1, wl + WO_C1, c1, ch1, cl1,
        g1, b1, m1, v1, 256, 64, 0);

    // off2: 64 -> 128
    k_conv_mma<128><<<dim3(NIMG * 32, 1), 256, SMEMB>>>(
        ch1, cl1, wh + WO_OFF2, wl + WO_OFF2, off2, nullptr, nullptr,
        nullptr, nullptr, nullptr, nullptr, 64, 128, 0);

    // deform2 -> NHWC bf16 (C=64)
    k_deform_nhwc<<<dim3(128, 1, NIMG), dim3(32, 8)>>>(c1, off2, dh2, dl2, 64);

    // conv2 + bn2 + lrelu + transpose: 64 -> 64
    k_conv_mma<64><<<dim3(NIMG * 32, 1), 256, SMEMB>>>(
        dh2, dl2, wh + WO_C2, wl + WO_C2, out, nullptr, nullptr,
        g2, b2, m2, v2, 64, 64, 1);
}

// round 8
// speedup vs baseline: 3.4142x; 1.1353x over previous
#include <cuda_runtime.h>
#include <cuda_bf16.h>
#include <cstdint>

#define HW   4096
#define NIMG 32

// ---------------- device scratch (no allocations allowed) ----------------
__device__ float g_off1[32u * 512u * 4096u];   // offsets 1 (NCHW f32)
__device__ float g_c1  [32u *  64u * 4096u];   // conv1 out (NCHW f32, deform2 src)
__device__ float g_off2[32u * 128u * 4096u];   // offsets 2 (NCHW f32)
// NHWC bf16 hi/lo operands
__device__ __nv_bfloat16 g_xh [32u * 4096u * 256u];
__device__ __nv_bfloat16 g_xl [32u * 4096u * 256u];
__device__ __nv_bfloat16 g_dh1[32u * 4096u * 256u];
__device__ __nv_bfloat16 g_dl1[32u * 4096u * 256u];
__device__ __nv_bfloat16 g_ch1[32u * 4096u * 64u];
__device__ __nv_bfloat16 g_cl1[32u * 4096u * 64u];
__device__ __nv_bfloat16 g_dh2[32u * 4096u * 64u];
__device__ __nv_bfloat16 g_dl2[32u * 4096u * 64u];
// weights, all 4 convs, [oc][tap][ic] hi/lo
#define WO_OFF1 0
#define WO_C1   1179648
#define WO_OFF2 1327104
#define WO_C2   1400832
__device__ __nv_bfloat16 g_wh[1437696];
__device__ __nv_bfloat16 g_wl[1437696];

// ---------------- helpers ----------------
__device__ __forceinline__ uint32_t smem_u32(const void* p) {
    uint32_t a;
    asm("{ .reg .u64 t; cvta.to.shared.u64 t, %1; cvt.u32.u64 %0, t; }"
        : "=r"(a) : "l"(p));
    return a;
}
__device__ __forceinline__ void ldsm_x4(uint32_t& r0, uint32_t& r1,
                                        uint32_t& r2, uint32_t& r3, uint32_t addr) {
    asm volatile("ldmatrix.sync.aligned.m8n8.x4.shared.b16 {%0,%1,%2,%3}, [%4];"
                 : "=r"(r0), "=r"(r1), "=r"(r2), "=r"(r3) : "r"(addr));
}
__device__ __forceinline__ void mma_bf16(float* c, const uint32_t* a,
                                         const uint32_t* b) {
    asm volatile(
        "mma.sync.aligned.m16n8k16.row.col.f32.bf16.bf16.f32 "
        "{%0,%1,%2,%3}, {%4,%5,%6,%7}, {%8,%9}, {%0,%1,%2,%3};"
        : "+f"(c[0]), "+f"(c[1]), "+f"(c[2]), "+f"(c[3])
        : "r"(a[0]), "r"(a[1]), "r"(a[2]), "r"(a[3]), "r"(b[0]), "r"(b[1]));
}
__device__ __forceinline__ void cpa16(uint32_t dst, const void* src, uint32_t sz) {
    asm volatile("cp.async.cg.shared.global [%0], [%1], 16, %2;"
                 :: "r"(dst), "l"(src), "r"(sz));
}
#define CPA_COMMIT() asm volatile("cp.async.commit_group;" ::: "memory")
#define CPA_WAIT1()  asm volatile("cp.async.wait_group 1;" ::: "memory")

// smem geometry (bytes)
#define ROWB   144                 // row stride (9x16B -> conflict-free ldmatrix)
#define A_ROWS 264                 // 4 image rows x 66 cols (halo block)
#define AMATB  (A_ROWS * ROWB)     // 38016 per precision
#define ABUFB  (2 * AMATB)         // 76032 (hi+lo)
#define BBUFB  36864               // max: 128 oc rows x 144B x 2 pre
#define SM_A0  0
#define SM_A1  76032
#define SM_B0  152064
#define SM_B1  188928
#define SMEMB  225792

// ---------------- prep: x -> NHWC bf16 hi/lo ----------------
__global__ void k_prep_x(const float* __restrict__ x,
                         __nv_bfloat16* __restrict__ xh, __nv_bfloat16* __restrict__ xl)
{
    __shared__ float sm[32][33];
    int n    = blockIdx.z;
    int c0   = blockIdx.y << 5;
    int pix0 = blockIdx.x << 5;
    int tx = threadIdx.x, ty = threadIdx.y;
    int b = n >> 3, t = n & 7;
#pragma unroll
    for (int q = 0; q < 4; q++) {
        int c = c0 + ty + q * 8;
        sm[ty + q * 8][tx] = x[((((long long)b * 256 + c) * 8 + t) << 12) + pix0 + tx];
    }
    __syncthreads();
#pragma unroll
    for (int q = 0; q < 4; q++) {
        int pix = pix0 + ty + q * 8;
        float v = sm[tx][ty + q * 8];
        __nv_bfloat16 hi = __float2bfloat16(v);
        __nv_bfloat16 lo = __float2bfloat16(v - __bfloat162float(hi));
        long long o = ((long long)n * 4096 + pix) * 256 + c0 + tx;
        xh[o] = hi;
        xl[o] = lo;
    }
}

// ---------------- prep: w (oc,ic,3,3) -> [oc][tap][ic] bf16 hi/lo ------------
__global__ void k_prep_w(const float* __restrict__ w,
                         __nv_bfloat16* __restrict__ wh, __nv_bfloat16* __restrict__ wl,
                         int Cin, int total)
{
    int i = blockIdx.x * 256 + threadIdx.x;
    if (i >= total) return;
    int oc  = i / (Cin * 9);
    int r   = i - oc * (Cin * 9);
    int tap = r / Cin;
    int ic  = r - tap * Cin;
    float v = w[(long long)(oc * Cin + ic) * 9 + tap];
    __nv_bfloat16 hi = __float2bfloat16(v);
    __nv_bfloat16 lo = __float2bfloat16(v - __bfloat162float(hi));
    wh[i] = hi;
    wl[i] = lo;
}

// ---------------- staging ----------------
// A halo block: 264 rows (4 image rows x 66 cols), 64 ic (128B) per row, hi+lo.
__device__ __forceinline__ void stage_A(
    uint32_t abase, int tid, int ic0, int n, int y0, int Cin,
    const __nv_bfloat16* __restrict__ xh, const __nv_bfloat16* __restrict__ xl)
{
    for (int i = tid; i < 2 * A_ROWS * 8; i += 256) {
        int pre = i >= A_ROWS * 8;
        int f   = pre ? i - A_ROWS * 8 : i;
        int row = f >> 3, u = f & 7;
        int rel_y = row / 66, rel_x = row - rel_y * 66;
        int ys = y0 - 1 + rel_y, xs = rel_x - 1;
        bool ok = ((unsigned)ys < 64u) && ((unsigned)xs < 64u);
        const __nv_bfloat16* base = pre ? xl : xh;
        const __nv_bfloat16* src = ok ?
            base + (((long long)n * 4096 + ys * 64 + xs) * Cin + ic0 + (u << 3)) : base;
        cpa16(abase + pre * AMATB + row * ROWB + (u << 4), src, ok ? 16u : 0u);
    }
}

template<int NOC>
__device__ __forceinline__ void stage_B(
    uint32_t bbase, int tid, int tap, int ic0, int oc0, int Cin,
    const __nv_bfloat16* __restrict__ wh, const __nv_bfloat16* __restrict__ wl)
{
    for (int i = tid; i < NOC * 16; i += 256) {
        int pre = i >= NOC * 8;
        int f   = pre ? i - NOC * 8 : i;
        int r = f >> 3, u = f & 7;
        const __nv_bfloat16* src = (pre ? wl : wh) +
            ((long long)(oc0 + r) * 9 + tap) * Cin + ic0 + (u << 3);
        cpa16(bbase + pre * (NOC * ROWB) + r * ROWB + (u << 4), src, 16u);
    }
}

// ---------------- mma implicit-GEMM conv: D[128 px][NOC oc] ------------------
// A staged ONCE per ic64-chunk (halo block, double-buffered); per tap the
// fragment addresses shift by (dy*66+dx) rows. B double-buffered per chunk.
template<int NOC>
__global__ __launch_bounds__(256)
void k_conv_mma(const __nv_bfloat16* __restrict__ xh, const __nv_bfloat16* __restrict__ xl,
                const __nv_bfloat16* __restrict__ wh, const __nv_bfloat16* __restrict__ wl,
                float* __restrict__ out_f32,
                __nv_bfloat16* __restrict__ out_h, __nv_bfloat16* __restrict__ out_l,
                const float* __restrict__ bng, const float* __restrict__ bnb,
                const float* __restrict__ bnm, const float* __restrict__ bnv,
                int Cin, int Cout, int outTrans)
{
    extern __shared__ __align__(16) char smc[];
    const uint32_t uS = smem_u32(smc);

    const int tid  = threadIdx.x;
    const int lane = tid & 31;
    const int wid  = tid >> 5;
    const int wm   = wid >> 1;
    const int wn   = wid & 1;

    const int n   = blockIdx.x >> 5;
    const int mt  = blockIdx.x & 31;
    const int y0  = mt << 1;
    const int oc0 = blockIdx.y * NOC;
    const int nic = Cin >> 6;
    const int nchunks = 9 * nic;

    constexpr int J2 = NOC / 32;
    float acc[2][J2 * 2][4];
#pragma unroll
    for (int i = 0; i < 2; i++)
#pragma unroll
        for (int j = 0; j < J2 * 2; j++)
#pragma unroll
            for (int q = 0; q < 4; q++) acc[i][j][q] = 0.f;

    // per-lane fragment bases
    const int aOff = (lane >> 4) << 4;
    int rowoff[2];
#pragma unroll
    for (int i = 0; i < 2; i++) {
        int m = wm * 32 + (lane & 15) + i * 16;       // pixel row 0..127
        rowoff[i] = (((m >> 6) + 1) * 66 + (m & 63) + 1) * ROWB;
    }
    const int bRow = wn * (NOC >> 1) + (lane & 7) + ((lane >> 4) << 3);
    const int bOff = ((lane >> 3) & 1) << 4;

    const uint32_t uA[2] = {uS + SM_A0, uS + SM_A1};
    const uint32_t uB[2] = {uS + SM_B0, uS + SM_B1};

    // prologue: A chunk 0 + B chunk 0
    stage_A(uA[0], tid, 0, n, y0, Cin, xh, xl);
    stage_B<NOC>(uB[0], tid, 0, 0, oc0, Cin, wh, wl);
    CPA_COMMIT();

    for (int c = 0; c < nchunks; c++) {
        const int nx = c + 1;
        if (nx < nchunks) {
            const int nicc = nx / 9;
            const int ntap = nx - nicc * 9;
            if (ntap == 0)
                stage_A(uA[nicc & 1], tid, nicc << 6, n, y0, Cin, xh, xl);
            stage_B<NOC>(uB[nx & 1], tid, ntap, nicc << 6, oc0, Cin, wh, wl);
        }
        CPA_COMMIT();
        CPA_WAIT1();
        __syncthreads();

        const int icc = c / 9;
        const int tap = c - icc * 9;
        const int d144 = ((tap / 3) * 66 + (tap - (tap / 3) * 3)) * ROWB - 67 * ROWB;
        const uint32_t aH = uA[icc & 1] + d144;
        const uint32_t aL = aH + AMATB;
        const uint32_t bH = uB[c & 1];
        const uint32_t bL = bH + NOC * ROWB;

#pragma unroll
        for (int ks = 0; ks < 4; ks++) {
            const int kbyte = ks * 32;
            uint32_t ah[2][4], al[2][4], bh[J2][4], bl[J2][4];
#pragma unroll
            for (int i = 0; i < 2; i++)
                ldsm_x4(ah[i][0], ah[i][1], ah[i][2], ah[i][3],
                        aH + rowoff[i] + kbyte + aOff);
#pragma unroll
            for (int j2 = 0; j2 < J2; j2++)
                ldsm_x4(bh[j2][0], bh[j2][1], bh[j2][2], bh[j2][3],
                        bH + (bRow + j2 * 16) * ROWB + kbyte + bOff);
#pragma unroll
            for (int i = 0; i < 2; i++)
#pragma unroll
                for (int j2 = 0; j2 < J2; j2++) {
                    mma_bf16(acc[i][j2 * 2 + 0], ah[i], &bh[j2][0]);
                    mma_bf16(acc[i][j2 * 2 + 1], ah[i], &bh[j2][2]);
                }
#pragma unroll
            for (int i = 0; i < 2; i++)
                ldsm_x4(al[i][0], al[i][1], al[i][2], al[i][3],
                        aL + rowoff[i] + kbyte + aOff);
#pragma unroll
            for (int i = 0; i < 2; i++)
#pragma unroll
                for (int j2 = 0; j2 < J2; j2++) {
                    mma_bf16(acc[i][j2 * 2 + 0], al[i], &bh[j2][0]);
                    mma_bf16(acc[i][j2 * 2 + 1], al[i], &bh[j2][2]);
                }
#pragma unroll
            for (int j2 = 0; j2 < J2; j2++)
                ldsm_x4(bl[j2][0], bl[j2][1], bl[j2][2], bl[j2][3],
                        bL + (bRow + j2 * 16) * ROWB + kbyte + bOff);
#pragma unroll
            for (int i = 0; i < 2; i++)
#pragma unroll
                for (int j2 = 0; j2 < J2; j2++) {
                    mma_bf16(acc[i][j2 * 2 + 0], ah[i], &bl[j2][0]);
                    mma_bf16(acc[i][j2 * 2 + 1], ah[i], &bl[j2][2]);
                }
        }
        __syncthreads();
    }

    // epilogue
    const bool dobn = (bng != nullptr);
    const int qrow = lane >> 2;
    const int qcol = (lane & 3) << 1;
    const long long pixbase = (long long)mt * 128 + wm * 32;
    const int b = n >> 3, tt = n & 7;
#pragma unroll
    for (int i = 0; i < 2; i++) {
#pragma unroll
        for (int j = 0; j < J2 * 2; j++) {
            int oc = oc0 + wn * (NOC >> 1) + j * 8 + qcol;
            long long p0 = pixbase + i * 16 + qrow;
            float v0 = acc[i][j][0], v1 = acc[i][j][1];
            float v2 = acc[i][j][2], v3 = acc[i][j][3];
            if (dobn) {
                float sc0 = bng[oc] * rsqrtf(bnv[oc] + 1e-5f);
                float bi0 = bnb[oc] - bnm[oc] * sc0;
                float sc1 = bng[oc + 1] * rsqrtf(bnv[oc + 1] + 1e-5f);
                float bi1 = bnb[oc + 1] - bnm[oc + 1] * sc1;
                v0 = v0 * sc0 + bi0; v0 = (v0 > 0.f) ? v0 : 0.01f * v0;
                v1 = v1 * sc1 + bi1; v1 = (v1 > 0.f) ? v1 : 0.01f * v1;
                v2 = v2 * sc0 + bi0; v2 = (v2 > 0.f) ? v2 : 0.01f * v2;
                v3 = v3 * sc1 + bi1; v3 = (v3 > 0.f) ? v3 : 0.01f * v3;
            }
            if (out_f32) {
                long long o0, o1;
                if (outTrans) {
                    o0 = ((((long long)b * Cout + oc) * 8 + tt) << 12) + p0;
                    o1 = ((((long long)b * Cout + oc + 1) * 8 + tt) << 12) + p0;
                } else {
                    o0 = (((long long)n * Cout + oc) << 12) + p0;
                    o1 = (((long long)n * Cout + oc + 1) << 12) + p0;
                }
                out_f32[o0]     = v0;
                out_f32[o1]     = v1;
                out_f32[o0 + 8] = v2;
                out_f32[o1 + 8] = v3;
            }
            if (out_h) {
                __nv_bfloat16 h0 = __float2bfloat16(v0);
                __nv_bfloat16 h1 = __float2bfloat16(v1);
                __nv_bfloat16 h2 = __float2bfloat16(v2);
                __nv_bfloat16 h3 = __float2bfloat16(v3);
                __nv_bfloat162 hp0; hp0.x = h0; hp0.y = h1;
                __nv_bfloat162 hp1; hp1.x = h2; hp1.y = h3;
                __nv_bfloat162 lp0;
                lp0.x = __float2bfloat16(v0 - __bfloat162float(h0));
                lp0.y = __float2bfloat16(v1 - __bfloat162float(h1));
                __nv_bfloat162 lp1;
                lp1.x = __float2bfloat16(v2 - __bfloat162float(h2));
                lp1.y = __float2bfloat16(v3 - __bfloat162float(h3));
                long long q0 = ((long long)n * 4096 + p0) * Cout + oc;
                long long q1 = ((long long)n * 4096 + p0 + 8) * Cout + oc;
                *(__nv_bfloat162*)(out_h + q0) = hp0;
                *(__nv_bfloat162*)(out_h + q1) = hp1;
                *(__nv_bfloat162*)(out_l + q0) = lp0;
                *(__nv_bfloat162*)(out_l + q1) = lp1;
            }
        }
    }
}

// ---------------- deform -> NHWC bf16 hi/lo ----------------
// isX=1: source is original x (Bs,C,T,H,W); isX=0: source is NCHW f32.
__global__ void k_deform_nhwc(const float* __restrict__ src, const float* __restrict__ off,
                              __nv_bfloat16* __restrict__ oh, __nv_bfloat16* __restrict__ ol,
                              int C, int isX)
{
    __shared__ float sv[64][33];
    const int n    = blockIdx.z;
    const int c0   = blockIdx.y << 6;
    const int pix0 = blockIdx.x << 5;
    const int tx = threadIdx.x, ty = threadIdx.y;

    const int pix = pix0 + tx;
    const int h = pix >> 6, w = pix & 63;
#pragma unroll
    for (int q = 0; q < 8; q++) {
        int c = c0 + q * 8 + ty;
        const float* offb = off + (((long long)n * C + c) << 13);
        float oy = offb[2 * pix];
        float ox = offb[2 * pix + 1];
        float cy = fminf(fmaxf((float)h + oy, 0.f), 63.f);
        float cx = fminf(fmaxf((float)w + ox, 0.f), 63.f);
        float y0f = floorf(cy), x0f = floorf(cx);
        float tyf = cy - y0f, txf = cx - x0f;
        int y0 = (int)y0f, x0 = (int)x0f;
        int y1 = min(y0 + 1, 63), x1 = min(x0 + 1, 63);
        const float* xc;
        if (isX) {
            int b = n >> 3, t = n & 7;
            xc = src + ((((long long)b * 256 + c) * 8 + t) << 12);
        } else {
            xc = src + (((long long)n * C + c) << 12);
        }
        float v00 = xc[(y0 << 6) + x0];
        float v01 = xc[(y0 << 6) + x1];
        float v10 = xc[(y1 << 6) + x0];
        float v11 = xc[(y1 << 6) + x1];
        sv[q * 8 + ty][tx] =
            v00 * (1.f - tyf) * (1.f - txf) + v01 * (1.f - tyf) * txf +
            v10 * tyf * (1.f - txf)         + v11 * tyf * txf;
    }
    __syncthreads();

    const int tid = ty * 32 + tx;
    const int pl  = tid >> 3;
    const int cb  = (tid & 7) << 3;
    __nv_bfloat16 hv[8], lv[8];
#pragma unroll
    for (int k = 0; k < 8; k++) {
        float v = sv[cb + k][pl];
        hv[k] = __float2bfloat16(v);
        lv[k] = __float2bfloat16(v - __bfloat162float(hv[k]));
    }
    long long o = ((long long)n * 4096 + pix0 + pl) * C + c0 + cb;
    *(uint4*)(oh + o) = *(uint4*)hv;
    *(uint4*)(ol + o) = *(uint4*)lv;
}

// ---------------- launch ----------------
extern "C" void kernel_launch(void* const* d_in, const int* in_sizes, int n_in,
                              void* d_out, int out_size)
{
    const float* x      = (const float*)d_in[0];
    const float* w_off1 = (const float*)d_in[3];
    const float* w1     = (const float*)d_in[4];
    const float* g1     = (const float*)d_in[5];
    const float* b1     = (const float*)d_in[6];
    const float* m1     = (const float*)d_in[7];
    const float* v1     = (const float*)d_in[8];
    const float* w_off2 = (const float*)d_in[9];
    const float* w2     = (const float*)d_in[10];
    const float* g2     = (const float*)d_in[11];
    const float* b2     = (const float*)d_in[12];
    const float* m2     = (const float*)d_in[13];
    const float* v2     = (const float*)d_in[14];
    float* out = (float*)d_out;

    float *off1, *c1, *off2;
    __nv_bfloat16 *xh, *xl, *dh1, *dl1, *ch1, *cl1, *dh2, *dl2, *wh, *wl;
    cudaGetSymbolAddress((void**)&off1, g_off1);
    cudaGetSymbolAddress((void**)&c1,   g_c1);
    cudaGetSymbolAddress((void**)&off2, g_off2);
    cudaGetSymbolAddress((void**)&xh,   g_xh);
    cudaGetSymbolAddress((void**)&xl,   g_xl);
    cudaGetSymbolAddress((void**)&dh1,  g_dh1);
    cudaGetSymbolAddress((void**)&dl1,  g_dl1);
    cudaGetSymbolAddress((void**)&ch1,  g_ch1);
    cudaGetSymbolAddress((void**)&cl1,  g_cl1);
    cudaGetSymbolAddress((void**)&dh2,  g_dh2);
    cudaGetSymbolAddress((void**)&dl2,  g_dl2);
    cudaGetSymbolAddress((void**)&wh,   g_wh);
    cudaGetSymbolAddress((void**)&wl,   g_wl);

    cudaFuncSetAttribute(k_conv_mma<128>, cudaFuncAttributeMaxDynamicSharedMemorySize, SMEMB);
    cudaFuncSetAttribute(k_conv_mma<64>,  cudaFuncAttributeMaxDynamicSharedMemorySize, SMEMB);

    // preps
    k_prep_x<<<dim3(128, 8, NIMG), dim3(32, 8)>>>(x, xh, xl);
    k_prep_w<<<(1179648 + 255) / 256, 256>>>(w_off1, wh + WO_OFF1, wl + WO_OFF1, 256, 1179648);
    k_prep_w<<<(147456 + 255) / 256, 256>>>(w1,     wh + WO_C1,   wl + WO_C1,   256, 147456);
    k_prep_w<<<(73728 + 255) / 256, 256>>>(w_off2,  wh + WO_OFF2, wl + WO_OFF2, 64,  73728);
    k_prep_w<<<(36864 + 255) / 256, 256>>>(w2,      wh + WO_C2,   wl + WO_C2,   64,  36864);

    // off1: 256 -> 512
    k_conv_mma<128><<<dim3(NIMG * 32, 4), 256, SMEMB>>>(
        xh, xl, wh + WO_OFF1, wl + WO_OFF1, off1, nullptr, nullptr,
        nullptr, nullptr, nullptr, nullptr, 256, 512, 0);

    // deform1 (reads original x directly) -> NHWC bf16 (C=256)
    k_deform_nhwc<<<dim3(128, 4, NIMG), dim3(32, 8)>>>(x, off1, dh1, dl1, 256, 1);

    // conv1 + bn1 + lrelu: 256 -> 64 (f32 NCHW + NHWC bf16 split)
    k_conv_mma<64><<<dim3(NIMG * 32, 1), 256, SMEMB>>>(
        dh1, dl1, wh + WO_C1, wl + WO_C1, c1, ch1, cl1,
        g1, b1, m1, v1, 256, 64, 0);

    // off2: 64 -> 128
    k_conv_mma<128><<<dim3(NIMG * 32, 1), 256, SMEMB>>>(
        ch1, cl1, wh + WO_OFF2, wl + WO_OFF2, off2, nullptr, nullptr,
        nullptr, nullptr, nullptr, nullptr, 64, 128, 0);

    // deform2 -> NHWC bf16 (C=64)
    k_deform_nhwc<<<dim3(128, 1, NIMG), dim3(32, 8)>>>(c1, off2, dh2, dl2, 64, 0);

    // conv2 + bn2 + lrelu + transpose: 64 -> 64
    k_conv_mma<64><<<dim3(NIMG * 32, 1), 256, SMEMB>>>(
        dh2, dl2, wh + WO_C2, wl + WO_C2, out, nullptr, nullptr,
        g2, b2, m2, v2, 64, 64, 1);
}

// round 9
// speedup vs baseline: 3.7101x; 1.0867x over previous
#include <cuda_runtime.h>
#include <cuda_bf16.h>
#include <cstdint>

#define HW   4096
#define NIMG 32

// ---------------- device scratch (no allocations allowed) ----------------
__device__ float g_off1[32u * 512u * 4096u];   // offsets 1 (NCHW f32)
__device__ float g_c1  [32u *  64u * 4096u];   // conv1 out (NCHW f32, deform2 src)
__device__ float g_off2[32u * 128u * 4096u];   // offsets 2 (NCHW f32)
// NHWC bf16 hi/lo operands
__device__ __nv_bfloat16 g_xh [32u * 4096u * 256u];
__device__ __nv_bfloat16 g_xl [32u * 4096u * 256u];
__device__ __nv_bfloat16 g_dh1[32u * 4096u * 256u];
__device__ __nv_bfloat16 g_dl1[32u * 4096u * 256u];
__device__ __nv_bfloat16 g_ch1[32u * 4096u * 64u];
__device__ __nv_bfloat16 g_cl1[32u * 4096u * 64u];
__device__ __nv_bfloat16 g_dh2[32u * 4096u * 64u];
__device__ __nv_bfloat16 g_dl2[32u * 4096u * 64u];
// weights, all 4 convs, [oc][tap][ic] hi/lo
#define WO_OFF1 0
#define WO_C1   1179648
#define WO_OFF2 1327104
#define WO_C2   1400832
__device__ __nv_bfloat16 g_wh[1437696];
__device__ __nv_bfloat16 g_wl[1437696];

// ---------------- helpers ----------------
__device__ __forceinline__ uint32_t smem_u32(const void* p) {
    uint32_t a;
    asm("{ .reg .u64 t; cvta.to.shared.u64 t, %1; cvt.u32.u64 %0, t; }"
        : "=r"(a) : "l"(p));
    return a;
}
__device__ __forceinline__ void ldsm_x4(uint32_t& r0, uint32_t& r1,
                                        uint32_t& r2, uint32_t& r3, uint32_t addr) {
    asm volatile("ldmatrix.sync.aligned.m8n8.x4.shared.b16 {%0,%1,%2,%3}, [%4];"
                 : "=r"(r0), "=r"(r1), "=r"(r2), "=r"(r3) : "r"(addr));
}
__device__ __forceinline__ void mma_bf16(float* c, const uint32_t* a,
                                         const uint32_t* b) {
    asm volatile(
        "mma.sync.aligned.m16n8k16.row.col.f32.bf16.bf16.f32 "
        "{%0,%1,%2,%3}, {%4,%5,%6,%7}, {%8,%9}, {%0,%1,%2,%3};"
        : "+f"(c[0]), "+f"(c[1]), "+f"(c[2]), "+f"(c[3])
        : "r"(a[0]), "r"(a[1]), "r"(a[2]), "r"(a[3]), "r"(b[0]), "r"(b[1]));
}
__device__ __forceinline__ void cpa16(uint32_t dst, const void* src, uint32_t sz) {
    asm volatile("cp.async.cg.shared.global [%0], [%1], 16, %2;"
                 :: "r"(dst), "l"(src), "r"(sz));
}
#define CPA_COMMIT() asm volatile("cp.async.commit_group;" ::: "memory")
#define CPA_WAIT1()  asm volatile("cp.async.wait_group 1;" ::: "memory")
#define CPA_WAIT0()  asm volatile("cp.async.wait_group 0;" ::: "memory")

// smem geometry (bytes)
#define ROWB   144                 // row stride (9x16B -> conflict-free ldmatrix)
#define A_ROWS 396                 // 6 image rows x 66 cols (halo for 4-row tile)
#define AMATB  (A_ROWS * ROWB)     // 57024 per precision
#define ABUFB  (2 * AMATB)         // 114048 (hi+lo), SINGLE buffered
#define SMEMB  (ABUFB + 2 * 128 * ROWB * 2)   // + 2x B double buffers = 187776

// ---------------- prep: x -> NHWC bf16 hi/lo ----------------
__global__ void k_prep_x(const float* __restrict__ x,
                         __nv_bfloat16* __restrict__ xh, __nv_bfloat16* __restrict__ xl)
{
    __shared__ float sm[32][33];
    int n    = blockIdx.z;
    int c0   = blockIdx.y << 5;
    int pix0 = blockIdx.x << 5;
    int tx = threadIdx.x, ty = threadIdx.y;
    int b = n >> 3, t = n & 7;
#pragma unroll
    for (int q = 0; q < 4; q++) {
        int c = c0 + ty + q * 8;
        sm[ty + q * 8][tx] = x[((((long long)b * 256 + c) * 8 + t) << 12) + pix0 + tx];
    }
    __syncthreads();
#pragma unroll
    for (int q = 0; q < 4; q++) {
        int pix = pix0 + ty + q * 8;
        float v = sm[tx][ty + q * 8];
        __nv_bfloat16 hi = __float2bfloat16(v);
        __nv_bfloat16 lo = __float2bfloat16(v - __bfloat162float(hi));
        long long o = ((long long)n * 4096 + pix) * 256 + c0 + tx;
        xh[o] = hi;
        xl[o] = lo;
    }
}

// ---------------- prep: w (oc,ic,3,3) -> [oc][tap][ic] bf16 hi/lo ------------
__global__ void k_prep_w(const float* __restrict__ w,
                         __nv_bfloat16* __restrict__ wh, __nv_bfloat16* __restrict__ wl,
                         int Cin, int total)
{
    int i = blockIdx.x * 256 + threadIdx.x;
    if (i >= total) return;
    int oc  = i / (Cin * 9);
    int r   = i - oc * (Cin * 9);
    int tap = r / Cin;
    int ic  = r - tap * Cin;
    float v = w[(long long)(oc * Cin + ic) * 9 + tap];
    __nv_bfloat16 hi = __float2bfloat16(v);
    __nv_bfloat16 lo = __float2bfloat16(v - __bfloat162float(hi));
    wh[i] = hi;
    wl[i] = lo;
}

// ---------------- staging ----------------
// A halo block: 396 rows (6 image rows x 66 cols), 64 ic (128B) per row, hi+lo.
__device__ __forceinline__ void stage_A(
    uint32_t abase, int tid, int ic0, int n, int y0, int Cin,
    const __nv_bfloat16* __restrict__ xh, const __nv_bfloat16* __restrict__ xl)
{
    for (int i = tid; i < 2 * A_ROWS * 8; i += 256) {
        int pre = i >= A_ROWS * 8;
        int f   = pre ? i - A_ROWS * 8 : i;
        int row = f >> 3, u = f & 7;
        int rel_y = row / 66, rel_x = row - rel_y * 66;
        int ys = y0 - 1 + rel_y, xs = rel_x - 1;
        bool ok = ((unsigned)ys < 64u) && ((unsigned)xs < 64u);
        const __nv_bfloat16* base = pre ? xl : xh;
        const __nv_bfloat16* src = ok ?
            base + (((long long)n * 4096 + ys * 64 + xs) * Cin + ic0 + (u << 3)) : base;
        cpa16(abase + pre * AMATB + row * ROWB + (u << 4), src, ok ? 16u : 0u);
    }
}

template<int NOC>
__device__ __forceinline__ void stage_B(
    uint32_t bbase, int tid, int tap, int ic0, int oc0, int Cin,
    const __nv_bfloat16* __restrict__ wh, const __nv_bfloat16* __restrict__ wl)
{
    for (int i = tid; i < NOC * 16; i += 256) {
        int pre = i >= NOC * 8;
        int f   = pre ? i - NOC * 8 : i;
        int r = f >> 3, u = f & 7;
        const __nv_bfloat16* src = (pre ? wl : wh) +
            ((long long)(oc0 + r) * 9 + tap) * Cin + ic0 + (u << 3);
        cpa16(bbase + pre * (NOC * ROWB) + r * ROWB + (u << 4), src, 16u);
    }
}

// ---------------- mma implicit-GEMM conv: D[256 px][NOC oc] ------------------
// M=256 (4 image rows). A halo single-buffered, staged per ic64-chunk;
// per tap fragments shift by (dy*66+dx) rows. B double-buffered per chunk.
// 8 warps = 4(M) x 2(N); warp tile 64 px x NOC/2 oc.
template<int NOC>
__global__ __launch_bounds__(256)
void k_conv_mma(const __nv_bfloat16* __restrict__ xh, const __nv_bfloat16* __restrict__ xl,
                const __nv_bfloat16* __restrict__ wh, const __nv_bfloat16* __restrict__ wl,
                float* __restrict__ out_f32,
                __nv_bfloat16* __restrict__ out_h, __nv_bfloat16* __restrict__ out_l,
                const float* __restrict__ bng, const float* __restrict__ bnb,
                const float* __restrict__ bnm, const float* __restrict__ bnv,
                int Cin, int Cout, int outTrans)
{
    extern __shared__ __align__(16) char smc[];
    const uint32_t uS = smem_u32(smc);

    const int tid  = threadIdx.x;
    const int lane = tid & 31;
    const int wid  = tid >> 5;
    const int wm   = wid >> 1;          // 0..3: 64-px slab
    const int wn   = wid & 1;

    const int n   = blockIdx.x >> 4;
    const int mt  = blockIdx.x & 15;
    const int y0  = mt << 2;            // 4 image rows per tile
    const int oc0 = blockIdx.y * NOC;
    const int nic = Cin >> 6;
    const int nchunks = 9 * nic;

    constexpr int J2 = NOC / 32;
    float acc[4][J2 * 2][4];
#pragma unroll
    for (int i = 0; i < 4; i++)
#pragma unroll
        for (int j = 0; j < J2 * 2; j++)
#pragma unroll
            for (int q = 0; q < 4; q++) acc[i][j][q] = 0.f;

    // per-lane fragment bases: 4 m16 tiles per warp
    const int aOff = (lane >> 4) << 4;
    int rowoff[4];
#pragma unroll
    for (int i = 0; i < 4; i++) {
        int m = wm * 64 + (lane & 15) + i * 16;       // pixel row 0..255
        rowoff[i] = (((m >> 6) + 1) * 66 + (m & 63) + 1) * ROWB;
    }
    const int bRow = wn * (NOC >> 1) + (lane & 7) + ((lane >> 4) << 3);
    const int bOff = ((lane >> 3) & 1) << 4;

    const uint32_t uA = uS;
    const uint32_t uB[2] = {uS + ABUFB, uS + ABUFB + NOC * ROWB * 2};

    // prologue: A chunk 0 + B chunk 0
    stage_A(uA, tid, 0, n, y0, Cin, xh, xl);
    stage_B<NOC>(uB[0], tid, 0, 0, oc0, Cin, wh, wl);
    CPA_COMMIT();

    for (int c = 0; c < nchunks; c++) {
        const int icc = c / 9;
        const int tap = c - icc * 9;
        const bool newA = (tap == 0) && (c > 0);
        if (newA)   // previous iteration's trailing sync protects the A buffer
            stage_A(uA, tid, icc << 6, n, y0, Cin, xh, xl);
        const int nx = c + 1;
        if (nx < nchunks) {
            const int nicc = nx / 9;
            const int ntap = nx - nicc * 9;
            stage_B<NOC>(uB[nx & 1], tid, ntap, nicc << 6, oc0, Cin, wh, wl);
        }
        CPA_COMMIT();
        if (newA) { CPA_WAIT0(); } else { CPA_WAIT1(); }
        __syncthreads();

        const int d144 = ((tap / 3) * 66 + (tap - (tap / 3) * 3) - 67) * ROWB;
        const uint32_t aH = uA + d144;
        const uint32_t aL = aH + AMATB;
        const uint32_t bH = uB[c & 1];
        const uint32_t bL = bH + NOC * ROWB;

#pragma unroll
        for (int ks = 0; ks < 4; ks++) {
            const int kbyte = ks * 32;
            uint32_t ah[4][4], al[4][4], bh[J2][4], bl[J2][4];
#pragma unroll
            for (int i = 0; i < 4; i++)
                ldsm_x4(ah[i][0], ah[i][1], ah[i][2], ah[i][3],
                        aH + rowoff[i] + kbyte + aOff);
#pragma unroll
            for (int j2 = 0; j2 < J2; j2++)
                ldsm_x4(bh[j2][0], bh[j2][1], bh[j2][2], bh[j2][3],
                        bH + (bRow + j2 * 16) * ROWB + kbyte + bOff);
#pragma unroll
            for (int i = 0; i < 4; i++)
#pragma unroll
                for (int j2 = 0; j2 < J2; j2++) {
                    mma_bf16(acc[i][j2 * 2 + 0], ah[i], &bh[j2][0]);
                    mma_bf16(acc[i][j2 * 2 + 1], ah[i], &bh[j2][2]);
                }
#pragma unroll
            for (int i = 0; i < 4; i++)
                ldsm_x4(al[i][0], al[i][1], al[i][2], al[i][3],
                        aL + rowoff[i] + kbyte + aOff);
#pragma unroll
            for (int i = 0; i < 4; i++)
#pragma unroll
                for (int j2 = 0; j2 < J2; j2++) {
                    mma_bf16(acc[i][j2 * 2 + 0], al[i], &bh[j2][0]);
                    mma_bf16(acc[i][j2 * 2 + 1], al[i], &bh[j2][2]);
                }
#pragma unroll
            for (int j2 = 0; j2 < J2; j2++)
                ldsm_x4(bl[j2][0], bl[j2][1], bl[j2][2], bl[j2][3],
                        bL + (bRow + j2 * 16) * ROWB + kbyte + bOff);
#pragma unroll
            for (int i = 0; i < 4; i++)
#pragma unroll
                for (int j2 = 0; j2 < J2; j2++) {
                    mma_bf16(acc[i][j2 * 2 + 0], ah[i], &bl[j2][0]);
                    mma_bf16(acc[i][j2 * 2 + 1], ah[i], &bl[j2][2]);
                }
        }
        __syncthreads();
    }

    // epilogue
    const bool dobn = (bng != nullptr);
    const int qrow = lane >> 2;
    const int qcol = (lane & 3) << 1;
    const long long pixbase = (long long)mt * 256 + wm * 64;
    const int b = n >> 3, tt = n & 7;
#pragma unroll
    for (int i = 0; i < 4; i++) {
#pragma unroll
        for (int j = 0; j < J2 * 2; j++) {
            int oc = oc0 + wn * (NOC >> 1) + j * 8 + qcol;
            long long p0 = pixbase + i * 16 + qrow;
            float v0 = acc[i][j][0], v1 = acc[i][j][1];
            float v2 = acc[i][j][2], v3 = acc[i][j][3];
            if (dobn) {
                float sc0 = bng[oc] * rsqrtf(bnv[oc] + 1e-5f);
                float bi0 = bnb[oc] - bnm[oc] * sc0;
                float sc1 = bng[oc + 1] * rsqrtf(bnv[oc + 1] + 1e-5f);
                float bi1 = bnb[oc + 1] - bnm[oc + 1] * sc1;
                v0 = v0 * sc0 + bi0; v0 = (v0 > 0.f) ? v0 : 0.01f * v0;
                v1 = v1 * sc1 + bi1; v1 = (v1 > 0.f) ? v1 : 0.01f * v1;
                v2 = v2 * sc0 + bi0; v2 = (v2 > 0.f) ? v2 : 0.01f * v2;
                v3 = v3 * sc1 + bi1; v3 = (v3 > 0.f) ? v3 : 0.01f * v3;
            }
            if (out_f32) {
                long long o0, o1;
                if (outTrans) {
                    o0 = ((((long long)b * Cout + oc) * 8 + tt) << 12) + p0;
                    o1 = ((((long long)b * Cout + oc + 1) * 8 + tt) << 12) + p0;
                } else {
                    o0 = (((long long)n * Cout + oc) << 12) + p0;
                    o1 = (((long long)n * Cout + oc + 1) << 12) + p0;
                }
                out_f32[o0]     = v0;
                out_f32[o1]     = v1;
                out_f32[o0 + 8] = v2;
                out_f32[o1 + 8] = v3;
            }
            if (out_h) {
                __nv_bfloat16 h0 = __float2bfloat16(v0);
                __nv_bfloat16 h1 = __float2bfloat16(v1);
                __nv_bfloat16 h2 = __float2bfloat16(v2);
                __nv_bfloat16 h3 = __float2bfloat16(v3);
                __nv_bfloat162 hp0; hp0.x = h0; hp0.y = h1;
                __nv_bfloat162 hp1; hp1.x = h2; hp1.y = h3;
                __nv_bfloat162 lp0;
                lp0.x = __float2bfloat16(v0 - __bfloat162float(h0));
                lp0.y = __float2bfloat16(v1 - __bfloat162float(h1));
                __nv_bfloat162 lp1;
                lp1.x = __float2bfloat16(v2 - __bfloat162float(h2));
                lp1.y = __float2bfloat16(v3 - __bfloat162float(h3));
                long long q0 = ((long long)n * 4096 + p0) * Cout + oc;
                long long q1 = ((long long)n * 4096 + p0 + 8) * Cout + oc;
                *(__nv_bfloat162*)(out_h + q0) = hp0;
                *(__nv_bfloat162*)(out_h + q1) = hp1;
                *(__nv_bfloat162*)(out_l + q0) = lp0;
                *(__nv_bfloat162*)(out_l + q1) = lp1;
            }
        }
    }
}

// ---------------- deform -> NHWC bf16 hi/lo ----------------
__global__ void k_deform_nhwc(const float* __restrict__ src, const float* __restrict__ off,
                              __nv_bfloat16* __restrict__ oh, __nv_bfloat16* __restrict__ ol,
                              int C, int isX)
{
    __shared__ float sv[64][33];
    const int n    = blockIdx.z;
    const int c0   = blockIdx.y << 6;
    const int pix0 = blockIdx.x << 5;
    const int tx = threadIdx.x, ty = threadIdx.y;

    const int pix = pix0 + tx;
    const int h = pix >> 6, w = pix & 63;
#pragma unroll
    for (int q = 0; q < 8; q++) {
        int c = c0 + q * 8 + ty;
        const float* offb = off + (((long long)n * C + c) << 13);
        float oy = offb[2 * pix];
        float ox = offb[2 * pix + 1];
        float cy = fminf(fmaxf((float)h + oy, 0.f), 63.f);
        float cx = fminf(fmaxf((float)w + ox, 0.f), 63.f);
        float y0f = floorf(cy), x0f = floorf(cx);
        float tyf = cy - y0f, txf = cx - x0f;
        int y0 = (int)y0f, x0 = (int)x0f;
        int y1 = min(y0 + 1, 63), x1 = min(x0 + 1, 63);
        const float* xc;
        if (isX) {
            int b = n >> 3, t = n & 7;
            xc = src + ((((long long)b * 256 + c) * 8 + t) << 12);
        } else {
            xc = src + (((long long)n * C + c) << 12);
        }
        float v00 = xc[(y0 << 6) + x0];
        float v01 = xc[(y0 << 6) + x1];
        float v10 = xc[(y1 << 6) + x0];
        float v11 = xc[(y1 << 6) + x1];
        sv[q * 8 + ty][tx] =
            v00 * (1.f - tyf) * (1.f - txf) + v01 * (1.f - tyf) * txf +
            v10 * tyf * (1.f - txf)         + v11 * tyf * txf;
    }
    __syncthreads();

    const int tid = ty * 32 + tx;
    const int pl  = tid >> 3;
    const int cb  = (tid & 7) << 3;
    __nv_bfloat16 hv[8], lv[8];
#pragma unroll
    for (int k = 0; k < 8; k++) {
        float v = sv[cb + k][pl];
        hv[k] = __float2bfloat16(v);
        lv[k] = __float2bfloat16(v - __bfloat162float(hv[k]));
    }
    long long o = ((long long)n * 4096 + pix0 + pl) * C + c0 + cb;
    *(uint4*)(oh + o) = *(uint4*)hv;
    *(uint4*)(ol + o) = *(uint4*)lv;
}

// ---------------- launch ----------------
extern "C" void kernel_launch(void* const* d_in, const int* in_sizes, int n_in,
                              void* d_out, int out_size)
{
    const float* x      = (const float*)d_in[0];
    const float* w_off1 = (const float*)d_in[3];
    const float* w1     = (const float*)d_in[4];
    const float* g1     = (const float*)d_in[5];
    const float* b1     = (const float*)d_in[6];
    const float* m1     = (const float*)d_in[7];
    const float* v1     = (const float*)d_in[8];
    const float* w_off2 = (const float*)d_in[9];
    const float* w2     = (const float*)d_in[10];
    const float* g2     = (const float*)d_in[11];
    const float* b2     = (const float*)d_in[12];
    const float* m2     = (const float*)d_in[13];
    const float* v2     = (const float*)d_in[14];
    float* out = (float*)d_out;

    float *off1, *c1, *off2;
    __nv_bfloat16 *xh, *xl, *dh1, *dl1, *ch1, *cl1, *dh2, *dl2, *wh, *wl;
    cudaGetSymbolAddress((void**)&off1, g_off1);
    cudaGetSymbolAddress((void**)&c1,   g_c1);
    cudaGetSymbolAddress((void**)&off2, g_off2);
    cudaGetSymbolAddress((void**)&xh,   g_xh);
    cudaGetSymbolAddress((void**)&xl,   g_xl);
    cudaGetSymbolAddress((void**)&dh1,  g_dh1);
    cudaGetSymbolAddress((void**)&dl1,  g_dl1);
    cudaGetSymbolAddress((void**)&ch1,  g_ch1);
    cudaGetSymbolAddress((void**)&cl1,  g_cl1);
    cudaGetSymbolAddress((void**)&dh2,  g_dh2);
    cudaGetSymbolAddress((void**)&dl2,  g_dl2);
    cudaGetSymbolAddress((void**)&wh,   g_wh);
    cudaGetSymbolAddress((void**)&wl,   g_wl);

    cudaFuncSetAttribute(k_conv_mma<128>, cudaFuncAttributeMaxDynamicSharedMemorySize, SMEMB);
    cudaFuncSetAttribute(k_conv_mma<64>,  cudaFuncAttributeMaxDynamicSharedMemorySize, SMEMB);

    const int SM64 = ABUFB + 2 * 64 * ROWB * 2;   // 150912 for NOC=64

    // preps
    k_prep_x<<<dim3(128, 8, NIMG), dim3(32, 8)>>>(x, xh, xl);
    k_prep_w<<<(1179648 + 255) / 256, 256>>>(w_off1, wh + WO_OFF1, wl + WO_OFF1, 256, 1179648);
    k_prep_w<<<(147456 + 255) / 256, 256>>>(w1,     wh + WO_C1,   wl + WO_C1,   256, 147456);
    k_prep_w<<<(73728 + 255) / 256, 256>>>(w_off2,  wh + WO_OFF2, wl + WO_OFF2, 64,  73728);
    k_prep_w<<<(36864 + 255) / 256, 256>>>(w2,      wh + WO_C2,   wl + WO_C2,   64,  36864);

    // off1: 256 -> 512
    k_conv_mma<128><<<dim3(NIMG * 16, 4), 256, SMEMB>>>(
        xh, xl, wh + WO_OFF1, wl + WO_OFF1, off1, nullptr, nullptr,
        nullptr, nullptr, nullptr, nullptr, 256, 512, 0);

    // deform1 (reads original x directly) -> NHWC bf16 (C=256)
    k_deform_nhwc<<<dim3(128, 4, NIMG), dim3(32, 8)>>>(x, off1, dh1, dl1, 256, 1);

    // conv1 + bn1 + lrelu: 256 -> 64
    k_conv_mma<64><<<dim3(NIMG * 16, 1), 256, SM64>>>(
        dh1, dl1, wh + WO_C1, wl + WO_C1, c1, ch1, cl1,
        g1, b1, m1, v1, 256, 64, 0);

    // off2: 64 -> 128
    k_conv_mma<128><<<dim3(NIMG * 16, 1), 256, SMEMB>>>(
        ch1, cl1, wh + WO_OFF2, wl + WO_OFF2, off2, nullptr, nullptr,
        nullptr, nullptr, nullptr, nullptr, 64, 128, 0);

    // deform2 -> NHWC bf16 (C=64)
    k_deform_nhwc<<<dim3(128, 1, NIMG), dim3(32, 8)>>>(c1, off2, dh2, dl2, 64, 0);

    // conv2 + bn2 + lrelu + transpose: 64 -> 64
    k_conv_mma<64><<<dim3(NIMG * 16, 1), 256, SM64>>>(
        dh2, dl2, wh + WO_C2, wl + WO_C2, out, nullptr, nullptr,
        g2, b2, m2, v2, 64, 64, 1);
}

// round 10
// speedup vs baseline: 6.7679x; 1.8242x over previous
#include <cuda_runtime.h>
#include <cuda_bf16.h>
#include <cuda_fp16.h>
#include <cstdint>

#define HW   4096
#define NIMG 32

// ---------------- device scratch (no allocations allowed) ----------------
__device__ float g_off1[32u * 512u * 4096u];   // offsets 1 (NCHW f32)
__device__ float g_c1  [32u *  64u * 4096u];   // conv1 out (NCHW f32, deform2 src)
__device__ float g_off2[32u * 128u * 4096u];   // offsets 2 (NCHW f32)
// fp16 single-precision operands (offset convs)
__device__ __half g_xf16[32u * 4096u * 256u];  // x NHWC fp16
__device__ __half g_cf16[32u * 4096u * 64u];   // conv1 out NHWC fp16
__device__ __half g_wf16[1253376];             // w_off1 @0 (1179648), w_off2 @1179648
#define WF_OFF1 0
#define WF_OFF2 1179648
// bf16 hi/lo split operands (value convs)
__device__ __nv_bfloat16 g_dh1[32u * 4096u * 256u];
__device__ __nv_bfloat16 g_dl1[32u * 4096u * 256u];
__device__ __nv_bfloat16 g_dh2[32u * 4096u * 64u];
__device__ __nv_bfloat16 g_dl2[32u * 4096u * 64u];
__device__ __nv_bfloat16 g_wh[184320];         // w1 @0 (147456), w2 @147456
__device__ __nv_bfloat16 g_wl[184320];
#define WB_C1 0
#define WB_C2 147456

// ---------------- helpers ----------------
__device__ __forceinline__ uint32_t smem_u32(const void* p) {
    uint32_t a;
    asm("{ .reg .u64 t; cvta.to.shared.u64 t, %1; cvt.u32.u64 %0, t; }"
        : "=r"(a) : "l"(p));
    return a;
}
__device__ __forceinline__ void ldsm_x4(uint32_t& r0, uint32_t& r1,
                                        uint32_t& r2, uint32_t& r3, uint32_t addr) {
    asm volatile("ldmatrix.sync.aligned.m8n8.x4.shared.b16 {%0,%1,%2,%3}, [%4];"
                 : "=r"(r0), "=r"(r1), "=r"(r2), "=r"(r3) : "r"(addr));
}
__device__ __forceinline__ void mma_bf16(float* c, const uint32_t* a,
                                         const uint32_t* b) {
    asm volatile(
        "mma.sync.aligned.m16n8k16.row.col.f32.bf16.bf16.f32 "
        "{%0,%1,%2,%3}, {%4,%5,%6,%7}, {%8,%9}, {%0,%1,%2,%3};"
        : "+f"(c[0]), "+f"(c[1]), "+f"(c[2]), "+f"(c[3])
        : "r"(a[0]), "r"(a[1]), "r"(a[2]), "r"(a[3]), "r"(b[0]), "r"(b[1]));
}
__device__ __forceinline__ void mma_f16(float* c, const uint32_t* a,
                                        const uint32_t* b) {
    asm volatile(
        "mma.sync.aligned.m16n8k16.row.col.f32.f16.f16.f32 "
        "{%0,%1,%2,%3}, {%4,%5,%6,%7}, {%8,%9}, {%0,%1,%2,%3};"
        : "+f"(c[0]), "+f"(c[1]), "+f"(c[2]), "+f"(c[3])
        : "r"(a[0]), "r"(a[1]), "r"(a[2]), "r"(a[3]), "r"(b[0]), "r"(b[1]));
}
__device__ __forceinline__ void cpa16(uint32_t dst, const void* src, uint32_t sz) {
    asm volatile("cp.async.cg.shared.global [%0], [%1], 16, %2;"
                 :: "r"(dst), "l"(src), "r"(sz));
}
#define CPA_COMMIT() asm volatile("cp.async.commit_group;" ::: "memory")
#define CPA_WAIT1()  asm volatile("cp.async.wait_group 1;" ::: "memory")
#define CPA_WAIT0()  asm volatile("cp.async.wait_group 0;" ::: "memory")

// smem geometry (bytes)
#define ROWB   144                 // row stride (9x16B -> conflict-free ldmatrix)
#define A_ROWS 396                 // 6 image rows x 66 cols (halo for 4-row tile)
#define AMATB  (A_ROWS * ROWB)     // 57024 per precision plane

// ---------------- prep: x -> NHWC fp16 ----------------
__global__ void k_prep_x16(const float* __restrict__ x, __half* __restrict__ xf)
{
    __shared__ float sm[32][33];
    int n    = blockIdx.z;
    int c0   = blockIdx.y << 5;
    int pix0 = blockIdx.x << 5;
    int tx = threadIdx.x, ty = threadIdx.y;
    int b = n >> 3, t = n & 7;
#pragma unroll
    for (int q = 0; q < 4; q++) {
        int c = c0 + ty + q * 8;
        sm[ty + q * 8][tx] = x[((((long long)b * 256 + c) * 8 + t) << 12) + pix0 + tx];
    }
    __syncthreads();
#pragma unroll
    for (int q = 0; q < 4; q++) {
        int pix = pix0 + ty + q * 8;
        xf[((long long)n * 4096 + pix) * 256 + c0 + tx] = __float2half(sm[tx][ty + q * 8]);
    }
}

// ---------------- prep: w -> [oc][tap][ic] ----------------
__global__ void k_prep_w16(const float* __restrict__ w, __half* __restrict__ wf,
                           int Cin, int total)
{
    int i = blockIdx.x * 256 + threadIdx.x;
    if (i >= total) return;
    int oc  = i / (Cin * 9);
    int r   = i - oc * (Cin * 9);
    int tap = r / Cin;
    int ic  = r - tap * Cin;
    wf[i] = __float2half(w[(long long)(oc * Cin + ic) * 9 + tap]);
}
__global__ void k_prep_wsplit(const float* __restrict__ w,
                              __nv_bfloat16* __restrict__ wh, __nv_bfloat16* __restrict__ wl,
                              int Cin, int total)
{
    int i = blockIdx.x * 256 + threadIdx.x;
    if (i >= total) return;
    int oc  = i / (Cin * 9);
    int r   = i - oc * (Cin * 9);
    int tap = r / Cin;
    int ic  = r - tap * Cin;
    float v = w[(long long)(oc * Cin + ic) * 9 + tap];
    __nv_bfloat16 hi = __float2bfloat16(v);
    wh[i] = hi;
    wl[i] = __float2bfloat16(v - __bfloat162float(hi));
}

// ---------------- staging ----------------
template<bool S3>
__device__ __forceinline__ void stage_A(
    uint32_t abase, int tid, int ic0, int n, int y0, int Cin,
    const __nv_bfloat16* __restrict__ xh, const __nv_bfloat16* __restrict__ xl)
{
    const int TOT = (S3 ? 2 : 1) * A_ROWS * 8;
    for (int i = tid; i < TOT; i += 256) {
        int pre = S3 ? (i >= A_ROWS * 8) : 0;
        int f   = i - pre * (A_ROWS * 8);
        int row = f >> 3, u = f & 7;
        int rel_y = row / 66, rel_x = row - rel_y * 66;
        int ys = y0 - 1 + rel_y, xs = rel_x - 1;
        bool ok = ((unsigned)ys < 64u) && ((unsigned)xs < 64u);
        const __nv_bfloat16* base = pre ? xl : xh;
        const __nv_bfloat16* src = ok ?
            base + (((long long)n * 4096 + ys * 64 + xs) * Cin + ic0 + (u << 3)) : base;
        cpa16(abase + pre * AMATB + row * ROWB + (u << 4), src, ok ? 16u : 0u);
    }
}

template<int NOC, bool S3>
__device__ __forceinline__ void stage_B(
    uint32_t bbase, int tid, int tap, int ic0, int oc0, int Cin,
    const __nv_bfloat16* __restrict__ wh, const __nv_bfloat16* __restrict__ wl)
{
    const int TOT = NOC * 8 * (S3 ? 2 : 1);
    for (int i = tid; i < TOT; i += 256) {
        int pre = S3 ? (i >= NOC * 8) : 0;
        int f   = i - pre * (NOC * 8);
        int r = f >> 3, u = f & 7;
        const __nv_bfloat16* src = (pre ? wl : wh) +
            ((long long)(oc0 + r) * 9 + tap) * Cin + ic0 + (u << 3);
        cpa16(bbase + pre * (NOC * ROWB) + r * ROWB + (u << 4), src, 16u);
    }
}

// ---------------- mma implicit-GEMM conv: D[256 px][NOC oc] ------------------
// S3=true : 3-pass bf16 hi/lo (value convs). S3=false: 1-pass fp16 (offset convs).
template<int NOC, bool S3>
__global__ __launch_bounds__(256)
void k_conv_mma(const __nv_bfloat16* __restrict__ xh, const __nv_bfloat16* __restrict__ xl,
                const __nv_bfloat16* __restrict__ wh, const __nv_bfloat16* __restrict__ wl,
                float* __restrict__ out_f32, __half* __restrict__ out_h16,
                const float* __restrict__ bng, const float* __restrict__ bnb,
                const float* __restrict__ bnm, const float* __restrict__ bnv,
                int Cin, int Cout, int outTrans)
{
    extern __shared__ __align__(16) char smc[];
    const uint32_t uS = smem_u32(smc);

    const int tid  = threadIdx.x;
    const int lane = tid & 31;
    const int wid  = tid >> 5;
    const int wm   = wid >> 1;
    const int wn   = wid & 1;

    const int n   = blockIdx.x >> 4;
    const int mt  = blockIdx.x & 15;
    const int y0  = mt << 2;
    const int oc0 = blockIdx.y * NOC;
    const int nic = Cin >> 6;
    const int nchunks = 9 * nic;

    constexpr int J2 = NOC / 32;
    constexpr int BBUF = NOC * ROWB * (S3 ? 2 : 1);
    float acc[4][J2 * 2][4];
#pragma unroll
    for (int i = 0; i < 4; i++)
#pragma unroll
        for (int j = 0; j < J2 * 2; j++)
#pragma unroll
            for (int q = 0; q < 4; q++) acc[i][j][q] = 0.f;

    const int aOff = (lane >> 4) << 4;
    int rowoff[4];
#pragma unroll
    for (int i = 0; i < 4; i++) {
        int m = wm * 64 + (lane & 15) + i * 16;
        rowoff[i] = (((m >> 6) + 1) * 66 + (m & 63) + 1) * ROWB;
    }
    const int bRow = wn * (NOC >> 1) + (lane & 7) + ((lane >> 4) << 3);
    const int bOff = ((lane >> 3) & 1) << 4;

    const uint32_t uA = uS;
    const uint32_t uB0 = uS + (S3 ? 2 : 1) * AMATB;
    const uint32_t uB[2] = {uB0, uB0 + BBUF};

    stage_A<S3>(uA, tid, 0, n, y0, Cin, xh, xl);
    stage_B<NOC, S3>(uB[0], tid, 0, 0, oc0, Cin, wh, wl);
    CPA_COMMIT();

    for (int c = 0; c < nchunks; c++) {
        const int icc = c / 9;
        const int tap = c - icc * 9;
        const bool newA = (tap == 0) && (c > 0);
        if (newA)
            stage_A<S3>(uA, tid, icc << 6, n, y0, Cin, xh, xl);
        const int nx = c + 1;
        if (nx < nchunks) {
            const int nicc = nx / 9;
            const int ntap = nx - nicc * 9;
            stage_B<NOC, S3>(uB[nx & 1], tid, ntap, nicc << 6, oc0, Cin, wh, wl);
        }
        CPA_COMMIT();
        if (newA) { CPA_WAIT0(); } else { CPA_WAIT1(); }
        __syncthreads();

        const int d144 = ((tap / 3) * 66 + (tap - (tap / 3) * 3) - 67) * ROWB;
        const uint32_t aH = uA + d144;
        const uint32_t aL = aH + AMATB;
        const uint32_t bH = uB[c & 1];
        const uint32_t bL = bH + NOC * ROWB;

#pragma unroll
        for (int ks = 0; ks < 4; ks++) {
            const int kbyte = ks * 32;
            uint32_t ah[4][4], bh[J2][4];
#pragma unroll
            for (int i = 0; i < 4; i++)
                ldsm_x4(ah[i][0], ah[i][1], ah[i][2], ah[i][3],
                        aH + rowoff[i] + kbyte + aOff);
#pragma unroll
            for (int j2 = 0; j2 < J2; j2++)
                ldsm_x4(bh[j2][0], bh[j2][1], bh[j2][2], bh[j2][3],
                        bH + (bRow + j2 * 16) * ROWB + kbyte + bOff);
#pragma unroll
            for (int i = 0; i < 4; i++)
#pragma unroll
                for (int j2 = 0; j2 < J2; j2++) {
                    if constexpr (S3) {
                        mma_bf16(acc[i][j2 * 2 + 0], ah[i], &bh[j2][0]);
                        mma_bf16(acc[i][j2 * 2 + 1], ah[i], &bh[j2][2]);
                    } else {
                        mma_f16(acc[i][j2 * 2 + 0], ah[i], &bh[j2][0]);
                        mma_f16(acc[i][j2 * 2 + 1], ah[i], &bh[j2][2]);
                    }
                }
            if constexpr (S3) {
                uint32_t al[4][4], bl[J2][4];
#pragma unroll
                for (int i = 0; i < 4; i++)
                    ldsm_x4(al[i][0], al[i][1], al[i][2], al[i][3],
                            aL + rowoff[i] + kbyte + aOff);
#pragma unroll
                for (int i = 0; i < 4; i++)
#pragma unroll
                    for (int j2 = 0; j2 < J2; j2++) {
                        mma_bf16(acc[i][j2 * 2 + 0], al[i], &bh[j2][0]);
                        mma_bf16(acc[i][j2 * 2 + 1], al[i], &bh[j2][2]);
                    }
#pragma unroll
                for (int j2 = 0; j2 < J2; j2++)
                    ldsm_x4(bl[j2][0], bl[j2][1], bl[j2][2], bl[j2][3],
                            bL + (bRow + j2 * 16) * ROWB + kbyte + bOff);
#pragma unroll
                for (int i = 0; i < 4; i++)
#pragma unroll
                    for (int j2 = 0; j2 < J2; j2++) {
                        mma_bf16(acc[i][j2 * 2 + 0], ah[i], &bl[j2][0]);
                        mma_bf16(acc[i][j2 * 2 + 1], ah[i], &bl[j2][2]);
                    }
            }
        }
        __syncthreads();
    }

    // epilogue
    const bool dobn = (bng != nullptr);
    const int qrow = lane >> 2;
    const int qcol = (lane & 3) << 1;
    const long long pixbase = (long long)mt * 256 + wm * 64;
    const int b = n >> 3, tt = n & 7;
#pragma unroll
    for (int i = 0; i < 4; i++) {
#pragma unroll
        for (int j = 0; j < J2 * 2; j++) {
            int oc = oc0 + wn * (NOC >> 1) + j * 8 + qcol;
            long long p0 = pixbase + i * 16 + qrow;
            float v0 = acc[i][j][0], v1 = acc[i][j][1];
            float v2 = acc[i][j][2], v3 = acc[i][j][3];
            if (dobn) {
                float sc0 = bng[oc] * rsqrtf(bnv[oc] + 1e-5f);
                float bi0 = bnb[oc] - bnm[oc] * sc0;
                float sc1 = bng[oc + 1] * rsqrtf(bnv[oc + 1] + 1e-5f);
                float bi1 = bnb[oc + 1] - bnm[oc + 1] * sc1;
                v0 = v0 * sc0 + bi0; v0 = (v0 > 0.f) ? v0 : 0.01f * v0;
                v1 = v1 * sc1 + bi1; v1 = (v1 > 0.f) ? v1 : 0.01f * v1;
                v2 = v2 * sc0 + bi0; v2 = (v2 > 0.f) ? v2 : 0.01f * v2;
                v3 = v3 * sc1 + bi1; v3 = (v3 > 0.f) ? v3 : 0.01f * v3;
            }
            if (out_f32) {
                long long o0, o1;
                if (outTrans) {
                    o0 = ((((long long)b * Cout + oc) * 8 + tt) << 12) + p0;
                    o1 = ((((long long)b * Cout + oc + 1) * 8 + tt) << 12) + p0;
                } else {
                    o0 = (((long long)n * Cout + oc) << 12) + p0;
                    o1 = (((long long)n * Cout + oc + 1) << 12) + p0;
                }
                out_f32[o0]     = v0;
                out_f32[o1]     = v1;
                out_f32[o0 + 8] = v2;
                out_f32[o1 + 8] = v3;
            }
            if (out_h16) {
                long long q0 = ((long long)n * 4096 + p0) * Cout + oc;
                long long q1 = ((long long)n * 4096 + p0 + 8) * Cout + oc;
                *(__half2*)(out_h16 + q0) = __floats2half2_rn(v0, v1);
                *(__half2*)(out_h16 + q1) = __floats2half2_rn(v2, v3);
            }
        }
    }
}

// ---------------- deform -> NHWC bf16 hi/lo ----------------
__global__ void k_deform_nhwc(const float* __restrict__ src, const float* __restrict__ off,
                              __nv_bfloat16* __restrict__ oh, __nv_bfloat16* __restrict__ ol,
                              int C, int isX)
{
    __shared__ float sv[64][33];
    const int n    = blockIdx.z;
    const int c0   = blockIdx.y << 6;
    const int pix0 = blockIdx.x << 5;
    const int tx = threadIdx.x, ty = threadIdx.y;

    const int pix = pix0 + tx;
    const int h = pix >> 6, w = pix & 63;
#pragma unroll
    for (int q = 0; q < 8; q++) {
        int c = c0 + q * 8 + ty;
        const float* offb = off + (((long long)n * C + c) << 13);
        float oy = offb[2 * pix];
        float ox = offb[2 * pix + 1];
        float cy = fminf(fmaxf((float)h + oy, 0.f), 63.f);
        float cx = fminf(fmaxf((float)w + ox, 0.f), 63.f);
        float y0f = floorf(cy), x0f = floorf(cx);
        float tyf = cy - y0f, txf = cx - x0f;
        int y0 = (int)y0f, x0 = (int)x0f;
        int y1 = min(y0 + 1, 63), x1 = min(x0 + 1, 63);
        const float* xc;
        if (isX) {
            int b = n >> 3, t = n & 7;
            xc = src + ((((long long)b * 256 + c) * 8 + t) << 12);
        } else {
            xc = src + (((long long)n * C + c) << 12);
        }
        float v00 = xc[(y0 << 6) + x0];
        float v01 = xc[(y0 << 6) + x1];
        float v10 = xc[(y1 << 6) + x0];
        float v11 = xc[(y1 << 6) + x1];
        sv[q * 8 + ty][tx] =
            v00 * (1.f - tyf) * (1.f - txf) + v01 * (1.f - tyf) * txf +
            v10 * tyf * (1.f - txf)         + v11 * tyf * txf;
    }
    __syncthreads();

    const int tid = ty * 32 + tx;
    const int pl  = tid >> 3;
    const int cb  = (tid & 7) << 3;
    __nv_bfloat16 hv[8], lv[8];
#pragma unroll
    for (int k = 0; k < 8; k++) {
        float v = sv[cb + k][pl];
        hv[k] = __float2bfloat16(v);
        lv[k] = __float2bfloat16(v - __bfloat162float(hv[k]));
    }
    long long o = ((long long)n * 4096 + pix0 + pl) * C + c0 + cb;
    *(uint4*)(oh + o) = *(uint4*)hv;
    *(uint4*)(ol + o) = *(uint4*)lv;
}

// ---------------- launch ----------------
extern "C" void kernel_launch(void* const* d_in, const int* in_sizes, int n_in,
                              void* d_out, int out_size)
{
    const float* x      = (const float*)d_in[0];
    const float* w_off1 = (const float*)d_in[3];
    const float* w1     = (const float*)d_in[4];
    const float* g1     = (const float*)d_in[5];
    const float* b1     = (const float*)d_in[6];
    const float* m1     = (const float*)d_in[7];
    const float* v1     = (const float*)d_in[8];
    const float* w_off2 = (const float*)d_in[9];
    const float* w2     = (const float*)d_in[10];
    const float* g2     = (const float*)d_in[11];
    const float* b2     = (const float*)d_in[12];
    const float* m2     = (const float*)d_in[13];
    const float* v2     = (const float*)d_in[14];
    float* out = (float*)d_out;

    float *off1, *c1, *off2;
    __half *xf16, *cf16, *wf16;
    __nv_bfloat16 *dh1, *dl1, *dh2, *dl2, *wh, *wl;
    cudaGetSymbolAddress((void**)&off1, g_off1);
    cudaGetSymbolAddress((void**)&c1,   g_c1);
    cudaGetSymbolAddress((void**)&off2, g_off2);
    cudaGetSymbolAddress((void**)&xf16, g_xf16);
    cudaGetSymbolAddress((void**)&cf16, g_cf16);
    cudaGetSymbolAddress((void**)&wf16, g_wf16);
    cudaGetSymbolAddress((void**)&dh1,  g_dh1);
    cudaGetSymbolAddress((void**)&dl1,  g_dl1);
    cudaGetSymbolAddress((void**)&dh2,  g_dh2);
    cudaGetSymbolAddress((void**)&dl2,  g_dl2);
    cudaGetSymbolAddress((void**)&wh,   g_wh);
    cudaGetSymbolAddress((void**)&wl,   g_wl);

    // smem sizes
    const int SM_OFF  = AMATB + 2 * 128 * ROWB;          // 1-pass, NOC=128: 93888
    const int SM_CONV = 2 * AMATB + 2 * 64 * ROWB * 2;   // 3-pass, NOC=64: 150912

    cudaFuncSetAttribute(k_conv_mma<128, false>, cudaFuncAttributeMaxDynamicSharedMemorySize, SM_OFF);
    cudaFuncSetAttribute(k_conv_mma<64, true>,   cudaFuncAttributeMaxDynamicSharedMemorySize, SM_CONV);

    // preps
    k_prep_x16<<<dim3(128, 8, NIMG), dim3(32, 8)>>>(x, xf16);
    k_prep_w16<<<(1179648 + 255) / 256, 256>>>(w_off1, wf16 + WF_OFF1, 256, 1179648);
    k_prep_w16<<<(73728 + 255) / 256, 256>>>(w_off2, wf16 + WF_OFF2, 64, 73728);
    k_prep_wsplit<<<(147456 + 255) / 256, 256>>>(w1, wh + WB_C1, wl + WB_C1, 256, 147456);
    k_prep_wsplit<<<(36864 + 255) / 256, 256>>>(w2, wh + WB_C2, wl + WB_C2, 64, 36864);

    // off1: 256 -> 512 (1-pass fp16)
    k_conv_mma<128, false><<<dim3(NIMG * 16, 4), 256, SM_OFF>>>(
        (const __nv_bfloat16*)xf16, nullptr,
        (const __nv_bfloat16*)(wf16 + WF_OFF1), nullptr,
        off1, nullptr, nullptr, nullptr, nullptr, nullptr, 256, 512, 0);

    // deform1 (reads original x directly) -> NHWC bf16 split (C=256)
    k_deform_nhwc<<<dim3(128, 4, NIMG), dim3(32, 8)>>>(x, off1, dh1, dl1, 256, 1);

    // conv1 + bn1 + lrelu: 256 -> 64 (3-pass bf16; f32 NCHW + fp16 NHWC out)
    k_conv_mma<64, true><<<dim3(NIMG * 16, 1), 256, SM_CONV>>>(
        dh1, dl1, wh + WB_C1, wl + WB_C1, c1, cf16,
        g1, b1, m1, v1, 256, 64, 0);

    // off2: 64 -> 128 (1-pass fp16)
    k_conv_mma<128, false><<<dim3(NIMG * 16, 1), 256, SM_OFF>>>(
        (const __nv_bfloat16*)cf16, nullptr,
        (const __nv_bfloat16*)(wf16 + WF_OFF2), nullptr,
        off2, nullptr, nullptr, nullptr, nullptr, nullptr, 64, 128, 0);

    // deform2 -> NHWC bf16 split (C=64)
    k_deform_nhwc<<<dim3(128, 1, NIMG), dim3(32, 8)>>>(c1, off2, dh2, dl2, 64, 0);

    // conv2 + bn2 + lrelu + transpose: 64 -> 64 (3-pass bf16)
    k_conv_mma<64, true><<<dim3(NIMG * 16, 1), 256, SM_CONV>>>(
        dh2, dl2, wh + WB_C2, wl + WB_C2, out, nullptr,
        g2, b2, m2, v2, 64, 64, 1);
}

// round 11
// speedup vs baseline: 7.6694x; 1.1332x over previous
#include <cuda_runtime.h>
#include <cuda_fp16.h>
#include <cstdint>

#define HW   4096
#define NIMG 32

// ---------------- device scratch (no allocations allowed) ----------------
__device__ float g_off1[32u * 512u * 4096u];   // offsets 1 (NCHW f32)
__device__ float g_c1  [32u *  64u * 4096u];   // conv1 out (NCHW f32, deform2 src)
__device__ float g_off2[32u * 128u * 4096u];   // offsets 2 (NCHW f32)
// fp16 NHWC operands
__device__ __half g_xf16[32u * 4096u * 256u];  // x NHWC fp16 (off1 A)
__device__ __half g_cf16[32u * 4096u * 64u];   // conv1 out NHWC fp16 (off2 A)
__device__ __half g_dh1 [32u * 4096u * 256u];  // deform1 out NHWC fp16 (conv1 A)
__device__ __half g_dh2 [32u * 4096u * 64u];   // deform2 out NHWC fp16 (conv2 A)
// weights [oc][tap][ic] fp16
__device__ __half g_wf16[1253376];             // w_off1 @0, w_off2 @1179648 (single)
#define WF_OFF1 0
#define WF_OFF2 1179648
__device__ __half g_wfh[184320];               // w1 @0 (147456), w2 @147456 (hi)
__device__ __half g_wfl[184320];               // (lo)
#define WB_C1 0
#define WB_C2 147456

// ---------------- helpers ----------------
__device__ __forceinline__ uint32_t smem_u32(const void* p) {
    uint32_t a;
    asm("{ .reg .u64 t; cvta.to.shared.u64 t, %1; cvt.u32.u64 %0, t; }"
        : "=r"(a) : "l"(p));
    return a;
}
__device__ __forceinline__ void ldsm_x4(uint32_t& r0, uint32_t& r1,
                                        uint32_t& r2, uint32_t& r3, uint32_t addr) {
    asm volatile("ldmatrix.sync.aligned.m8n8.x4.shared.b16 {%0,%1,%2,%3}, [%4];"
                 : "=r"(r0), "=r"(r1), "=r"(r2), "=r"(r3) : "r"(addr));
}
__device__ __forceinline__ void mma_f16(float* c, const uint32_t* a,
                                        const uint32_t* b) {
    asm volatile(
        "mma.sync.aligned.m16n8k16.row.col.f32.f16.f16.f32 "
        "{%0,%1,%2,%3}, {%4,%5,%6,%7}, {%8,%9}, {%0,%1,%2,%3};"
        : "+f"(c[0]), "+f"(c[1]), "+f"(c[2]), "+f"(c[3])
        : "r"(a[0]), "r"(a[1]), "r"(a[2]), "r"(a[3]), "r"(b[0]), "r"(b[1]));
}
__device__ __forceinline__ void cpa16(uint32_t dst, const void* src, uint32_t sz) {
    asm volatile("cp.async.cg.shared.global [%0], [%1], 16, %2;"
                 :: "r"(dst), "l"(src), "r"(sz));
}
#define CPA_COMMIT() asm volatile("cp.async.commit_group;" ::: "memory")
#define CPA_WAIT1()  asm volatile("cp.async.wait_group 1;" ::: "memory")
#define CPA_WAIT0()  asm volatile("cp.async.wait_group 0;" ::: "memory")

#define ROWB 144   // smem row stride (9x16B -> conflict-free ldmatrix)

// ---------------- prep: x -> NHWC fp16 ----------------
__global__ void k_prep_x16(const float* __restrict__ x, __half* __restrict__ xf)
{
    __shared__ float sm[32][33];
    int n    = blockIdx.z;
    int c0   = blockIdx.y << 5;
    int pix0 = blockIdx.x << 5;
    int tx = threadIdx.x, ty = threadIdx.y;
    int b = n >> 3, t = n & 7;
#pragma unroll
    for (int q = 0; q < 4; q++) {
        int c = c0 + ty + q * 8;
        sm[ty + q * 8][tx] = x[((((long long)b * 256 + c) * 8 + t) << 12) + pix0 + tx];
    }
    __syncthreads();
#pragma unroll
    for (int q = 0; q < 4; q++) {
        int pix = pix0 + ty + q * 8;
        xf[((long long)n * 4096 + pix) * 256 + c0 + tx] = __float2half(sm[tx][ty + q * 8]);
    }
}

// ---------------- prep: w -> [oc][tap][ic] fp16 (single / hi+lo split) -------
__global__ void k_prep_w16(const float* __restrict__ w, __half* __restrict__ wf,
                           int Cin, int total)
{
    int i = blockIdx.x * 256 + threadIdx.x;
    if (i >= total) return;
    int oc  = i / (Cin * 9);
    int r   = i - oc * (Cin * 9);
    int tap = r / Cin;
    int ic  = r - tap * Cin;
    wf[i] = __float2half(w[(long long)(oc * Cin + ic) * 9 + tap]);
}
__global__ void k_prep_wsplit16(const float* __restrict__ w,
                                __half* __restrict__ wh, __half* __restrict__ wl,
                                int Cin, int total)
{
    int i = blockIdx.x * 256 + threadIdx.x;
    if (i >= total) return;
    int oc  = i / (Cin * 9);
    int r   = i - oc * (Cin * 9);
    int tap = r / Cin;
    int ic  = r - tap * Cin;
    float v = w[(long long)(oc * Cin + ic) * 9 + tap];
    __half hi = __float2half(v);
    wh[i] = hi;
    wl[i] = __float2half(v - __half2float(hi));
}

// ---------------- staging ----------------
template<int MI>
__device__ __forceinline__ void stage_A(
    uint32_t abase, int tid, int ic0, int n, int y0, int Cin,
    const __half* __restrict__ xA)
{
    constexpr int AR = (MI + 2) * 66;
    for (int i = tid; i < AR * 8; i += 256) {
        int row = i >> 3, u = i & 7;
        int rel_y = row / 66, rel_x = row - rel_y * 66;
        int ys = y0 - 1 + rel_y, xs = rel_x - 1;
        bool ok = ((unsigned)ys < 64u) && ((unsigned)xs < 64u);
        const __half* src = ok ?
            xA + (((long long)n * 4096 + ys * 64 + xs) * Cin + ic0 + (u << 3)) : xA;
        cpa16(abase + row * ROWB + (u << 4), src, ok ? 16u : 0u);
    }
}

template<int NOC, bool BSPL>
__device__ __forceinline__ void stage_B(
    uint32_t bbase, int tid, int tap, int ic0, int oc0, int Cin,
    const __half* __restrict__ wh, const __half* __restrict__ wl)
{
    const int TOT = NOC * 8 * (BSPL ? 2 : 1);
    for (int i = tid; i < TOT; i += 256) {
        int pre = BSPL ? (i >= NOC * 8) : 0;
        int f   = i - pre * (NOC * 8);
        int r = f >> 3, u = f & 7;
        const __half* src = (pre ? wl : wh) +
            ((long long)(oc0 + r) * 9 + tap) * Cin + ic0 + (u << 3);
        cpa16(bbase + pre * (NOC * ROWB) + r * ROWB + (u << 4), src, 16u);
    }
}

// ---------------- mma implicit-GEMM conv: D[64*MI px][NOC oc] ----------------
// A: single fp16 plane, staged per ic64-chunk (halo, tap shift via address).
// B: fp16, optionally hi/lo split (BSPL -> 2 passes). 8 warps = 4(M) x 2(N).
template<int NOC, int MI, bool BSPL>
__global__ __launch_bounds__(256)
void k_conv_mma(const __half* __restrict__ xA,
                const __half* __restrict__ wh, const __half* __restrict__ wl,
                float* __restrict__ out_f32, __half* __restrict__ out_h16,
                const float* __restrict__ bng, const float* __restrict__ bnb,
                const float* __restrict__ bnm, const float* __restrict__ bnv,
                int Cin, int Cout, int outTrans)
{
    extern __shared__ __align__(16) char smc[];
    const uint32_t uS = smem_u32(smc);

    constexpr int NT = 64 / MI;               // m-tiles per image
    constexpr int AB = (MI + 2) * 66 * ROWB;  // A plane bytes
    constexpr int BB = NOC * ROWB * (BSPL ? 2 : 1);
    constexpr int J2 = NOC / 32;

    const int tid  = threadIdx.x;
    const int lane = tid & 31;
    const int wid  = tid >> 5;
    const int wm   = wid >> 1;
    const int wn   = wid & 1;

    const int n   = blockIdx.x / NT;
    const int mt  = blockIdx.x - n * NT;
    const int y0  = mt * MI;
    const int oc0 = blockIdx.y * NOC;
    const int nic = Cin >> 6;
    const int nchunks = 9 * nic;

    float acc[MI][J2 * 2][4];
#pragma unroll
    for (int i = 0; i < MI; i++)
#pragma unroll
        for (int j = 0; j < J2 * 2; j++)
#pragma unroll
            for (int q = 0; q < 4; q++) acc[i][j][q] = 0.f;

    const int aOff = (lane >> 4) << 4;
    int rowoff[MI];
#pragma unroll
    for (int i = 0; i < MI; i++) {
        int m = wm * (16 * MI) + (lane & 15) + i * 16;
        rowoff[i] = (((m >> 6) + 1) * 66 + (m & 63) + 1) * ROWB;
    }
    const int bRow = wn * (NOC >> 1) + (lane & 7) + ((lane >> 4) << 3);
    const int bOff = ((lane >> 3) & 1) << 4;

    const uint32_t uA = uS;
    const uint32_t uB[2] = {uS + AB, uS + AB + BB};

    stage_A<MI>(uA, tid, 0, n, y0, Cin, xA);
    stage_B<NOC, BSPL>(uB[0], tid, 0, 0, oc0, Cin, wh, wl);
    CPA_COMMIT();

    for (int c = 0; c < nchunks; c++) {
        const int icc = c / 9;
        const int tap = c - icc * 9;
        const bool newA = (tap == 0) && (c > 0);
        if (newA)   // trailing syncthreads of previous iter protects the A buffer
            stage_A<MI>(uA, tid, icc << 6, n, y0, Cin, xA);
        const int nx = c + 1;
        if (nx < nchunks) {
            const int nicc = nx / 9;
            const int ntap = nx - nicc * 9;
            stage_B<NOC, BSPL>(uB[nx & 1], tid, ntap, nicc << 6, oc0, Cin, wh, wl);
        }
        CPA_COMMIT();
        if (newA) { CPA_WAIT0(); } else { CPA_WAIT1(); }
        __syncthreads();

        const int d144 = ((tap / 3) * 66 + (tap - (tap / 3) * 3) - 67) * ROWB;
        const uint32_t aH = uA + d144;
        const uint32_t bH = uB[c & 1];
        const uint32_t bL = bH + NOC * ROWB;

#pragma unroll
        for (int ks = 0; ks < 4; ks++) {
            const int kbyte = ks * 32;
            uint32_t ah[MI][4], bh[J2][4];
#pragma unroll
            for (int i = 0; i < MI; i++)
                ldsm_x4(ah[i][0], ah[i][1], ah[i][2], ah[i][3],
                        aH + rowoff[i] + kbyte + aOff);
#pragma unroll
            for (int j2 = 0; j2 < J2; j2++)
                ldsm_x4(bh[j2][0], bh[j2][1], bh[j2][2], bh[j2][3],
                        bH + (bRow + j2 * 16) * ROWB + kbyte + bOff);
#pragma unroll
            for (int i = 0; i < MI; i++)
#pragma unroll
                for (int j2 = 0; j2 < J2; j2++) {
                    mma_f16(acc[i][j2 * 2 + 0], ah[i], &bh[j2][0]);
                    mma_f16(acc[i][j2 * 2 + 1], ah[i], &bh[j2][2]);
                }
            if constexpr (BSPL) {
                uint32_t bl[J2][4];
#pragma unroll
                for (int j2 = 0; j2 < J2; j2++)
                    ldsm_x4(bl[j2][0], bl[j2][1], bl[j2][2], bl[j2][3],
                            bL + (bRow + j2 * 16) * ROWB + kbyte + bOff);
#pragma unroll
                for (int i = 0; i < MI; i++)
#pragma unroll
                    for (int j2 = 0; j2 < J2; j2++) {
                        mma_f16(acc[i][j2 * 2 + 0], ah[i], &bl[j2][0]);
                        mma_f16(acc[i][j2 * 2 + 1], ah[i], &bl[j2][2]);
                    }
            }
        }
        __syncthreads();
    }

    // epilogue
    const bool dobn = (bng != nullptr);
    const int qrow = lane >> 2;
    const int qcol = (lane & 3) << 1;
    const long long pixbase = (long long)mt * (64 * MI) + wm * (16 * MI);
    const int b = n >> 3, tt = n & 7;
#pragma unroll
    for (int i = 0; i < MI; i++) {
#pragma unroll
        for (int j = 0; j < J2 * 2; j++) {
            int oc = oc0 + wn * (NOC >> 1) + j * 8 + qcol;
            long long p0 = pixbase + i * 16 + qrow;
            float v0 = acc[i][j][0], v1 = acc[i][j][1];
            float v2 = acc[i][j][2], v3 = acc[i][j][3];
            if (dobn) {
                float sc0 = bng[oc] * rsqrtf(bnv[oc] + 1e-5f);
                float bi0 = bnb[oc] - bnm[oc] * sc0;
                float sc1 = bng[oc + 1] * rsqrtf(bnv[oc + 1] + 1e-5f);
                float bi1 = bnb[oc + 1] - bnm[oc + 1] * sc1;
                v0 = v0 * sc0 + bi0; v0 = (v0 > 0.f) ? v0 : 0.01f * v0;
                v1 = v1 * sc1 + bi1; v1 = (v1 > 0.f) ? v1 : 0.01f * v1;
                v2 = v2 * sc0 + bi0; v2 = (v2 > 0.f) ? v2 : 0.01f * v2;
                v3 = v3 * sc1 + bi1; v3 = (v3 > 0.f) ? v3 : 0.01f * v3;
            }
            if (out_f32) {
                long long o0, o1;
                if (outTrans) {
                    o0 = ((((long long)b * Cout + oc) * 8 + tt) << 12) + p0;
                    o1 = ((((long long)b * Cout + oc + 1) * 8 + tt) << 12) + p0;
                } else {
                    o0 = (((long long)n * Cout + oc) << 12) + p0;
                    o1 = (((long long)n * Cout + oc + 1) << 12) + p0;
                }
                out_f32[o0]     = v0;
                out_f32[o1]     = v1;
                out_f32[o0 + 8] = v2;
                out_f32[o1 + 8] = v3;
            }
            if (out_h16) {
                long long q0 = ((long long)n * 4096 + p0) * Cout + oc;
                long long q1 = ((long long)n * 4096 + p0 + 8) * Cout + oc;
                *(__half2*)(out_h16 + q0) = __floats2half2_rn(v0, v1);
                *(__half2*)(out_h16 + q1) = __floats2half2_rn(v2, v3);
            }
        }
    }
}

// ---------------- deform -> NHWC fp16 (single plane) ----------------
__global__ void k_deform_nhwc(const float* __restrict__ src, const float* __restrict__ off,
                              __half* __restrict__ oh, int C, int isX)
{
    __shared__ float sv[64][33];
    const int n    = blockIdx.z;
    const int c0   = blockIdx.y << 6;
    const int pix0 = blockIdx.x << 5;
    const int tx = threadIdx.x, ty = threadIdx.y;

    const int pix = pix0 + tx;
    const int h = pix >> 6, w = pix & 63;
#pragma unroll
    for (int q = 0; q < 8; q++) {
        int c = c0 + q * 8 + ty;
        const float* offb = off + (((long long)n * C + c) << 13);
        float oy = offb[2 * pix];
        float ox = offb[2 * pix + 1];
        float cy = fminf(fmaxf((float)h + oy, 0.f), 63.f);
        float cx = fminf(fmaxf((float)w + ox, 0.f), 63.f);
        float y0f = floorf(cy), x0f = floorf(cx);
        float tyf = cy - y0f, txf = cx - x0f;
        int y0 = (int)y0f, x0 = (int)x0f;
        int y1 = min(y0 + 1, 63), x1 = min(x0 + 1, 63);
        const float* xc;
        if (isX) {
            int b = n >> 3, t = n & 7;
            xc = src + ((((long long)b * 256 + c) * 8 + t) << 12);
        } else {
            xc = src + (((long long)n * C + c) << 12);
        }
        float v00 = xc[(y0 << 6) + x0];
        float v01 = xc[(y0 << 6) + x1];
        float v10 = xc[(y1 << 6) + x0];
        float v11 = xc[(y1 << 6) + x1];
        sv[q * 8 + ty][tx] =
            v00 * (1.f - tyf) * (1.f - txf) + v01 * (1.f - tyf) * txf +
            v10 * tyf * (1.f - txf)         + v11 * tyf * txf;
    }
    __syncthreads();

    const int tid = ty * 32 + tx;
    const int pl  = tid >> 3;
    const int cb  = (tid & 7) << 3;
    __half hv[8];
#pragma unroll
    for (int k = 0; k < 8; k++)
        hv[k] = __float2half(sv[cb + k][pl]);
    long long o = ((long long)n * 4096 + pix0 + pl) * C + c0 + cb;
    *(uint4*)(oh + o) = *(uint4*)hv;
}

// ---------------- launch ----------------
extern "C" void kernel_launch(void* const* d_in, const int* in_sizes, int n_in,
                              void* d_out, int out_size)
{
    const float* x      = (const float*)d_in[0];
    const float* w_off1 = (const float*)d_in[3];
    const float* w1     = (const float*)d_in[4];
    const float* g1     = (const float*)d_in[5];
    const float* b1     = (const float*)d_in[6];
    const float* m1     = (const float*)d_in[7];
    const float* v1     = (const float*)d_in[8];
    const float* w_off2 = (const float*)d_in[9];
    const float* w2     = (const float*)d_in[10];
    const float* g2     = (const float*)d_in[11];
    const float* b2     = (const float*)d_in[12];
    const float* m2     = (const float*)d_in[13];
    const float* v2     = (const float*)d_in[14];
    float* out = (float*)d_out;

    float *off1, *c1, *off2;
    __half *xf16, *cf16, *dh1, *dh2, *wf16, *wfh, *wfl;
    cudaGetSymbolAddress((void**)&off1, g_off1);
    cudaGetSymbolAddress((void**)&c1,   g_c1);
    cudaGetSymbolAddress((void**)&off2, g_off2);
    cudaGetSymbolAddress((void**)&xf16, g_xf16);
    cudaGetSymbolAddress((void**)&cf16, g_cf16);
    cudaGetSymbolAddress((void**)&dh1,  g_dh1);
    cudaGetSymbolAddress((void**)&dh2,  g_dh2);
    cudaGetSymbolAddress((void**)&wf16, g_wf16);
    cudaGetSymbolAddress((void**)&wfh,  g_wfh);
    cudaGetSymbolAddress((void**)&wfl,  g_wfl);

    // smem sizes
    const int SM_OFF  = 6 * 66 * ROWB + 2 * 128 * ROWB;      // MI=4, B single: 93888
    const int SM_CONV = 4 * 66 * ROWB + 2 * 2 * 64 * ROWB;   // MI=2, B split: 74880

    cudaFuncSetAttribute(k_conv_mma<128, 4, false>, cudaFuncAttributeMaxDynamicSharedMemorySize, SM_OFF);
    cudaFuncSetAttribute(k_conv_mma<64, 2, true>,   cudaFuncAttributeMaxDynamicSharedMemorySize, SM_CONV);

    // preps
    k_prep_x16<<<dim3(128, 8, NIMG), dim3(32, 8)>>>(x, xf16);
    k_prep_w16<<<(1179648 + 255) / 256, 256>>>(w_off1, wf16 + WF_OFF1, 256, 1179648);
    k_prep_w16<<<(73728 + 255) / 256, 256>>>(w_off2, wf16 + WF_OFF2, 64, 73728);
    k_prep_wsplit16<<<(147456 + 255) / 256, 256>>>(w1, wfh + WB_C1, wfl + WB_C1, 256, 147456);
    k_prep_wsplit16<<<(36864 + 255) / 256, 256>>>(w2, wfh + WB_C2, wfl + WB_C2, 64, 36864);

    // off1: 256 -> 512 (1-pass fp16, M=256 tiles)
    k_conv_mma<128, 4, false><<<dim3(NIMG * 16, 4), 256, SM_OFF>>>(
        xf16, wf16 + WF_OFF1, nullptr, off1, nullptr,
        nullptr, nullptr, nullptr, nullptr, 256, 512, 0);

    // deform1 (reads original x) -> NHWC fp16 (C=256)
    k_deform_nhwc<<<dim3(128, 4, NIMG), dim3(32, 8)>>>(x, off1, dh1, 256, 1);

    // conv1 + bn1 + lrelu: 256 -> 64 (2-pass: x fp16 single, w fp16 split; M=128)
    k_conv_mma<64, 2, true><<<dim3(NIMG * 32, 1), 256, SM_CONV>>>(
        dh1, wfh + WB_C1, wfl + WB_C1, c1, cf16,
        g1, b1, m1, v1, 256, 64, 0);

    // off2: 64 -> 128 (1-pass fp16)
    k_conv_mma<128, 4, false><<<dim3(NIMG * 16, 1), 256, SM_OFF>>>(
        cf16, wf16 + WF_OFF2, nullptr, off2, nullptr,
        nullptr, nullptr, nullptr, nullptr, 64, 128, 0);

    // deform2 -> NHWC fp16 (C=64)
    k_deform_nhwc<<<dim3(128, 1, NIMG), dim3(32, 8)>>>(c1, off2, dh2, 64, 0);

    // conv2 + bn2 + lrelu + transpose: 64 -> 64 (2-pass)
    k_conv_mma<64, 2, true><<<dim3(NIMG * 32, 1), 256, SM_CONV>>>(
        dh2, wfh + WB_C2, wfl + WB_C2, out, nullptr,
        g2, b2, m2, v2, 64, 64, 1);
}

// round 12
// speedup vs baseline: 7.9477x; 1.0363x over previous
#include <cuda_runtime.h>
#include <cuda_fp16.h>
#include <cstdint>

#define HW   4096
#define NIMG 32

// ---------------- device scratch (no allocations allowed) ----------------
__device__ __half g_off1h[32u * 512u * 4096u];  // offsets 1 (NCHW fp16)
__device__ float  g_c1   [32u *  64u * 4096u];  // conv1 out (NCHW f32, deform2 src)
__device__ __half g_off2h[32u * 128u * 4096u];  // offsets 2 (NCHW fp16)
// fp16 NHWC operands
__device__ __half g_xf16[32u * 4096u * 256u];   // x NHWC fp16 (off1 A)
__device__ __half g_cf16[32u * 4096u * 64u];    // conv1 out NHWC fp16 (off2 A)
__device__ __half g_dh1 [32u * 4096u * 256u];   // deform1 out NHWC fp16 (conv1 A)
__device__ __half g_dh2 [32u * 4096u * 64u];    // deform2 out NHWC fp16 (conv2 A)
// weights [oc][tap][ic] fp16
__device__ __half g_wf16[1253376];              // w_off1 @0, w_off2 @1179648
#define WF_OFF1 0
#define WF_OFF2 1179648
__device__ __half g_wfh[184320];                // w1 @0, w2 @147456 (hi)
__device__ __half g_wfl[184320];                // (lo)
#define WB_C1 0
#define WB_C2 147456

// ---------------- helpers ----------------
__device__ __forceinline__ uint32_t smem_u32(const void* p) {
    uint32_t a;
    asm("{ .reg .u64 t; cvta.to.shared.u64 t, %1; cvt.u32.u64 %0, t; }"
        : "=r"(a) : "l"(p));
    return a;
}
__device__ __forceinline__ void ldsm_x4(uint32_t& r0, uint32_t& r1,
                                        uint32_t& r2, uint32_t& r3, uint32_t addr) {
    asm volatile("ldmatrix.sync.aligned.m8n8.x4.shared.b16 {%0,%1,%2,%3}, [%4];"
                 : "=r"(r0), "=r"(r1), "=r"(r2), "=r"(r3) : "r"(addr));
}
__device__ __forceinline__ void mma_f16(float* c, const uint32_t* a,
                                        const uint32_t* b) {
    asm volatile(
        "mma.sync.aligned.m16n8k16.row.col.f32.f16.f16.f32 "
        "{%0,%1,%2,%3}, {%4,%5,%6,%7}, {%8,%9}, {%0,%1,%2,%3};"
        : "+f"(c[0]), "+f"(c[1]), "+f"(c[2]), "+f"(c[3])
        : "r"(a[0]), "r"(a[1]), "r"(a[2]), "r"(a[3]), "r"(b[0]), "r"(b[1]));
}
__device__ __forceinline__ void cpa16(uint32_t dst, const void* src, uint32_t sz) {
    asm volatile("cp.async.cg.shared.global [%0], [%1], 16, %2;"
                 :: "r"(dst), "l"(src), "r"(sz));
}
#define CPA_COMMIT() asm volatile("cp.async.commit_group;" ::: "memory")
#define CPA_WAIT1()  asm volatile("cp.async.wait_group 1;" ::: "memory")
#define CPA_WAIT0()  asm volatile("cp.async.wait_group 0;" ::: "memory")

#define ROWB 144   // smem row stride (9x16B -> conflict-free ldmatrix)

// ---------------- prep: x -> NHWC fp16 ----------------
__global__ void k_prep_x16(const float* __restrict__ x, __half* __restrict__ xf)
{
    __shared__ float sm[32][33];
    int n    = blockIdx.z;
    int c0   = blockIdx.y << 5;
    int pix0 = blockIdx.x << 5;
    int tx = threadIdx.x, ty = threadIdx.y;
    int b = n >> 3, t = n & 7;
#pragma unroll
    for (int q = 0; q < 4; q++) {
        int c = c0 + ty + q * 8;
        sm[ty + q * 8][tx] = x[((((long long)b * 256 + c) * 8 + t) << 12) + pix0 + tx];
    }
    __syncthreads();
#pragma unroll
    for (int q = 0; q < 4; q++) {
        int pix = pix0 + ty + q * 8;
        xf[((long long)n * 4096 + pix) * 256 + c0 + tx] = __float2half(sm[tx][ty + q * 8]);
    }
}

// ---------------- prep: w -> [oc][tap][ic] fp16 (single / hi+lo split) -------
__global__ void k_prep_w16(const float* __restrict__ w, __half* __restrict__ wf,
                           int Cin, int total)
{
    int i = blockIdx.x * 256 + threadIdx.x;
    if (i >= total) return;
    int oc  = i / (Cin * 9);
    int r   = i - oc * (Cin * 9);
    int tap = r / Cin;
    int ic  = r - tap * Cin;
    wf[i] = __float2half(w[(long long)(oc * Cin + ic) * 9 + tap]);
}
__global__ void k_prep_wsplit16(const float* __restrict__ w,
                                __half* __restrict__ wh, __half* __restrict__ wl,
                                int Cin, int total)
{
    int i = blockIdx.x * 256 + threadIdx.x;
    if (i >= total) return;
    int oc  = i / (Cin * 9);
    int r   = i - oc * (Cin * 9);
    int tap = r / Cin;
    int ic  = r - tap * Cin;
    float v = w[(long long)(oc * Cin + ic) * 9 + tap];
    __half hi = __float2half(v);
    wh[i] = hi;
    wl[i] = __float2half(v - __half2float(hi));
}

// ---------------- staging ----------------
template<int MI>
__device__ __forceinline__ void stage_A(
    uint32_t abase, int tid, int ic0, int n, int y0, int Cin,
    const __half* __restrict__ xA)
{
    constexpr int AR = (MI + 2) * 66;
    for (int i = tid; i < AR * 8; i += 256) {
        int row = i >> 3, u = i & 7;
        int rel_y = row / 66, rel_x = row - rel_y * 66;
        int ys = y0 - 1 + rel_y, xs = rel_x - 1;
        bool ok = ((unsigned)ys < 64u) && ((unsigned)xs < 64u);
        const __half* src = ok ?
            xA + (((long long)n * 4096 + ys * 64 + xs) * Cin + ic0 + (u << 3)) : xA;
        cpa16(abase + row * ROWB + (u << 4), src, ok ? 16u : 0u);
    }
}

// stage 3 taps of B at once: layout [pre][tap_local][oc_row]
template<int NOC, bool BSPL>
__device__ __forceinline__ void stage_B3(
    uint32_t bbase, int tid, int trio, int ic0, int oc0, int Cin,
    const __half* __restrict__ wh, const __half* __restrict__ wl)
{
    constexpr int PLANE = 3 * NOC * 8;
    const int TOT = PLANE * (BSPL ? 2 : 1);
    for (int i = tid; i < TOT; i += 256) {
        int pre = BSPL ? (i >= PLANE) : 0;
        int f   = i - pre * PLANE;
        int tl  = f / (NOC * 8);
        int g   = f - tl * (NOC * 8);
        int r = g >> 3, u = g & 7;
        int tap = trio * 3 + tl;
        const __half* src = (pre ? wl : wh) +
            ((long long)(oc0 + r) * 9 + tap) * Cin + ic0 + (u << 3);
        cpa16(bbase + (pre * 3 + tl) * (NOC * ROWB) + r * ROWB + (u << 4), src, 16u);
    }
}

// ---------------- mma implicit-GEMM conv: D[64*MI px][NOC oc] ----------------
// A: fp16 halo plane per ic64-chunk; tap shift via fragment address.
// B: 3 taps staged per buffer (double-buffered). BSPL: w hi/lo -> 2 passes.
// OFF16: NCHW output written as fp16 (offset tensors).
template<int NOC, int MI, bool BSPL, bool OFF16>
__global__ __launch_bounds__(256)
void k_conv_mma(const __half* __restrict__ xA,
                const __half* __restrict__ wh, const __half* __restrict__ wl,
                void* __restrict__ out_nchw, __half* __restrict__ out_h16,
                const float* __restrict__ bng, const float* __restrict__ bnb,
                const float* __restrict__ bnm, const float* __restrict__ bnv,
                int Cin, int Cout, int outTrans)
{
    extern __shared__ __align__(16) char smc[];
    const uint32_t uS = smem_u32(smc);

    constexpr int NT = 64 / MI;
    constexpr int AB = (MI + 2) * 66 * ROWB;
    constexpr int BB = 3 * NOC * ROWB * (BSPL ? 2 : 1);
    constexpr int J2 = NOC / 32;

    const int tid  = threadIdx.x;
    const int lane = tid & 31;
    const int wid  = tid >> 5;
    const int wm   = wid >> 1;
    const int wn   = wid & 1;

    const int n   = blockIdx.x / NT;
    const int mt  = blockIdx.x - n * NT;
    const int y0  = mt * MI;
    const int oc0 = blockIdx.y * NOC;
    const int nic = Cin >> 6;
    const int nstage = 3 * nic;          // stages of 3 taps

    float acc[MI][J2 * 2][4];
#pragma unroll
    for (int i = 0; i < MI; i++)
#pragma unroll
        for (int j = 0; j < J2 * 2; j++)
#pragma unroll
            for (int q = 0; q < 4; q++) acc[i][j][q] = 0.f;

    const int aOff = (lane >> 4) << 4;
    int rowoff[MI];
#pragma unroll
    for (int i = 0; i < MI; i++) {
        int m = wm * (16 * MI) + (lane & 15) + i * 16;
        rowoff[i] = (((m >> 6) + 1) * 66 + (m & 63) + 1) * ROWB;
    }
    const int bRow = wn * (NOC >> 1) + (lane & 7) + ((lane >> 4) << 3);
    const int bOff = ((lane >> 3) & 1) << 4;

    const uint32_t uA = uS;
    const uint32_t uB[2] = {uS + AB, uS + AB + BB};

    stage_A<MI>(uA, tid, 0, n, y0, Cin, xA);
    stage_B3<NOC, BSPL>(uB[0], tid, 0, 0, oc0, Cin, wh, wl);
    CPA_COMMIT();

    for (int s = 0; s < nstage; s++) {
        const int icc  = s / 3;
        const int trio = s - icc * 3;
        const bool newA = (trio == 0) && (s > 0);
        if (newA)   // previous stage's trailing __syncthreads protects A
            stage_A<MI>(uA, tid, icc << 6, n, y0, Cin, xA);
        const int nx = s + 1;
        if (nx < nstage) {
            const int nicc = nx / 3;
            stage_B3<NOC, BSPL>(uB[nx & 1], tid, nx - nicc * 3, nicc << 6,
                                oc0, Cin, wh, wl);
        }
        CPA_COMMIT();
        if (newA) { CPA_WAIT0(); } else { CPA_WAIT1(); }
        __syncthreads();

        const uint32_t bBase = uB[s & 1];
#pragma unroll
        for (int tl = 0; tl < 3; tl++) {
            const int tap = trio * 3 + tl;
            const int d144 = ((tap / 3) * 66 + (tap - (tap / 3) * 3) - 67) * ROWB;
            const uint32_t aH = uA + d144;
            const uint32_t bH = bBase + tl * (NOC * ROWB);
            const uint32_t bL = bBase + (3 + tl) * (NOC * ROWB);

#pragma unroll
            for (int ks = 0; ks < 4; ks++) {
                const int kbyte = ks * 32;
                uint32_t ah[MI][4], bh[J2][4];
#pragma unroll
                for (int i = 0; i < MI; i++)
                    ldsm_x4(ah[i][0], ah[i][1], ah[i][2], ah[i][3],
                            aH + rowoff[i] + kbyte + aOff);
#pragma unroll
                for (int j2 = 0; j2 < J2; j2++)
                    ldsm_x4(bh[j2][0], bh[j2][1], bh[j2][2], bh[j2][3],
                            bH + (bRow + j2 * 16) * ROWB + kbyte + bOff);
#pragma unroll
                for (int i = 0; i < MI; i++)
#pragma unroll
                    for (int j2 = 0; j2 < J2; j2++) {
                        mma_f16(acc[i][j2 * 2 + 0], ah[i], &bh[j2][0]);
                        mma_f16(acc[i][j2 * 2 + 1], ah[i], &bh[j2][2]);
                    }
                if constexpr (BSPL) {
                    uint32_t bl[J2][4];
#pragma unroll
                    for (int j2 = 0; j2 < J2; j2++)
                        ldsm_x4(bl[j2][0], bl[j2][1], bl[j2][2], bl[j2][3],
                                bL + (bRow + j2 * 16) * ROWB + kbyte + bOff);
#pragma unroll
                    for (int i = 0; i < MI; i++)
#pragma unroll
                        for (int j2 = 0; j2 < J2; j2++) {
                            mma_f16(acc[i][j2 * 2 + 0], ah[i], &bl[j2][0]);
                            mma_f16(acc[i][j2 * 2 + 1], ah[i], &bl[j2][2]);
                        }
                }
            }
        }
        __syncthreads();
    }

    // epilogue
    const bool dobn = (bng != nullptr);
    const int qrow = lane >> 2;
    const int qcol = (lane & 3) << 1;
    const long long pixbase = (long long)mt * (64 * MI) + wm * (16 * MI);
    const int b = n >> 3, tt = n & 7;
#pragma unroll
    for (int i = 0; i < MI; i++) {
#pragma unroll
        for (int j = 0; j < J2 * 2; j++) {
            int oc = oc0 + wn * (NOC >> 1) + j * 8 + qcol;
            long long p0 = pixbase + i * 16 + qrow;
            float v0 = acc[i][j][0], v1 = acc[i][j][1];
            float v2 = acc[i][j][2], v3 = acc[i][j][3];
            if (dobn) {
                float sc0 = bng[oc] * rsqrtf(bnv[oc] + 1e-5f);
                float bi0 = bnb[oc] - bnm[oc] * sc0;
                float sc1 = bng[oc + 1] * rsqrtf(bnv[oc + 1] + 1e-5f);
                float bi1 = bnb[oc + 1] - bnm[oc + 1] * sc1;
                v0 = v0 * sc0 + bi0; v0 = (v0 > 0.f) ? v0 : 0.01f * v0;
                v1 = v1 * sc1 + bi1; v1 = (v1 > 0.f) ? v1 : 0.01f * v1;
                v2 = v2 * sc0 + bi0; v2 = (v2 > 0.f) ? v2 : 0.01f * v2;
                v3 = v3 * sc1 + bi1; v3 = (v3 > 0.f) ? v3 : 0.01f * v3;
            }
            if (out_nchw) {
                long long o0, o1;
                if (outTrans) {
                    o0 = ((((long long)b * Cout + oc) * 8 + tt) << 12) + p0;
                    o1 = ((((long long)b * Cout + oc + 1) * 8 + tt) << 12) + p0;
                } else {
                    o0 = (((long long)n * Cout + oc) << 12) + p0;
                    o1 = (((long long)n * Cout + oc + 1) << 12) + p0;
                }
                if constexpr (OFF16) {
                    __half* o = (__half*)out_nchw;
                    o[o0]     = __float2half(v0);
                    o[o1]     = __float2half(v1);
                    o[o0 + 8] = __float2half(v2);
                    o[o1 + 8] = __float2half(v3);
                } else {
                    float* o = (float*)out_nchw;
                    o[o0]     = v0;
                    o[o1]     = v1;
                    o[o0 + 8] = v2;
                    o[o1 + 8] = v3;
                }
            }
            if (out_h16) {
                long long q0 = ((long long)n * 4096 + p0) * Cout + oc;
                long long q1 = ((long long)n * 4096 + p0 + 8) * Cout + oc;
                *(__half2*)(out_h16 + q0) = __floats2half2_rn(v0, v1);
                *(__half2*)(out_h16 + q1) = __floats2half2_rn(v2, v3);
            }
        }
    }
}

// ---------------- deform -> NHWC fp16 (offsets read as fp16) ----------------
__global__ void k_deform_nhwc(const float* __restrict__ src, const __half* __restrict__ off,
                              __half* __restrict__ oh, int C, int isX)
{
    __shared__ float sv[64][33];
    const int n    = blockIdx.z;
    const int c0   = blockIdx.y << 6;
    const int pix0 = blockIdx.x << 5;
    const int tx = threadIdx.x, ty = threadIdx.y;

    const int pix = pix0 + tx;
    const int h = pix >> 6, w = pix & 63;
#pragma unroll
    for (int q = 0; q < 8; q++) {
        int c = c0 + q * 8 + ty;
        const __half* offb = off + (((long long)n * C + c) << 13);
        float oy = __half2float(offb[2 * pix]);
        float ox = __half2float(offb[2 * pix + 1]);
        float cy = fminf(fmaxf((float)h + oy, 0.f), 63.f);
        float cx = fminf(fmaxf((float)w + ox, 0.f), 63.f);
        float y0f = floorf(cy), x0f = floorf(cx);
        float tyf = cy - y0f, txf = cx - x0f;
        int y0 = (int)y0f, x0 = (int)x0f;
        int y1 = min(y0 + 1, 63), x1 = min(x0 + 1, 63);
        const float* xc;
        if (isX) {
            int b = n >> 3, t = n & 7;
            xc = src + ((((long long)b * 256 + c) * 8 + t) << 12);
        } else {
            xc = src + (((long long)n * C + c) << 12);
        }
        float v00 = xc[(y0 << 6) + x0];
        float v01 = xc[(y0 << 6) + x1];
        float v10 = xc[(y1 << 6) + x0];
        float v11 = xc[(y1 << 6) + x1];
        sv[q * 8 + ty][tx] =
            v00 * (1.f - tyf) * (1.f - txf) + v01 * (1.f - tyf) * txf +
            v10 * tyf * (1.f - txf)         + v11 * tyf * txf;
    }
    __syncthreads();

    const int tid = ty * 32 + tx;
    const int pl  = tid >> 3;
    const int cb  = (tid & 7) << 3;
    __half hv[8];
#pragma unroll
    for (int k = 0; k < 8; k++)
        hv[k] = __float2half(sv[cb + k][pl]);
    long long o = ((long long)n * 4096 + pix0 + pl) * C + c0 + cb;
    *(uint4*)(oh + o) = *(uint4*)hv;
}

// ---------------- launch ----------------
extern "C" void kernel_launch(void* const* d_in, const int* in_sizes, int n_in,
                              void* d_out, int out_size)
{
    const float* x      = (const float*)d_in[0];
    const float* w_off1 = (const float*)d_in[3];
    const float* w1     = (const float*)d_in[4];
    const float* g1     = (const float*)d_in[5];
    const float* b1     = (const float*)d_in[6];
    const float* m1     = (const float*)d_in[7];
    const float* v1     = (const float*)d_in[8];
    const float* w_off2 = (const float*)d_in[9];
    const float* w2     = (const float*)d_in[10];
    const float* g2     = (const float*)d_in[11];
    const float* b2     = (const float*)d_in[12];
    const float* m2     = (const float*)d_in[13];
    const float* v2     = (const float*)d_in[14];
    float* out = (float*)d_out;

    float *c1;
    __half *off1h, *off2h, *xf16, *cf16, *dh1, *dh2, *wf16, *wfh, *wfl;
    cudaGetSymbolAddress((void**)&off1h, g_off1h);
    cudaGetSymbolAddress((void**)&c1,    g_c1);
    cudaGetSymbolAddress((void**)&off2h, g_off2h);
    cudaGetSymbolAddress((void**)&xf16,  g_xf16);
    cudaGetSymbolAddress((void**)&cf16,  g_cf16);
    cudaGetSymbolAddress((void**)&dh1,   g_dh1);
    cudaGetSymbolAddress((void**)&dh2,   g_dh2);
    cudaGetSymbolAddress((void**)&wf16,  g_wf16);
    cudaGetSymbolAddress((void**)&wfh,   g_wfh);
    cudaGetSymbolAddress((void**)&wfl,   g_wfl);

    // smem: A(MI=4) 57024 + 2x B3 buffers 55296 = 167616 for both variants
    const int SM_ALL = 6 * 66 * ROWB + 2 * 3 * 128 * ROWB;   // 167616

    cudaFuncSetAttribute(k_conv_mma<128, 4, false, true>,
                         cudaFuncAttributeMaxDynamicSharedMemorySize, SM_ALL);
    cudaFuncSetAttribute(k_conv_mma<64, 4, true, false>,
                         cudaFuncAttributeMaxDynamicSharedMemorySize, SM_ALL);

    // preps
    k_prep_x16<<<dim3(128, 8, NIMG), dim3(32, 8)>>>(x, xf16);
    k_prep_w16<<<(1179648 + 255) / 256, 256>>>(w_off1, wf16 + WF_OFF1, 256, 1179648);
    k_prep_w16<<<(73728 + 255) / 256, 256>>>(w_off2, wf16 + WF_OFF2, 64, 73728);
    k_prep_wsplit16<<<(147456 + 255) / 256, 256>>>(w1, wfh + WB_C1, wfl + WB_C1, 256, 147456);
    k_prep_wsplit16<<<(36864 + 255) / 256, 256>>>(w2, wfh + WB_C2, wfl + WB_C2, 64, 36864);

    // off1: 256 -> 512 (1-pass fp16, fp16 NCHW offsets out)
    k_conv_mma<128, 4, false, true><<<dim3(NIMG * 16, 4), 256, SM_ALL>>>(
        xf16, wf16 + WF_OFF1, nullptr, off1h, nullptr,
        nullptr, nullptr, nullptr, nullptr, 256, 512, 0);

    // deform1 (reads original x) -> NHWC fp16 (C=256)
    k_deform_nhwc<<<dim3(128, 4, NIMG), dim3(32, 8)>>>(x, off1h, dh1, 256, 1);

    // conv1 + bn1 + lrelu: 256 -> 64 (2-pass w-split; f32 NCHW + fp16 NHWC out)
    k_conv_mma<64, 4, true, false><<<dim3(NIMG * 16, 1), 256, SM_ALL>>>(
        dh1, wfh + WB_C1, wfl + WB_C1, c1, cf16,
        g1, b1, m1, v1, 256, 64, 0);

    // off2: 64 -> 128 (1-pass fp16)
    k_conv_mma<128, 4, false, true><<<dim3(NIMG * 16, 1), 256, SM_ALL>>>(
        cf16, wf16 + WF_OFF2, nullptr, off2h, nullptr,
        nullptr, nullptr, nullptr, nullptr, 64, 128, 0);

    // deform2 -> NHWC fp16 (C=64)
    k_deform_nhwc<<<dim3(128, 1, NIMG), dim3(32, 8)>>>(c1, off2h, dh2, 64, 0);

    // conv2 + bn2 + lrelu + transpose: 64 -> 64 (2-pass)
    k_conv_mma<64, 4, true, false><<<dim3(NIMG * 16, 1), 256, SM_ALL>>>(
        dh2, wfh + WB_C2, wfl + WB_C2, out, nullptr,
        g2, b2, m2, v2, 64, 64, 1);
}